// round 13
// baseline (speedup 1.0000x reference)
#include <cuda_runtime.h>
#include <math.h>

#define BATCH 65536
#define FULL 0xffffffffu

typedef unsigned long long u64;

// -------- device scratch (allocation-free rule: __device__ globals) --------
// f and hh live ONLY as pre-split bf16 (hi,lo) k-pair images.
__device__ __align__(16) uint2 g_fP [(size_t)BATCH * 210];  // f: 420 floats -> 210 pairs
__device__ __align__(16) uint2 g_hhP[(size_t)BATCH * 128];  // hh: 256 -> 128 pairs
__device__ __align__(16) uint2 g_W1P[224 * 256];            // W1 padded K448 -> [kp][n]
__device__ __align__(16) uint2 g_W2P[352 * 64];             // [W2;Wres] padded K704 -> [kp][n]

// ---------------- packed f32x2 ops on b64 registers ----------------
__device__ __forceinline__ u64 pack2(float x, float y) {
    u64 r; asm("mov.b64 %0, {%1, %2};" : "=l"(r) : "f"(x), "f"(y)); return r;
}
__device__ __forceinline__ u64 dup2(float s) { return pack2(s, s); }
__device__ __forceinline__ void unpack2(u64 v, float& x, float& y) {
    asm("mov.b64 {%0, %1}, %2;" : "=f"(x), "=f"(y) : "l"(v));
}
__device__ __forceinline__ u64 fma2u(u64 a, u64 b, u64 c) {
    u64 d; asm("fma.rn.f32x2 %0, %1, %2, %3;" : "=l"(d) : "l"(a), "l"(b), "l"(c)); return d;
}
__device__ __forceinline__ u64 add2u(u64 a, u64 b) {
    u64 d; asm("add.rn.f32x2 %0, %1, %2;" : "=l"(d) : "l"(a), "l"(b)); return d;
}
__device__ __forceinline__ ulonglong2 lds2(const u64* p) {
    return *reinterpret_cast<const ulonglong2*>(p);
}

// ---------------- split-bf16 helpers (3xBF16 compensated GEMM) -------------
__device__ __forceinline__ void split_bf16x2(float e0, float e1,
                                             unsigned& hi, unsigned& lo) {
    asm("cvt.rn.bf16x2.f32 %0, %1, %2;" : "=r"(hi) : "f"(e1), "f"(e0));
    float h0 = __uint_as_float(hi << 16);
    float h1 = __uint_as_float(hi & 0xffff0000u);
    float r0 = e0 - h0, r1 = e1 - h1;
    asm("cvt.rn.bf16x2.f32 %0, %1, %2;" : "=r"(lo) : "f"(r1), "f"(r0));
}
__device__ __forceinline__ void mma_bf16(float* c, const unsigned* a, const unsigned* b) {
    asm volatile(
        "mma.sync.aligned.m16n8k16.row.col.f32.bf16.bf16.f32 "
        "{%0,%1,%2,%3},{%4,%5,%6,%7},{%8,%9},{%0,%1,%2,%3};"
        : "+f"(c[0]), "+f"(c[1]), "+f"(c[2]), "+f"(c[3])
        : "r"(a[0]), "r"(a[1]), "r"(a[2]), "r"(a[3]), "r"(b[0]), "r"(b[1]));
}

// ---- shuffle-scan series_decomp helper (replicate-pad MA-25) ----
__device__ __forceinline__ float decomp25(float val, int lane, int hi, int loix,
                                          int lom1, float fc0, float fc29) {
    float cs = val;
    #pragma unroll
    for (int off = 1; off < 32; off <<= 1) {
        float o = __shfl_up_sync(FULL, cs, off);
        if (lane >= off) cs += o;
    }
    float cshi = __shfl_sync(FULL, cs, hi);
    float cslo = __shfl_sync(FULL, cs, loix);
    float ssum = cshi - ((lom1 >= 0) ? cslo : 0.f);
    float x0  = __shfl_sync(FULL, val, 0);
    float x29 = __shfl_sync(FULL, val, 29);
    return val - (ssum + fc0 * x0 + fc29 * x29) * (1.f / 25.f);
}

// ---- warp-parallel top-3 with first-index tie-break, then softmax ----
__device__ __forceinline__ void top3softmax(float mv, int lane,
                                            float& w0, float& w1, float& w2,
                                            int& dl0, int& dl1, int& dl2) {
    float wv0, wv1, wv2;
    float mrun = mv;
    #pragma unroll
    for (int p = 0; p < 3; p++) {
        float bv = mrun; int bi = lane;
        #pragma unroll
        for (int off = 16; off; off >>= 1) {
            float vo = __shfl_xor_sync(FULL, bv, off);
            int   io = __shfl_xor_sync(FULL, bi, off);
            if (vo > bv || (vo == bv && io < bi)) { bv = vo; bi = io; }
        }
        if (p == 0) { wv0 = bv; dl0 = bi; }
        else if (p == 1) { wv1 = bv; dl1 = bi; }
        else { wv2 = bv; dl2 = bi; }
        if (lane == bi) mrun = -1e30f;
    }
    float e1 = expf(wv1 - wv0);
    float e2 = expf(wv2 - wv0);
    float inv = 1.f / (1.f + e1 + e2);
    w0 = inv; w1 = e1 * inv; w2 = e2 * inv;
}

// ---- circular correlation for one sample (lane = tau) ----
__device__ __forceinline__ float corr30(const u64* qsU, const u64* ksU,
                                        int t, bool act) {
    u64 acc2[4] = {};
    #pragma unroll
    for (int tq = 0; tq < 30; tq++) {
        int src = tq - t; if (src < 0) src += 30;
        ulonglong2 qa = lds2(qsU + tq*4), qb = lds2(qsU + tq*4 + 2);
        ulonglong2 ka = lds2(ksU + src*4), kb = lds2(ksU + src*4 + 2);
        acc2[0] = fma2u(qa.x, ka.x, acc2[0]);
        acc2[1] = fma2u(qa.y, ka.y, acc2[1]);
        acc2[2] = fma2u(qb.x, kb.x, acc2[2]);
        acc2[3] = fma2u(qb.y, kb.y, acc2[3]);
    }
    u64 s2 = add2u(add2u(acc2[0], acc2[1]), add2u(acc2[2], acc2[3]));
    float sx, sy; unpack2(s2, sx, sy);
    return act ? (sx + sy) * 0.125f : -1e30f;
}

// ============================================================================
// kW: pre-split weight images (W1 -> g_W1P, [W2;Wres] -> g_W2P)
// ============================================================================
__global__ void kW(const float* __restrict__ W1,
                   const float* __restrict__ W2,
                   const float* __restrict__ Wres)
{
    int idx = blockIdx.x * 256 + threadIdx.x;
    if (idx < 224 * 256) {
        int kp = idx >> 8, n = idx & 255;
        int r0 = 2 * kp, r1 = r0 + 1;
        float v0 = (r0 < 420) ? W1[(size_t)r0 * 256 + n] : 0.f;
        float v1 = (r1 < 420) ? W1[(size_t)r1 * 256 + n] : 0.f;
        unsigned h, l; split_bf16x2(v0, v1, h, l);
        g_W1P[idx] = make_uint2(h, l);
    }
    int idx2 = idx - 224 * 256;
    if (idx2 >= 0 && idx2 < 352 * 64) {
        int kp = idx2 >> 6, n = idx2 & 63;
        int r0 = 2 * kp, r1 = r0 + 1;
        float v0 = 0.f, v1 = 0.f;
        if (r0 < 256) v0 = W2[(size_t)r0 * 64 + n];
        else if (r0 - 256 < 420) v0 = Wres[(size_t)(r0 - 256) * 64 + n];
        if (r1 < 256) v1 = W2[(size_t)r1 * 64 + n];
        else if (r1 - 256 < 420) v1 = Wres[(size_t)(r1 - 256) * 64 + n];
        unsigned h, l; split_bf16x2(v0, v1, h, l);
        g_W2P[idx2] = make_uint2(h, l);
    }
}

// ============================================================================
// Kernel A: register-resident per-sample pipeline, FFMA2, 2 samples/warp.
// (R12 body; final store emits pre-split bf16 pairs into g_fP)
// ============================================================================
__global__ __launch_bounds__(256, 2) void kA(
    const float* __restrict__ x,
    const float* __restrict__ W_emb, const float* __restrict__ b_emb,
    const float* __restrict__ Wq, const float* __restrict__ bq,
    const float* __restrict__ Wk, const float* __restrict__ bk,
    const float* __restrict__ Wv, const float* __restrict__ bv,
    const float* __restrict__ Wo, const float* __restrict__ bo,
    const float* __restrict__ Wff1, const float* __restrict__ Wff2,
    const float* __restrict__ gnorm, const float* __restrict__ bnorm,
    const float* __restrict__ Wdy, const float* __restrict__ bdy,
    const float* __restrict__ channels)
{
    __shared__ __align__(16) float2 sWeP[336];
    __shared__ __align__(16) float  sbe[14];
    __shared__ __align__(16) float  sWq[112], sWk[112], sWv[112];
    __shared__ __align__(16) float  sbq[8], sbk[8], sbv[8];
    __shared__ __align__(16) float2 sWoP[64];
    __shared__ __align__(16) float  sbo[14];
    __shared__ __align__(16) float2 sF1P[400];
    __shared__ __align__(16) float2 sF2P[400];
    __shared__ __align__(16) float  sg[14], sb[14];
    __shared__ __align__(16) float  sWdy[900], sbdy[32];
    __shared__ __align__(16) float2 sAdjP[112];
    __shared__ __align__(16) float  scr[8][960];

    const int tid = threadIdx.x;
    for (int i = tid; i < 336; i += 256) {
        int ct = i >> 3, op = i & 7;
        float a = 0.f, b = 0.f;
        if (op < 7) { a = W_emb[(2*op)*42 + ct]; b = W_emb[(2*op+1)*42 + ct]; }
        sWeP[i] = make_float2(a, b);
    }
    for (int i = tid; i < 112; i += 256) { sWq[i]=Wq[i]; sWk[i]=Wk[i]; sWv[i]=Wv[i]; }
    for (int i = tid; i < 64; i += 256) {
        int h = i >> 3, dp = i & 7;
        float a = 0.f, b = 0.f;
        if (dp < 7) { a = Wo[h*14 + 2*dp]; b = Wo[h*14 + 2*dp + 1]; }
        sWoP[i] = make_float2(a, b);
    }
    for (int i = tid; i < 400; i += 256) {
        int f = i >> 3, dp = i & 7;
        float a1 = 0.f, b1v = 0.f, a2 = 0.f, b2v = 0.f;
        if (dp < 7) {
            a1 = Wff1[(2*dp)*50 + f]; b1v = Wff1[(2*dp+1)*50 + f];
            a2 = Wff2[f*14 + 2*dp];   b2v = Wff2[f*14 + 2*dp + 1];
        }
        sF1P[i] = make_float2(a1, b1v);
        sF2P[i] = make_float2(a2, b2v);
    }
    for (int i = tid; i < 900; i += 256) sWdy[i] = Wdy[i];
    if (tid < 30) sbdy[tid] = bdy[tid];
    if (tid < 14) { sbe[tid]=b_emb[tid]; sbo[tid]=bo[tid]; sg[tid]=gnorm[tid]; sb[tid]=bnorm[tid]; }
    if (tid < 8)  { sbq[tid]=bq[tid]; sbk[tid]=bk[tid]; sbv[tid]=bv[tid]; }
    if (tid < 14) {
        const float* row = channels + tid * 14;
        float mx = -1e30f;
        #pragma unroll
        for (int j = 0; j < 14; j++) mx = fmaxf(mx, row[j]);
        float s = 0.f;
        #pragma unroll
        for (int j = 0; j < 14; j++) s += expf(row[j] - mx);
        float inv = 1.f / s;
        #pragma unroll
        for (int j = 0; j < 7; j++)
            sAdjP[tid*8 + j] = make_float2(expf(row[2*j] - mx) * inv,
                                           expf(row[2*j+1] - mx) * inv);
        sAdjP[tid*8 + 7] = make_float2(0.f, 0.f);
    }
    __syncthreads();

    const int w    = tid >> 5;
    const int lane = tid & 31;
    const int t    = (lane < 30) ? lane : 0;
    const bool act = (lane < 30);
    const int smpA = blockIdx.x * 16 + w * 2;
    u64* scrU = reinterpret_cast<u64*>(scr[w]);

    {
        const float4* xpA = reinterpret_cast<const float4*>(x + (size_t)smpA * 420);
        const float4* xpB = reinterpret_cast<const float4*>(x + (size_t)(smpA+1) * 420);
        float4* sp = reinterpret_cast<float4*>(scr[w]);
        #pragma unroll
        for (int i = lane; i < 105; i += 32) { sp[i] = xpA[i]; sp[105 + i] = xpB[i]; }
    }
    __syncwarp();
    float xrA[14], xrB[14];
    #pragma unroll
    for (int d = 0; d < 14; d++) {
        xrA[d] = scr[w][t*14 + d];
        xrB[d] = scr[w][420 + t*14 + d];
    }
    __syncwarp();

    u64 xeA[7], xeB[7];
    {
        const u64* sbe2 = reinterpret_cast<const u64*>(sbe);
        #pragma unroll
        for (int op = 0; op < 7; op++) { xeA[op] = sbe2[op]; xeB[op] = sbe2[op]; }
        const u64* we = reinterpret_cast<const u64*>(sWeP);
        #pragma unroll
        for (int ci = 0; ci < 14; ci++) {
            float upA = __shfl_up_sync(FULL, xrA[ci], 1);
            float dnA = __shfl_down_sync(FULL, xrA[ci], 1);
            float upB = __shfl_up_sync(FULL, xrB[ci], 1);
            float dnB = __shfl_down_sync(FULL, xrB[ci], 1);
            float tapA[3] = { (lane > 0) ? upA : 0.f, xrA[ci], (lane < 29) ? dnA : 0.f };
            float tapB[3] = { (lane > 0) ? upB : 0.f, xrB[ci], (lane < 29) ? dnB : 0.f };
            #pragma unroll
            for (int tp = 0; tp < 3; tp++) {
                u64 xa = dup2(tapA[tp]), xb = dup2(tapB[tp]);
                const u64* wr = we + (ci*3 + tp) * 8;
                ulonglong2 w0 = lds2(wr), w1 = lds2(wr+2), w2 = lds2(wr+4);
                u64 w6 = wr[6];
                xeA[0] = fma2u(xa, w0.x, xeA[0]); xeB[0] = fma2u(xb, w0.x, xeB[0]);
                xeA[1] = fma2u(xa, w0.y, xeA[1]); xeB[1] = fma2u(xb, w0.y, xeB[1]);
                xeA[2] = fma2u(xa, w1.x, xeA[2]); xeB[2] = fma2u(xb, w1.x, xeB[2]);
                xeA[3] = fma2u(xa, w1.y, xeA[3]); xeB[3] = fma2u(xb, w1.y, xeB[3]);
                xeA[4] = fma2u(xa, w2.x, xeA[4]); xeB[4] = fma2u(xb, w2.x, xeB[4]);
                xeA[5] = fma2u(xa, w2.y, xeA[5]); xeB[5] = fma2u(xb, w2.y, xeB[5]);
                xeA[6] = fma2u(xa, w6,   xeA[6]); xeB[6] = fma2u(xb, w6,   xeB[6]);
            }
        }
    }

    u64 qA[4], kA_[4], vA[4], qB[4], kB_[4], vB[4];
    {
        const u64* bq2 = reinterpret_cast<const u64*>(sbq);
        const u64* bk2 = reinterpret_cast<const u64*>(sbk);
        const u64* bv2 = reinterpret_cast<const u64*>(sbv);
        #pragma unroll
        for (int hp = 0; hp < 4; hp++) {
            qA[hp]=bq2[hp]; kA_[hp]=bk2[hp]; vA[hp]=bv2[hp];
            qB[hp]=bq2[hp]; kB_[hp]=bk2[hp]; vB[hp]=bv2[hp];
        }
        const u64* wq2 = reinterpret_cast<const u64*>(sWq);
        const u64* wk2 = reinterpret_cast<const u64*>(sWk);
        const u64* wv2 = reinterpret_cast<const u64*>(sWv);
        #pragma unroll
        for (int dp = 0; dp < 7; dp++) {
            float ax, ay, bx, by;
            unpack2(xeA[dp], ax, ay);
            unpack2(xeB[dp], bx, by);
            float sA[2] = { ax, ay }, sB[2] = { bx, by };
            #pragma unroll
            for (int half = 0; half < 2; half++) {
                int d = 2*dp + half;
                u64 xa = dup2(sA[half]), xb = dup2(sB[half]);
                ulonglong2 qa = lds2(wq2 + d*4), qb = lds2(wq2 + d*4 + 2);
                ulonglong2 ka = lds2(wk2 + d*4), kb = lds2(wk2 + d*4 + 2);
                ulonglong2 va = lds2(wv2 + d*4), vb = lds2(wv2 + d*4 + 2);
                qA[0] = fma2u(xa, qa.x, qA[0]); qB[0] = fma2u(xb, qa.x, qB[0]);
                qA[1] = fma2u(xa, qa.y, qA[1]); qB[1] = fma2u(xb, qa.y, qB[1]);
                qA[2] = fma2u(xa, qb.x, qA[2]); qB[2] = fma2u(xb, qb.x, qB[2]);
                qA[3] = fma2u(xa, qb.y, qA[3]); qB[3] = fma2u(xb, qb.y, qB[3]);
                kA_[0] = fma2u(xa, ka.x, kA_[0]); kB_[0] = fma2u(xb, ka.x, kB_[0]);
                kA_[1] = fma2u(xa, ka.y, kA_[1]); kB_[1] = fma2u(xb, ka.y, kB_[1]);
                kA_[2] = fma2u(xa, kb.x, kA_[2]); kB_[2] = fma2u(xb, kb.x, kB_[2]);
                kA_[3] = fma2u(xa, kb.y, kA_[3]); kB_[3] = fma2u(xb, kb.y, kB_[3]);
                vA[0] = fma2u(xa, va.x, vA[0]); vB[0] = fma2u(xb, va.x, vB[0]);
                vA[1] = fma2u(xa, va.y, vA[1]); vB[1] = fma2u(xb, va.y, vB[1]);
                vA[2] = fma2u(xa, vb.x, vA[2]); vB[2] = fma2u(xb, vb.x, vB[2]);
                vA[3] = fma2u(xa, vb.y, vA[3]); vB[3] = fma2u(xb, vb.y, vB[3]);
            }
        }
    }

    u64* qsA = scrU;
    u64* ksA = scrU + 120;
    u64* qsB = scrU + 240;
    u64* ksB = scrU + 360;
    if (act) {
        *reinterpret_cast<ulonglong2*>(qsA + t*4)     = make_ulonglong2(qA[0], qA[1]);
        *reinterpret_cast<ulonglong2*>(qsA + t*4 + 2) = make_ulonglong2(qA[2], qA[3]);
        *reinterpret_cast<ulonglong2*>(ksA + t*4)     = make_ulonglong2(kA_[0], kA_[1]);
        *reinterpret_cast<ulonglong2*>(ksA + t*4 + 2) = make_ulonglong2(kA_[2], kA_[3]);
        *reinterpret_cast<ulonglong2*>(qsB + t*4)     = make_ulonglong2(qB[0], qB[1]);
        *reinterpret_cast<ulonglong2*>(qsB + t*4 + 2) = make_ulonglong2(qB[2], qB[3]);
        *reinterpret_cast<ulonglong2*>(ksB + t*4)     = make_ulonglong2(kB_[0], kB_[1]);
        *reinterpret_cast<ulonglong2*>(ksB + t*4 + 2) = make_ulonglong2(kB_[2], kB_[3]);
    }
    __syncwarp();

    float mvA = corr30(qsA, ksA, t, act);
    float mvB = corr30(qsB, ksB, t, act);
    float w0A, w1A, w2A, w0B, w1B, w2B;
    int dl0A, dl1A, dl2A, dl0B, dl1B, dl2B;
    top3softmax(mvA, lane, w0A, w1A, w2A, dl0A, dl1A, dl2A);
    top3softmax(mvB, lane, w0B, w1B, w2B, dl0B, dl1B, dl2B);

    u64 aggA[4], aggB[4];
    {
        int s0 = t + dl0A; if (s0 >= 30) s0 -= 30;
        int s1 = t + dl1A; if (s1 >= 30) s1 -= 30;
        int s2 = t + dl2A; if (s2 >= 30) s2 -= 30;
        u64 c0 = dup2(w0A), c1 = dup2(w1A), c2 = dup2(w2A);
        #pragma unroll
        for (int hp = 0; hp < 4; hp++) {
            u64 y0 = __shfl_sync(FULL, vA[hp], s0);
            u64 y1 = __shfl_sync(FULL, vA[hp], s1);
            u64 y2 = __shfl_sync(FULL, vA[hp], s2);
            aggA[hp] = fma2u(c0, y0, fma2u(c1, y1, fma2u(c2, y2, 0ULL)));
        }
    }
    {
        int s0 = t + dl0B; if (s0 >= 30) s0 -= 30;
        int s1 = t + dl1B; if (s1 >= 30) s1 -= 30;
        int s2 = t + dl2B; if (s2 >= 30) s2 -= 30;
        u64 c0 = dup2(w0B), c1 = dup2(w1B), c2 = dup2(w2B);
        #pragma unroll
        for (int hp = 0; hp < 4; hp++) {
            u64 y0 = __shfl_sync(FULL, vB[hp], s0);
            u64 y1 = __shfl_sync(FULL, vB[hp], s1);
            u64 y2 = __shfl_sync(FULL, vB[hp], s2);
            aggB[hp] = fma2u(c0, y0, fma2u(c1, y1, fma2u(c2, y2, 0ULL)));
        }
    }

    u64 x1A[7], x1B[7];
    {
        const u64* sbo2 = reinterpret_cast<const u64*>(sbo);
        #pragma unroll
        for (int dp = 0; dp < 7; dp++) {
            x1A[dp] = add2u(xeA[dp], sbo2[dp]);
            x1B[dp] = add2u(xeB[dp], sbo2[dp]);
        }
        const u64* wo = reinterpret_cast<const u64*>(sWoP);
        #pragma unroll
        for (int hp = 0; hp < 4; hp++) {
            float aAx, aAy, aBx, aBy;
            unpack2(aggA[hp], aAx, aAy);
            unpack2(aggB[hp], aBx, aBy);
            float sA[2] = { aAx, aAy }, sB[2] = { aBx, aBy };
            #pragma unroll
            for (int half = 0; half < 2; half++) {
                int h = 2*hp + half;
                u64 aa = dup2(sA[half]), ab = dup2(sB[half]);
                const u64* wr = wo + h*8;
                ulonglong2 w0v = lds2(wr), w1v = lds2(wr+2), w2v = lds2(wr+4);
                u64 w6 = wr[6];
                x1A[0] = fma2u(aa, w0v.x, x1A[0]); x1B[0] = fma2u(ab, w0v.x, x1B[0]);
                x1A[1] = fma2u(aa, w0v.y, x1A[1]); x1B[1] = fma2u(ab, w0v.y, x1B[1]);
                x1A[2] = fma2u(aa, w1v.x, x1A[2]); x1B[2] = fma2u(ab, w1v.x, x1B[2]);
                x1A[3] = fma2u(aa, w1v.y, x1A[3]); x1B[3] = fma2u(ab, w1v.y, x1B[3]);
                x1A[4] = fma2u(aa, w2v.x, x1A[4]); x1B[4] = fma2u(ab, w2v.x, x1B[4]);
                x1A[5] = fma2u(aa, w2v.y, x1A[5]); x1B[5] = fma2u(ab, w2v.y, x1B[5]);
                x1A[6] = fma2u(aa, w6,    x1A[6]); x1B[6] = fma2u(ab, w6,    x1B[6]);
            }
        }
    }

    const float fc0  = (t < 12) ? (float)(12 - t) : 0.f;
    const float fc29 = (t > 17) ? (float)(t - 17) : 0.f;
    const int hi   = (t + 12 > 29) ? 29 : t + 12;
    const int lom1 = t - 13;
    const int loix = (lom1 < 0) ? 0 : lom1;
    u64 xdA[7], xdB[7];
    #pragma unroll
    for (int dp = 0; dp < 7; dp++) {
        float vx, vy;
        unpack2(x1A[dp], vx, vy);
        xdA[dp] = pack2(decomp25(vx, lane, hi, loix, lom1, fc0, fc29),
                        decomp25(vy, lane, hi, loix, lom1, fc0, fc29));
        unpack2(x1B[dp], vx, vy);
        xdB[dp] = pack2(decomp25(vx, lane, hi, loix, lom1, fc0, fc29),
                        decomp25(vy, lane, hi, loix, lom1, fc0, fc29));
    }

    u64 x2A[7], x2B[7];
    {
        u64 yA[7] = {}, yB[7] = {};
        const u64* f1 = reinterpret_cast<const u64*>(sF1P);
        const u64* f2 = reinterpret_cast<const u64*>(sF2P);
        #pragma unroll 5
        for (int f = 0; f < 50; f++) {
            const u64* r1 = f1 + f*8;
            ulonglong2 a0 = lds2(r1), a1 = lds2(r1+2), a2l = lds2(r1+4);
            u64 a6 = r1[6];
            u64 hA = fma2u(xdA[0], a0.x, 0ULL);
            u64 hB = fma2u(xdB[0], a0.x, 0ULL);
            hA = fma2u(xdA[1], a0.y, hA);   hB = fma2u(xdB[1], a0.y, hB);
            hA = fma2u(xdA[2], a1.x, hA);   hB = fma2u(xdB[2], a1.x, hB);
            hA = fma2u(xdA[3], a1.y, hA);   hB = fma2u(xdB[3], a1.y, hB);
            hA = fma2u(xdA[4], a2l.x, hA);  hB = fma2u(xdB[4], a2l.x, hB);
            hA = fma2u(xdA[5], a2l.y, hA);  hB = fma2u(xdB[5], a2l.y, hB);
            hA = fma2u(xdA[6], a6, hA);     hB = fma2u(xdB[6], a6, hB);
            float hx, hy;
            unpack2(hA, hx, hy);
            float hsA = hx + hy;
            unpack2(hB, hx, hy);
            float hsB = hx + hy;
            float gAv = 0.5f * hsA * (1.f + erff(hsA * 0.70710678118654752f));
            float gBv = 0.5f * hsB * (1.f + erff(hsB * 0.70710678118654752f));
            u64 gA2 = dup2(gAv), gB2 = dup2(gBv);
            const u64* r2 = f2 + f*8;
            ulonglong2 b0 = lds2(r2), b1v = lds2(r2+2), b2v = lds2(r2+4);
            u64 b6 = r2[6];
            yA[0] = fma2u(gA2, b0.x, yA[0]);  yB[0] = fma2u(gB2, b0.x, yB[0]);
            yA[1] = fma2u(gA2, b0.y, yA[1]);  yB[1] = fma2u(gB2, b0.y, yB[1]);
            yA[2] = fma2u(gA2, b1v.x, yA[2]); yB[2] = fma2u(gB2, b1v.x, yB[2]);
            yA[3] = fma2u(gA2, b1v.y, yA[3]); yB[3] = fma2u(gB2, b1v.y, yB[3]);
            yA[4] = fma2u(gA2, b2v.x, yA[4]); yB[4] = fma2u(gB2, b2v.x, yB[4]);
            yA[5] = fma2u(gA2, b2v.y, yA[5]); yB[5] = fma2u(gB2, b2v.y, yB[5]);
            yA[6] = fma2u(gA2, b6, yA[6]);    yB[6] = fma2u(gB2, b6, yB[6]);
        }
        #pragma unroll
        for (int dp = 0; dp < 7; dp++) {
            x2A[dp] = add2u(xdA[dp], yA[dp]);
            x2B[dp] = add2u(xdB[dp], yB[dp]);
        }
    }

    float x3Ax[7], x3Ay[7], x3Bx[7], x3By[7];
    #pragma unroll
    for (int dp = 0; dp < 7; dp++) {
        float vx, vy;
        unpack2(x2A[dp], vx, vy);
        x3Ax[dp] = decomp25(vx, lane, hi, loix, lom1, fc0, fc29);
        x3Ay[dp] = decomp25(vy, lane, hi, loix, lom1, fc0, fc29);
        unpack2(x2B[dp], vx, vy);
        x3Bx[dp] = decomp25(vx, lane, hi, loix, lom1, fc0, fc29);
        x3By[dp] = decomp25(vy, lane, hi, loix, lom1, fc0, fc29);
    }
    {
        float mA = 0.f, mB = 0.f;
        #pragma unroll
        for (int dp = 0; dp < 7; dp++) { mA += x3Ax[dp] + x3Ay[dp]; mB += x3Bx[dp] + x3By[dp]; }
        mA *= (1.f / 14.f); mB *= (1.f / 14.f);
        float vA_ = 0.f, vB_ = 0.f;
        #pragma unroll
        for (int dp = 0; dp < 7; dp++) {
            float dx = x3Ax[dp] - mA, dy = x3Ay[dp] - mA;
            vA_ += dx * dx + dy * dy;
            dx = x3Bx[dp] - mB; dy = x3By[dp] - mB;
            vB_ += dx * dx + dy * dy;
        }
        vA_ *= (1.f / 14.f); vB_ *= (1.f / 14.f);
        float iA = rsqrtf(vA_ + 1e-5f), iB = rsqrtf(vB_ + 1e-5f);
        #pragma unroll
        for (int dp = 0; dp < 7; dp++) {
            float g0 = sg[2*dp], g1 = sg[2*dp+1], b0 = sb[2*dp], b1v = sb[2*dp+1];
            x3Ax[dp] = (x3Ax[dp] - mA) * iA * g0 + b0;
            x3Ay[dp] = (x3Ay[dp] - mA) * iA * g1 + b1v;
            x3Bx[dp] = (x3Bx[dp] - mB) * iB * g0 + b0;
            x3By[dp] = (x3By[dp] - mB) * iB * g1 + b1v;
        }
    }

    __syncwarp();
    u64* x3sA = scrU;
    u64* x3sB = scrU + 240;
    if (act) {
        *reinterpret_cast<ulonglong2*>(x3sA + t*8)     = make_ulonglong2(pack2(x3Ax[0], x3Ay[0]), pack2(x3Ax[1], x3Ay[1]));
        *reinterpret_cast<ulonglong2*>(x3sA + t*8 + 2) = make_ulonglong2(pack2(x3Ax[2], x3Ay[2]), pack2(x3Ax[3], x3Ay[3]));
        *reinterpret_cast<ulonglong2*>(x3sA + t*8 + 4) = make_ulonglong2(pack2(x3Ax[4], x3Ay[4]), pack2(x3Ax[5], x3Ay[5]));
        x3sA[t*8 + 6] = pack2(x3Ax[6], x3Ay[6]);
        *reinterpret_cast<ulonglong2*>(x3sB + t*8)     = make_ulonglong2(pack2(x3Bx[0], x3By[0]), pack2(x3Bx[1], x3By[1]));
        *reinterpret_cast<ulonglong2*>(x3sB + t*8 + 2) = make_ulonglong2(pack2(x3Bx[2], x3By[2]), pack2(x3Bx[3], x3By[3]));
        *reinterpret_cast<ulonglong2*>(x3sB + t*8 + 4) = make_ulonglong2(pack2(x3Bx[4], x3By[4]), pack2(x3Bx[5], x3By[5]));
        x3sB[t*8 + 6] = pack2(x3Bx[6], x3By[6]);
    }
    __syncwarp();
    u64 accA[7], accB[7];
    {
        u64 bias2 = dup2(sbdy[t]);
        #pragma unroll
        for (int dp = 0; dp < 7; dp++) { accA[dp] = bias2; accB[dp] = bias2; }
        #pragma unroll
        for (int m = 0; m < 30; m++) {
            u64 wm2 = dup2(sWdy[m*30 + t]);
            const u64* xa = x3sA + m*8;
            const u64* xb = x3sB + m*8;
            ulonglong2 a0 = lds2(xa), a1 = lds2(xa+2), a2l = lds2(xa+4);
            u64 a6 = xa[6];
            ulonglong2 b0 = lds2(xb), b1v = lds2(xb+2), b2v = lds2(xb+4);
            u64 b6 = xb[6];
            accA[0] = fma2u(a0.x, wm2, accA[0]);  accB[0] = fma2u(b0.x, wm2, accB[0]);
            accA[1] = fma2u(a0.y, wm2, accA[1]);  accB[1] = fma2u(b0.y, wm2, accB[1]);
            accA[2] = fma2u(a1.x, wm2, accA[2]);  accB[2] = fma2u(b1v.x, wm2, accB[2]);
            accA[3] = fma2u(a1.y, wm2, accA[3]);  accB[3] = fma2u(b1v.y, wm2, accB[3]);
            accA[4] = fma2u(a2l.x, wm2, accA[4]); accB[4] = fma2u(b2v.x, wm2, accB[4]);
            accA[5] = fma2u(a2l.y, wm2, accA[5]); accB[5] = fma2u(b2v.y, wm2, accB[5]);
            accA[6] = fma2u(a6,   wm2, accA[6]);  accB[6] = fma2u(b6,   wm2, accB[6]);
        }
    }

    // ---- dy = relu(adj @ h2) -> g_fP (pre-split bf16 pairs; pair via shfl) ----
    {
        uint2* foA = g_fP + (size_t)smpA * 210;
        uint2* foB = g_fP + (size_t)(smpA+1) * 210;
        const u64* adj = reinterpret_cast<const u64*>(sAdjP);
        #pragma unroll
        for (int i = 0; i < 14; i++) {
            const u64* ar = adj + i*8;
            ulonglong2 a0 = lds2(ar), a1 = lds2(ar+2), a2l = lds2(ar+4);
            u64 a6 = ar[6];
            u64 sA2 = fma2u(a0.x, accA[0], 0ULL);
            u64 sB2 = fma2u(a0.x, accB[0], 0ULL);
            sA2 = fma2u(a0.y, accA[1], sA2);  sB2 = fma2u(a0.y, accB[1], sB2);
            sA2 = fma2u(a1.x, accA[2], sA2);  sB2 = fma2u(a1.x, accB[2], sB2);
            sA2 = fma2u(a1.y, accA[3], sA2);  sB2 = fma2u(a1.y, accB[3], sB2);
            sA2 = fma2u(a2l.x, accA[4], sA2); sB2 = fma2u(a2l.x, accB[4], sB2);
            sA2 = fma2u(a2l.y, accA[5], sA2); sB2 = fma2u(a2l.y, accB[5], sB2);
            sA2 = fma2u(a6, accA[6], sA2);    sB2 = fma2u(a6, accB[6], sB2);
            float ax, ay;
            unpack2(sA2, ax, ay);
            float valA = fmaxf(ax + ay, 0.f);
            unpack2(sB2, ax, ay);
            float valB = fmaxf(ax + ay, 0.f);
            float vnA = __shfl_down_sync(FULL, valA, 1);
            float vnB = __shfl_down_sync(FULL, valB, 1);
            if (act && !(lane & 1)) {
                unsigned h, l;
                split_bf16x2(valA, vnA, h, l);
                foA[i*15 + (t >> 1)] = make_uint2(h, l);
                split_bf16x2(valB, vnB, h, l);
                foB[i*15 + (t >> 1)] = make_uint2(h, l);
            }
        }
    }
}

// ============================================================================
// Kernel B (3xBF16 m16n8k16, all-pre-split): hh = relu(f @ W1 + b1)
// M=65536, K=448(pad), N=256. BM=128, BN=64 (grid.y=4), BK=32 (16 kp).
// Emits hh pre-split into g_hhP.
// ============================================================================
__global__ __launch_bounds__(256) void kB(const float* __restrict__ b1)
{
    __shared__ __align__(16) uint2 Ahl[128][20];   // [m][kp] (16 used)
    __shared__ __align__(16) uint2 Bhl[64][20];    // [n][kp]
    const int tid = threadIdx.x;
    const int lane = tid & 31, wid = tid >> 5;
    const int wm = wid >> 1, wn = wid & 1;
    const int c4 = lane & 3;
    const size_t mbase = (size_t)blockIdx.x * 128;
    const int nbase = blockIdx.y * 64;
    float c[2][4][4] = {};

    for (int k0 = 0; k0 < 448; k0 += 32) {
        // A stage: pure copy from g_fP (zeros past pair 209)
        {
            int m = tid >> 1, half = tid & 1;
            const uint2* fr = g_fP + (size_t)(mbase + m) * 210;
            int kpg0 = (k0 >> 1) + half * 8;
            #pragma unroll
            for (int j = 0; j < 8; j += 2) {
                int kpg = kpg0 + j;
                uint4 v = make_uint4(0u, 0u, 0u, 0u);
                if (kpg < 210) v = *reinterpret_cast<const uint4*>(fr + kpg);
                *reinterpret_cast<uint4*>(&Ahl[m][half*8 + j]) = v;
            }
        }
        // B stage: pure copy from g_W1P
        {
            int kp = tid >> 4;
            int n4 = (tid & 15) * 4;
            const uint2* wp = g_W1P + (size_t)((k0 >> 1) + kp) * 256 + nbase + n4;
            uint4 v01 = *reinterpret_cast<const uint4*>(wp);
            uint4 v23 = *reinterpret_cast<const uint4*>(wp + 2);
            Bhl[n4+0][kp] = make_uint2(v01.x, v01.y);
            Bhl[n4+1][kp] = make_uint2(v01.z, v01.w);
            Bhl[n4+2][kp] = make_uint2(v23.x, v23.y);
            Bhl[n4+3][kp] = make_uint2(v23.z, v23.w);
        }
        __syncthreads();
        #pragma unroll
        for (int ks = 0; ks < 2; ks++) {
            int kb = ks * 8;
            unsigned ah[2][4], al[2][4], bh[4][2], bl[4][2];
            #pragma unroll
            for (int mt = 0; mt < 2; mt++) {
                int r = wm*32 + mt*16 + (lane>>2);
                uint2 e;
                e = Ahl[r  ][kb + c4];     ah[mt][0] = e.x; al[mt][0] = e.y;
                e = Ahl[r+8][kb + c4];     ah[mt][1] = e.x; al[mt][1] = e.y;
                e = Ahl[r  ][kb + c4 + 4]; ah[mt][2] = e.x; al[mt][2] = e.y;
                e = Ahl[r+8][kb + c4 + 4]; ah[mt][3] = e.x; al[mt][3] = e.y;
            }
            #pragma unroll
            for (int nt = 0; nt < 4; nt++) {
                int nn = wn*32 + nt*8 + (lane>>2);
                uint2 e;
                e = Bhl[nn][kb + c4];     bh[nt][0] = e.x; bl[nt][0] = e.y;
                e = Bhl[nn][kb + c4 + 4]; bh[nt][1] = e.x; bl[nt][1] = e.y;
            }
            #pragma unroll
            for (int mt = 0; mt < 2; mt++)
                #pragma unroll
                for (int nt = 0; nt < 4; nt++) {
                    mma_bf16(c[mt][nt], ah[mt], bh[nt]);
                    mma_bf16(c[mt][nt], ah[mt], bl[nt]);
                    mma_bf16(c[mt][nt], al[mt], bh[nt]);
                }
        }
        __syncthreads();
    }
    // epilogue: relu(+b1), pre-split into g_hhP
    #pragma unroll
    for (int mt = 0; mt < 2; mt++) {
        int r0 = wm*32 + mt*16 + (lane>>2);
        #pragma unroll
        for (int nt = 0; nt < 4; nt++) {
            int cl = nbase + wn*32 + nt*8 + 2*(lane&3);
            float b0 = b1[cl], b1v = b1[cl+1];
            float v0 = fmaxf(c[mt][nt][0] + b0, 0.f);
            float v1 = fmaxf(c[mt][nt][1] + b1v, 0.f);
            float v2 = fmaxf(c[mt][nt][2] + b0, 0.f);
            float v3 = fmaxf(c[mt][nt][3] + b1v, 0.f);
            unsigned h, l;
            split_bf16x2(v0, v1, h, l);
            g_hhP[(mbase + r0) * 128 + (cl >> 1)] = make_uint2(h, l);
            split_bf16x2(v2, v3, h, l);
            g_hhP[(mbase + r0 + 8) * 128 + (cl >> 1)] = make_uint2(h, l);
        }
    }
}

// ============================================================================
// Kernel C (3xBF16, all-pre-split, fused LN head):
// hr = [hh|f]@[W2;Wres]+b2+bres, out = LN64(hr)@W3+b3. K=704(pad), BK=32.
// ============================================================================
__global__ __launch_bounds__(256) void kC(const float* __restrict__ b2,
                                          const float* __restrict__ bres,
                                          const float* __restrict__ g_ln,
                                          const float* __restrict__ b_ln,
                                          const float* __restrict__ W3,
                                          const float* __restrict__ b3,
                                          float* __restrict__ out)
{
    __shared__ __align__(16) uint2 Ahl[128][20];
    __shared__ __align__(16) uint2 Bhl[64][20];
    __shared__ float sbb[64];
    __shared__ float sgw[64];
    __shared__ float sp[128][2][3];
    __shared__ float sconst[2];
    const int tid = threadIdx.x;
    const int lane = tid & 31, wid = tid >> 5;
    const int wm = wid >> 1, wn = wid & 1;
    const int c4 = lane & 3;
    const size_t mbase = (size_t)blockIdx.x * 128;
    float c[2][4][4] = {};

    if (tid < 64) {
        sbb[tid] = b2[tid] + bres[tid];
        sgw[tid] = g_ln[tid] * W3[tid];
    }

    for (int k0 = 0; k0 < 704; k0 += 32) {
        // A stage: copy from [g_hhP (128 pairs) | g_fP (210 pairs)]
        {
            int m = tid >> 1, half = tid & 1;
            const uint2* hrow = g_hhP + (size_t)(mbase + m) * 128;
            const uint2* frow = g_fP  + (size_t)(mbase + m) * 210;
            int kpg0 = (k0 >> 1) + half * 8;
            #pragma unroll
            for (int j = 0; j < 8; j += 2) {
                int kpg = kpg0 + j;
                uint4 v = make_uint4(0u, 0u, 0u, 0u);
                if (kpg < 128) v = *reinterpret_cast<const uint4*>(hrow + kpg);
                else if (kpg < 338) v = *reinterpret_cast<const uint4*>(frow + (kpg - 128));
                *reinterpret_cast<uint4*>(&Ahl[m][half*8 + j]) = v;
            }
        }
        // B stage: copy from g_W2P
        {
            int kp = tid >> 4;
            int n4 = (tid & 15) * 4;
            const uint2* wp = g_W2P + (size_t)((k0 >> 1) + kp) * 64 + n4;
            uint4 v01 = *reinterpret_cast<const uint4*>(wp);
            uint4 v23 = *reinterpret_cast<const uint4*>(wp + 2);
            Bhl[n4+0][kp] = make_uint2(v01.x, v01.y);
            Bhl[n4+1][kp] = make_uint2(v01.z, v01.w);
            Bhl[n4+2][kp] = make_uint2(v23.x, v23.y);
            Bhl[n4+3][kp] = make_uint2(v23.z, v23.w);
        }
        __syncthreads();
        #pragma unroll
        for (int ks = 0; ks < 2; ks++) {
            int kb = ks * 8;
            unsigned ah[2][4], al[2][4], bh[4][2], bl[4][2];
            #pragma unroll
            for (int mt = 0; mt < 2; mt++) {
                int r = wm*32 + mt*16 + (lane>>2);
                uint2 e;
                e = Ahl[r  ][kb + c4];     ah[mt][0] = e.x; al[mt][0] = e.y;
                e = Ahl[r+8][kb + c4];     ah[mt][1] = e.x; al[mt][1] = e.y;
                e = Ahl[r  ][kb + c4 + 4]; ah[mt][2] = e.x; al[mt][2] = e.y;
                e = Ahl[r+8][kb + c4 + 4]; ah[mt][3] = e.x; al[mt][3] = e.y;
            }
            #pragma unroll
            for (int nt = 0; nt < 4; nt++) {
                int nn = wn*32 + nt*8 + (lane>>2);
                uint2 e;
                e = Bhl[nn][kb + c4];     bh[nt][0] = e.x; bl[nt][0] = e.y;
                e = Bhl[nn][kb + c4 + 4]; bh[nt][1] = e.x; bl[nt][1] = e.y;
            }
            #pragma unroll
            for (int mt = 0; mt < 2; mt++)
                #pragma unroll
                for (int nt = 0; nt < 4; nt++) {
                    mma_bf16(c[mt][nt], ah[mt], bh[nt]);
                    mma_bf16(c[mt][nt], ah[mt], bl[nt]);
                    mma_bf16(c[mt][nt], al[mt], bh[nt]);
                }
        }
        __syncthreads();
    }

    // ---- fused epilogue: partial LN sums per (row, wn-half) ----
    #pragma unroll
    for (int mt = 0; mt < 2; mt++) {
        #pragma unroll
        for (int rb = 0; rb < 2; rb++) {
            float sv = 0.f, sq = 0.f, sgd = 0.f;
            #pragma unroll
            for (int nt = 0; nt < 4; nt++) {
                int cl = wn*32 + nt*8 + 2*(lane&3);
                float v0 = c[mt][nt][2*rb]     + sbb[cl];
                float v1 = c[mt][nt][2*rb + 1] + sbb[cl+1];
                sv += v0 + v1;
                sq += v0*v0 + v1*v1;
                sgd += v0*sgw[cl] + v1*sgw[cl+1];
            }
            sv += __shfl_xor_sync(FULL, sv, 1);
            sq += __shfl_xor_sync(FULL, sq, 1);
            sgd += __shfl_xor_sync(FULL, sgd, 1);
            sv += __shfl_xor_sync(FULL, sv, 2);
            sq += __shfl_xor_sync(FULL, sq, 2);
            sgd += __shfl_xor_sync(FULL, sgd, 2);
            if ((lane & 3) == 0) {
                int row = wm*32 + mt*16 + rb*8 + (lane>>2);
                sp[row][wn][0] = sv;
                sp[row][wn][1] = sq;
                sp[row][wn][2] = sgd;
            }
        }
    }
    if (tid == 0) {
        float G = 0.f, cb = b3[0];
        for (int d = 0; d < 64; d++) { G += sgw[d]; cb += b_ln[d] * W3[d]; }
        sconst[0] = G; sconst[1] = cb;
    }
    __syncthreads();
    if (tid < 128) {
        int row = tid;
        float sv  = sp[row][0][0] + sp[row][1][0];
        float sq  = sp[row][0][1] + sp[row][1][1];
        float sgd = sp[row][0][2] + sp[row][1][2];
        float m = sv * (1.f / 64.f);
        float var = sq * (1.f / 64.f) - m * m;
        float invs = rsqrtf(var + 1e-5f);
        out[mbase + row] = invs * (sgd - m * sconst[0]) + sconst[1];
    }
}

// ============================================================================
extern "C" void kernel_launch(void* const* d_in, const int* in_sizes, int n_in,
                              void* d_out, int out_size)
{
    (void)in_sizes; (void)n_in; (void)out_size;
    const float* x = (const float*)d_in[0];

    kW<<<312, 256>>>((const float*)d_in[18], (const float*)d_in[20],
                     (const float*)d_in[22]);

    kA<<<BATCH / 16, 256>>>(x,
        (const float*)d_in[1],  (const float*)d_in[2],
        (const float*)d_in[3],  (const float*)d_in[4],
        (const float*)d_in[5],  (const float*)d_in[6],
        (const float*)d_in[7],  (const float*)d_in[8],
        (const float*)d_in[9],  (const float*)d_in[10],
        (const float*)d_in[11], (const float*)d_in[12],
        (const float*)d_in[13], (const float*)d_in[14],
        (const float*)d_in[15], (const float*)d_in[16],
        (const float*)d_in[17]);

    kB<<<dim3(BATCH / 128, 4), 256>>>((const float*)d_in[19]);

    kC<<<BATCH / 128, 256>>>((const float*)d_in[21], (const float*)d_in[23],
                             (const float*)d_in[24], (const float*)d_in[25],
                             (const float*)d_in[26], (const float*)d_in[27],
                             (float*)d_out);
}

// round 14
// speedup vs baseline: 1.0053x; 1.0053x over previous
#include <cuda_runtime.h>
#include <math.h>

#define BATCH 65536
#define FULL 0xffffffffu

typedef unsigned long long u64;

// -------- device scratch (allocation-free rule: __device__ globals) --------
__device__ float g_f [(size_t)BATCH * 420];                 // DyConv output (f32)
__device__ __align__(16) uint2 g_hhP[(size_t)BATCH * 128];  // hh pre-split, 128 k-pairs
__device__ __align__(16) uint2 g_W1P[224 * 256];            // W1 padded K448 -> [kp][n]
__device__ __align__(16) uint2 g_W2P[352 * 64];             // [W2;Wres] padded K704 -> [kp][n]

// ---------------- packed f32x2 ops on b64 registers ----------------
__device__ __forceinline__ u64 pack2(float x, float y) {
    u64 r; asm("mov.b64 %0, {%1, %2};" : "=l"(r) : "f"(x), "f"(y)); return r;
}
__device__ __forceinline__ u64 dup2(float s) { return pack2(s, s); }
__device__ __forceinline__ void unpack2(u64 v, float& x, float& y) {
    asm("mov.b64 {%0, %1}, %2;" : "=f"(x), "=f"(y) : "l"(v));
}
__device__ __forceinline__ u64 fma2u(u64 a, u64 b, u64 c) {
    u64 d; asm("fma.rn.f32x2 %0, %1, %2, %3;" : "=l"(d) : "l"(a), "l"(b), "l"(c)); return d;
}
__device__ __forceinline__ u64 add2u(u64 a, u64 b) {
    u64 d; asm("add.rn.f32x2 %0, %1, %2;" : "=l"(d) : "l"(a), "l"(b)); return d;
}
__device__ __forceinline__ ulonglong2 lds2(const u64* p) {
    return *reinterpret_cast<const ulonglong2*>(p);
}

// ---------------- split-bf16 helpers (3xBF16 compensated GEMM) -------------
__device__ __forceinline__ void split_bf16x2(float e0, float e1,
                                             unsigned& hi, unsigned& lo) {
    asm("cvt.rn.bf16x2.f32 %0, %1, %2;" : "=r"(hi) : "f"(e1), "f"(e0));
    float h0 = __uint_as_float(hi << 16);
    float h1 = __uint_as_float(hi & 0xffff0000u);
    float r0 = e0 - h0, r1 = e1 - h1;
    asm("cvt.rn.bf16x2.f32 %0, %1, %2;" : "=r"(lo) : "f"(r1), "f"(r0));
}
__device__ __forceinline__ void mma_bf16(float* c, const unsigned* a, const unsigned* b) {
    asm volatile(
        "mma.sync.aligned.m16n8k16.row.col.f32.bf16.bf16.f32 "
        "{%0,%1,%2,%3},{%4,%5,%6,%7},{%8,%9},{%0,%1,%2,%3};"
        : "+f"(c[0]), "+f"(c[1]), "+f"(c[2]), "+f"(c[3])
        : "r"(a[0]), "r"(a[1]), "r"(a[2]), "r"(a[3]), "r"(b[0]), "r"(b[1]));
}

// ---- shuffle-scan series_decomp helper (replicate-pad MA-25) ----
__device__ __forceinline__ float decomp25(float val, int lane, int hi, int loix,
                                          int lom1, float fc0, float fc29) {
    float cs = val;
    #pragma unroll
    for (int off = 1; off < 32; off <<= 1) {
        float o = __shfl_up_sync(FULL, cs, off);
        if (lane >= off) cs += o;
    }
    float cshi = __shfl_sync(FULL, cs, hi);
    float cslo = __shfl_sync(FULL, cs, loix);
    float ssum = cshi - ((lom1 >= 0) ? cslo : 0.f);
    float x0  = __shfl_sync(FULL, val, 0);
    float x29 = __shfl_sync(FULL, val, 29);
    return val - (ssum + fc0 * x0 + fc29 * x29) * (1.f / 25.f);
}

// ---- warp-parallel top-3 with first-index tie-break, then softmax ----
__device__ __forceinline__ void top3softmax(float mv, int lane,
                                            float& w0, float& w1, float& w2,
                                            int& dl0, int& dl1, int& dl2) {
    float wv0, wv1, wv2;
    float mrun = mv;
    #pragma unroll
    for (int p = 0; p < 3; p++) {
        float bv = mrun; int bi = lane;
        #pragma unroll
        for (int off = 16; off; off >>= 1) {
            float vo = __shfl_xor_sync(FULL, bv, off);
            int   io = __shfl_xor_sync(FULL, bi, off);
            if (vo > bv || (vo == bv && io < bi)) { bv = vo; bi = io; }
        }
        if (p == 0) { wv0 = bv; dl0 = bi; }
        else if (p == 1) { wv1 = bv; dl1 = bi; }
        else { wv2 = bv; dl2 = bi; }
        if (lane == bi) mrun = -1e30f;
    }
    float e1 = expf(wv1 - wv0);
    float e2 = expf(wv2 - wv0);
    float inv = 1.f / (1.f + e1 + e2);
    w0 = inv; w1 = e1 * inv; w2 = e2 * inv;
}

// ---- circular correlation for one sample (lane = tau) ----
__device__ __forceinline__ float corr30(const u64* qsU, const u64* ksU,
                                        int t, bool act) {
    u64 acc2[4] = {};
    #pragma unroll
    for (int tq = 0; tq < 30; tq++) {
        int src = tq - t; if (src < 0) src += 30;
        ulonglong2 qa = lds2(qsU + tq*4), qb = lds2(qsU + tq*4 + 2);
        ulonglong2 ka = lds2(ksU + src*4), kb = lds2(ksU + src*4 + 2);
        acc2[0] = fma2u(qa.x, ka.x, acc2[0]);
        acc2[1] = fma2u(qa.y, ka.y, acc2[1]);
        acc2[2] = fma2u(qb.x, kb.x, acc2[2]);
        acc2[3] = fma2u(qb.y, kb.y, acc2[3]);
    }
    u64 s2 = add2u(add2u(acc2[0], acc2[1]), add2u(acc2[2], acc2[3]));
    float sx, sy; unpack2(s2, sx, sy);
    return act ? (sx + sy) * 0.125f : -1e30f;
}

// ============================================================================
// kW: pre-split weight images (W1 -> g_W1P, [W2;Wres] -> g_W2P)
// ============================================================================
__global__ void kW(const float* __restrict__ W1,
                   const float* __restrict__ W2,
                   const float* __restrict__ Wres)
{
    int idx = blockIdx.x * 256 + threadIdx.x;
    if (idx < 224 * 256) {
        int kp = idx >> 8, n = idx & 255;
        int r0 = 2 * kp, r1 = r0 + 1;
        float v0 = (r0 < 420) ? W1[(size_t)r0 * 256 + n] : 0.f;
        float v1 = (r1 < 420) ? W1[(size_t)r1 * 256 + n] : 0.f;
        unsigned h, l; split_bf16x2(v0, v1, h, l);
        g_W1P[idx] = make_uint2(h, l);
    }
    int idx2 = idx - 224 * 256;
    if (idx2 >= 0 && idx2 < 352 * 64) {
        int kp = idx2 >> 6, n = idx2 & 63;
        int r0 = 2 * kp, r1 = r0 + 1;
        float v0 = 0.f, v1 = 0.f;
        if (r0 < 256) v0 = W2[(size_t)r0 * 64 + n];
        else if (r0 - 256 < 420) v0 = Wres[(size_t)(r0 - 256) * 64 + n];
        if (r1 < 256) v1 = W2[(size_t)r1 * 64 + n];
        else if (r1 - 256 < 420) v1 = Wres[(size_t)(r1 - 256) * 64 + n];
        unsigned h, l; split_bf16x2(v0, v1, h, l);
        g_W2P[idx2] = make_uint2(h, l);
    }
}

// ============================================================================
// Kernel A: register-resident per-sample pipeline, FFMA2, 2 samples/warp.
// (exact R12 version — best measured kA; f32 output to g_f)
// ============================================================================
__global__ __launch_bounds__(256, 2) void kA(
    const float* __restrict__ x,
    const float* __restrict__ W_emb, const float* __restrict__ b_emb,
    const float* __restrict__ Wq, const float* __restrict__ bq,
    const float* __restrict__ Wk, const float* __restrict__ bk,
    const float* __restrict__ Wv, const float* __restrict__ bv,
    const float* __restrict__ Wo, const float* __restrict__ bo,
    const float* __restrict__ Wff1, const float* __restrict__ Wff2,
    const float* __restrict__ gnorm, const float* __restrict__ bnorm,
    const float* __restrict__ Wdy, const float* __restrict__ bdy,
    const float* __restrict__ channels)
{
    __shared__ __align__(16) float2 sWeP[336];
    __shared__ __align__(16) float  sbe[14];
    __shared__ __align__(16) float  sWq[112], sWk[112], sWv[112];
    __shared__ __align__(16) float  sbq[8], sbk[8], sbv[8];
    __shared__ __align__(16) float2 sWoP[64];
    __shared__ __align__(16) float  sbo[14];
    __shared__ __align__(16) float2 sF1P[400];
    __shared__ __align__(16) float2 sF2P[400];
    __shared__ __align__(16) float  sg[14], sb[14];
    __shared__ __align__(16) float  sWdy[900], sbdy[32];
    __shared__ __align__(16) float2 sAdjP[112];
    __shared__ __align__(16) float  scr[8][960];

    const int tid = threadIdx.x;
    for (int i = tid; i < 336; i += 256) {
        int ct = i >> 3, op = i & 7;
        float a = 0.f, b = 0.f;
        if (op < 7) { a = W_emb[(2*op)*42 + ct]; b = W_emb[(2*op+1)*42 + ct]; }
        sWeP[i] = make_float2(a, b);
    }
    for (int i = tid; i < 112; i += 256) { sWq[i]=Wq[i]; sWk[i]=Wk[i]; sWv[i]=Wv[i]; }
    for (int i = tid; i < 64; i += 256) {
        int h = i >> 3, dp = i & 7;
        float a = 0.f, b = 0.f;
        if (dp < 7) { a = Wo[h*14 + 2*dp]; b = Wo[h*14 + 2*dp + 1]; }
        sWoP[i] = make_float2(a, b);
    }
    for (int i = tid; i < 400; i += 256) {
        int f = i >> 3, dp = i & 7;
        float a1 = 0.f, b1v = 0.f, a2 = 0.f, b2v = 0.f;
        if (dp < 7) {
            a1 = Wff1[(2*dp)*50 + f]; b1v = Wff1[(2*dp+1)*50 + f];
            a2 = Wff2[f*14 + 2*dp];   b2v = Wff2[f*14 + 2*dp + 1];
        }
        sF1P[i] = make_float2(a1, b1v);
        sF2P[i] = make_float2(a2, b2v);
    }
    for (int i = tid; i < 900; i += 256) sWdy[i] = Wdy[i];
    if (tid < 30) sbdy[tid] = bdy[tid];
    if (tid < 14) { sbe[tid]=b_emb[tid]; sbo[tid]=bo[tid]; sg[tid]=gnorm[tid]; sb[tid]=bnorm[tid]; }
    if (tid < 8)  { sbq[tid]=bq[tid]; sbk[tid]=bk[tid]; sbv[tid]=bv[tid]; }
    if (tid < 14) {
        const float* row = channels + tid * 14;
        float mx = -1e30f;
        #pragma unroll
        for (int j = 0; j < 14; j++) mx = fmaxf(mx, row[j]);
        float s = 0.f;
        #pragma unroll
        for (int j = 0; j < 14; j++) s += expf(row[j] - mx);
        float inv = 1.f / s;
        #pragma unroll
        for (int j = 0; j < 7; j++)
            sAdjP[tid*8 + j] = make_float2(expf(row[2*j] - mx) * inv,
                                           expf(row[2*j+1] - mx) * inv);
        sAdjP[tid*8 + 7] = make_float2(0.f, 0.f);
    }
    __syncthreads();

    const int w    = tid >> 5;
    const int lane = tid & 31;
    const int t    = (lane < 30) ? lane : 0;
    const bool act = (lane < 30);
    const int smpA = blockIdx.x * 16 + w * 2;
    u64* scrU = reinterpret_cast<u64*>(scr[w]);

    {
        const float4* xpA = reinterpret_cast<const float4*>(x + (size_t)smpA * 420);
        const float4* xpB = reinterpret_cast<const float4*>(x + (size_t)(smpA+1) * 420);
        float4* sp = reinterpret_cast<float4*>(scr[w]);
        #pragma unroll
        for (int i = lane; i < 105; i += 32) { sp[i] = xpA[i]; sp[105 + i] = xpB[i]; }
    }
    __syncwarp();
    float xrA[14], xrB[14];
    #pragma unroll
    for (int d = 0; d < 14; d++) {
        xrA[d] = scr[w][t*14 + d];
        xrB[d] = scr[w][420 + t*14 + d];
    }
    __syncwarp();

    u64 xeA[7], xeB[7];
    {
        const u64* sbe2 = reinterpret_cast<const u64*>(sbe);
        #pragma unroll
        for (int op = 0; op < 7; op++) { xeA[op] = sbe2[op]; xeB[op] = sbe2[op]; }
        const u64* we = reinterpret_cast<const u64*>(sWeP);
        #pragma unroll
        for (int ci = 0; ci < 14; ci++) {
            float upA = __shfl_up_sync(FULL, xrA[ci], 1);
            float dnA = __shfl_down_sync(FULL, xrA[ci], 1);
            float upB = __shfl_up_sync(FULL, xrB[ci], 1);
            float dnB = __shfl_down_sync(FULL, xrB[ci], 1);
            float tapA[3] = { (lane > 0) ? upA : 0.f, xrA[ci], (lane < 29) ? dnA : 0.f };
            float tapB[3] = { (lane > 0) ? upB : 0.f, xrB[ci], (lane < 29) ? dnB : 0.f };
            #pragma unroll
            for (int tp = 0; tp < 3; tp++) {
                u64 xa = dup2(tapA[tp]), xb = dup2(tapB[tp]);
                const u64* wr = we + (ci*3 + tp) * 8;
                ulonglong2 w0 = lds2(wr), w1 = lds2(wr+2), w2 = lds2(wr+4);
                u64 w6 = wr[6];
                xeA[0] = fma2u(xa, w0.x, xeA[0]); xeB[0] = fma2u(xb, w0.x, xeB[0]);
                xeA[1] = fma2u(xa, w0.y, xeA[1]); xeB[1] = fma2u(xb, w0.y, xeB[1]);
                xeA[2] = fma2u(xa, w1.x, xeA[2]); xeB[2] = fma2u(xb, w1.x, xeB[2]);
                xeA[3] = fma2u(xa, w1.y, xeA[3]); xeB[3] = fma2u(xb, w1.y, xeB[3]);
                xeA[4] = fma2u(xa, w2.x, xeA[4]); xeB[4] = fma2u(xb, w2.x, xeB[4]);
                xeA[5] = fma2u(xa, w2.y, xeA[5]); xeB[5] = fma2u(xb, w2.y, xeB[5]);
                xeA[6] = fma2u(xa, w6,   xeA[6]); xeB[6] = fma2u(xb, w6,   xeB[6]);
            }
        }
    }

    u64 qA[4], kA_[4], vA[4], qB[4], kB_[4], vB[4];
    {
        const u64* bq2 = reinterpret_cast<const u64*>(sbq);
        const u64* bk2 = reinterpret_cast<const u64*>(sbk);
        const u64* bv2 = reinterpret_cast<const u64*>(sbv);
        #pragma unroll
        for (int hp = 0; hp < 4; hp++) {
            qA[hp]=bq2[hp]; kA_[hp]=bk2[hp]; vA[hp]=bv2[hp];
            qB[hp]=bq2[hp]; kB_[hp]=bk2[hp]; vB[hp]=bv2[hp];
        }
        const u64* wq2 = reinterpret_cast<const u64*>(sWq);
        const u64* wk2 = reinterpret_cast<const u64*>(sWk);
        const u64* wv2 = reinterpret_cast<const u64*>(sWv);
        #pragma unroll
        for (int dp = 0; dp < 7; dp++) {
            float ax, ay, bx, by;
            unpack2(xeA[dp], ax, ay);
            unpack2(xeB[dp], bx, by);
            float sA[2] = { ax, ay }, sB[2] = { bx, by };
            #pragma unroll
            for (int half = 0; half < 2; half++) {
                int d = 2*dp + half;
                u64 xa = dup2(sA[half]), xb = dup2(sB[half]);
                ulonglong2 qa = lds2(wq2 + d*4), qb = lds2(wq2 + d*4 + 2);
                ulonglong2 ka = lds2(wk2 + d*4), kb = lds2(wk2 + d*4 + 2);
                ulonglong2 va = lds2(wv2 + d*4), vb = lds2(wv2 + d*4 + 2);
                qA[0] = fma2u(xa, qa.x, qA[0]); qB[0] = fma2u(xb, qa.x, qB[0]);
                qA[1] = fma2u(xa, qa.y, qA[1]); qB[1] = fma2u(xb, qa.y, qB[1]);
                qA[2] = fma2u(xa, qb.x, qA[2]); qB[2] = fma2u(xb, qb.x, qB[2]);
                qA[3] = fma2u(xa, qb.y, qA[3]); qB[3] = fma2u(xb, qb.y, qB[3]);
                kA_[0] = fma2u(xa, ka.x, kA_[0]); kB_[0] = fma2u(xb, ka.x, kB_[0]);
                kA_[1] = fma2u(xa, ka.y, kA_[1]); kB_[1] = fma2u(xb, ka.y, kB_[1]);
                kA_[2] = fma2u(xa, kb.x, kA_[2]); kB_[2] = fma2u(xb, kb.x, kB_[2]);
                kA_[3] = fma2u(xa, kb.y, kA_[3]); kB_[3] = fma2u(xb, kb.y, kB_[3]);
                vA[0] = fma2u(xa, va.x, vA[0]); vB[0] = fma2u(xb, va.x, vB[0]);
                vA[1] = fma2u(xa, va.y, vA[1]); vB[1] = fma2u(xb, va.y, vB[1]);
                vA[2] = fma2u(xa, vb.x, vA[2]); vB[2] = fma2u(xb, vb.x, vB[2]);
                vA[3] = fma2u(xa, vb.y, vA[3]); vB[3] = fma2u(xb, vb.y, vB[3]);
            }
        }
    }

    u64* qsA = scrU;
    u64* ksA = scrU + 120;
    u64* qsB = scrU + 240;
    u64* ksB = scrU + 360;
    if (act) {
        *reinterpret_cast<ulonglong2*>(qsA + t*4)     = make_ulonglong2(qA[0], qA[1]);
        *reinterpret_cast<ulonglong2*>(qsA + t*4 + 2) = make_ulonglong2(qA[2], qA[3]);
        *reinterpret_cast<ulonglong2*>(ksA + t*4)     = make_ulonglong2(kA_[0], kA_[1]);
        *reinterpret_cast<ulonglong2*>(ksA + t*4 + 2) = make_ulonglong2(kA_[2], kA_[3]);
        *reinterpret_cast<ulonglong2*>(qsB + t*4)     = make_ulonglong2(qB[0], qB[1]);
        *reinterpret_cast<ulonglong2*>(qsB + t*4 + 2) = make_ulonglong2(qB[2], qB[3]);
        *reinterpret_cast<ulonglong2*>(ksB + t*4)     = make_ulonglong2(kB_[0], kB_[1]);
        *reinterpret_cast<ulonglong2*>(ksB + t*4 + 2) = make_ulonglong2(kB_[2], kB_[3]);
    }
    __syncwarp();

    float mvA = corr30(qsA, ksA, t, act);
    float mvB = corr30(qsB, ksB, t, act);
    float w0A, w1A, w2A, w0B, w1B, w2B;
    int dl0A, dl1A, dl2A, dl0B, dl1B, dl2B;
    top3softmax(mvA, lane, w0A, w1A, w2A, dl0A, dl1A, dl2A);
    top3softmax(mvB, lane, w0B, w1B, w2B, dl0B, dl1B, dl2B);

    u64 aggA[4], aggB[4];
    {
        int s0 = t + dl0A; if (s0 >= 30) s0 -= 30;
        int s1 = t + dl1A; if (s1 >= 30) s1 -= 30;
        int s2 = t + dl2A; if (s2 >= 30) s2 -= 30;
        u64 c0 = dup2(w0A), c1 = dup2(w1A), c2 = dup2(w2A);
        #pragma unroll
        for (int hp = 0; hp < 4; hp++) {
            u64 y0 = __shfl_sync(FULL, vA[hp], s0);
            u64 y1 = __shfl_sync(FULL, vA[hp], s1);
            u64 y2 = __shfl_sync(FULL, vA[hp], s2);
            aggA[hp] = fma2u(c0, y0, fma2u(c1, y1, fma2u(c2, y2, 0ULL)));
        }
    }
    {
        int s0 = t + dl0B; if (s0 >= 30) s0 -= 30;
        int s1 = t + dl1B; if (s1 >= 30) s1 -= 30;
        int s2 = t + dl2B; if (s2 >= 30) s2 -= 30;
        u64 c0 = dup2(w0B), c1 = dup2(w1B), c2 = dup2(w2B);
        #pragma unroll
        for (int hp = 0; hp < 4; hp++) {
            u64 y0 = __shfl_sync(FULL, vB[hp], s0);
            u64 y1 = __shfl_sync(FULL, vB[hp], s1);
            u64 y2 = __shfl_sync(FULL, vB[hp], s2);
            aggB[hp] = fma2u(c0, y0, fma2u(c1, y1, fma2u(c2, y2, 0ULL)));
        }
    }

    u64 x1A[7], x1B[7];
    {
        const u64* sbo2 = reinterpret_cast<const u64*>(sbo);
        #pragma unroll
        for (int dp = 0; dp < 7; dp++) {
            x1A[dp] = add2u(xeA[dp], sbo2[dp]);
            x1B[dp] = add2u(xeB[dp], sbo2[dp]);
        }
        const u64* wo = reinterpret_cast<const u64*>(sWoP);
        #pragma unroll
        for (int hp = 0; hp < 4; hp++) {
            float aAx, aAy, aBx, aBy;
            unpack2(aggA[hp], aAx, aAy);
            unpack2(aggB[hp], aBx, aBy);
            float sA[2] = { aAx, aAy }, sB[2] = { aBx, aBy };
            #pragma unroll
            for (int half = 0; half < 2; half++) {
                int h = 2*hp + half;
                u64 aa = dup2(sA[half]), ab = dup2(sB[half]);
                const u64* wr = wo + h*8;
                ulonglong2 w0v = lds2(wr), w1v = lds2(wr+2), w2v = lds2(wr+4);
                u64 w6 = wr[6];
                x1A[0] = fma2u(aa, w0v.x, x1A[0]); x1B[0] = fma2u(ab, w0v.x, x1B[0]);
                x1A[1] = fma2u(aa, w0v.y, x1A[1]); x1B[1] = fma2u(ab, w0v.y, x1B[1]);
                x1A[2] = fma2u(aa, w1v.x, x1A[2]); x1B[2] = fma2u(ab, w1v.x, x1B[2]);
                x1A[3] = fma2u(aa, w1v.y, x1A[3]); x1B[3] = fma2u(ab, w1v.y, x1B[3]);
                x1A[4] = fma2u(aa, w2v.x, x1A[4]); x1B[4] = fma2u(ab, w2v.x, x1B[4]);
                x1A[5] = fma2u(aa, w2v.y, x1A[5]); x1B[5] = fma2u(ab, w2v.y, x1B[5]);
                x1A[6] = fma2u(aa, w6,    x1A[6]); x1B[6] = fma2u(ab, w6,    x1B[6]);
            }
        }
    }

    const float fc0  = (t < 12) ? (float)(12 - t) : 0.f;
    const float fc29 = (t > 17) ? (float)(t - 17) : 0.f;
    const int hi   = (t + 12 > 29) ? 29 : t + 12;
    const int lom1 = t - 13;
    const int loix = (lom1 < 0) ? 0 : lom1;
    u64 xdA[7], xdB[7];
    #pragma unroll
    for (int dp = 0; dp < 7; dp++) {
        float vx, vy;
        unpack2(x1A[dp], vx, vy);
        xdA[dp] = pack2(decomp25(vx, lane, hi, loix, lom1, fc0, fc29),
                        decomp25(vy, lane, hi, loix, lom1, fc0, fc29));
        unpack2(x1B[dp], vx, vy);
        xdB[dp] = pack2(decomp25(vx, lane, hi, loix, lom1, fc0, fc29),
                        decomp25(vy, lane, hi, loix, lom1, fc0, fc29));
    }

    u64 x2A[7], x2B[7];
    {
        u64 yA[7] = {}, yB[7] = {};
        const u64* f1 = reinterpret_cast<const u64*>(sF1P);
        const u64* f2 = reinterpret_cast<const u64*>(sF2P);
        #pragma unroll 5
        for (int f = 0; f < 50; f++) {
            const u64* r1 = f1 + f*8;
            ulonglong2 a0 = lds2(r1), a1 = lds2(r1+2), a2l = lds2(r1+4);
            u64 a6 = r1[6];
            u64 hA = fma2u(xdA[0], a0.x, 0ULL);
            u64 hB = fma2u(xdB[0], a0.x, 0ULL);
            hA = fma2u(xdA[1], a0.y, hA);   hB = fma2u(xdB[1], a0.y, hB);
            hA = fma2u(xdA[2], a1.x, hA);   hB = fma2u(xdB[2], a1.x, hB);
            hA = fma2u(xdA[3], a1.y, hA);   hB = fma2u(xdB[3], a1.y, hB);
            hA = fma2u(xdA[4], a2l.x, hA);  hB = fma2u(xdB[4], a2l.x, hB);
            hA = fma2u(xdA[5], a2l.y, hA);  hB = fma2u(xdB[5], a2l.y, hB);
            hA = fma2u(xdA[6], a6, hA);     hB = fma2u(xdB[6], a6, hB);
            float hx, hy;
            unpack2(hA, hx, hy);
            float hsA = hx + hy;
            unpack2(hB, hx, hy);
            float hsB = hx + hy;
            float gAv = 0.5f * hsA * (1.f + erff(hsA * 0.70710678118654752f));
            float gBv = 0.5f * hsB * (1.f + erff(hsB * 0.70710678118654752f));
            u64 gA2 = dup2(gAv), gB2 = dup2(gBv);
            const u64* r2 = f2 + f*8;
            ulonglong2 b0 = lds2(r2), b1v = lds2(r2+2), b2v = lds2(r2+4);
            u64 b6 = r2[6];
            yA[0] = fma2u(gA2, b0.x, yA[0]);  yB[0] = fma2u(gB2, b0.x, yB[0]);
            yA[1] = fma2u(gA2, b0.y, yA[1]);  yB[1] = fma2u(gB2, b0.y, yB[1]);
            yA[2] = fma2u(gA2, b1v.x, yA[2]); yB[2] = fma2u(gB2, b1v.x, yB[2]);
            yA[3] = fma2u(gA2, b1v.y, yA[3]); yB[3] = fma2u(gB2, b1v.y, yB[3]);
            yA[4] = fma2u(gA2, b2v.x, yA[4]); yB[4] = fma2u(gB2, b2v.x, yB[4]);
            yA[5] = fma2u(gA2, b2v.y, yA[5]); yB[5] = fma2u(gB2, b2v.y, yB[5]);
            yA[6] = fma2u(gA2, b6, yA[6]);    yB[6] = fma2u(gB2, b6, yB[6]);
        }
        #pragma unroll
        for (int dp = 0; dp < 7; dp++) {
            x2A[dp] = add2u(xdA[dp], yA[dp]);
            x2B[dp] = add2u(xdB[dp], yB[dp]);
        }
    }

    float x3Ax[7], x3Ay[7], x3Bx[7], x3By[7];
    #pragma unroll
    for (int dp = 0; dp < 7; dp++) {
        float vx, vy;
        unpack2(x2A[dp], vx, vy);
        x3Ax[dp] = decomp25(vx, lane, hi, loix, lom1, fc0, fc29);
        x3Ay[dp] = decomp25(vy, lane, hi, loix, lom1, fc0, fc29);
        unpack2(x2B[dp], vx, vy);
        x3Bx[dp] = decomp25(vx, lane, hi, loix, lom1, fc0, fc29);
        x3By[dp] = decomp25(vy, lane, hi, loix, lom1, fc0, fc29);
    }
    {
        float mA = 0.f, mB = 0.f;
        #pragma unroll
        for (int dp = 0; dp < 7; dp++) { mA += x3Ax[dp] + x3Ay[dp]; mB += x3Bx[dp] + x3By[dp]; }
        mA *= (1.f / 14.f); mB *= (1.f / 14.f);
        float vA_ = 0.f, vB_ = 0.f;
        #pragma unroll
        for (int dp = 0; dp < 7; dp++) {
            float dx = x3Ax[dp] - mA, dy = x3Ay[dp] - mA;
            vA_ += dx * dx + dy * dy;
            dx = x3Bx[dp] - mB; dy = x3By[dp] - mB;
            vB_ += dx * dx + dy * dy;
        }
        vA_ *= (1.f / 14.f); vB_ *= (1.f / 14.f);
        float iA = rsqrtf(vA_ + 1e-5f), iB = rsqrtf(vB_ + 1e-5f);
        #pragma unroll
        for (int dp = 0; dp < 7; dp++) {
            float g0 = sg[2*dp], g1 = sg[2*dp+1], b0 = sb[2*dp], b1v = sb[2*dp+1];
            x3Ax[dp] = (x3Ax[dp] - mA) * iA * g0 + b0;
            x3Ay[dp] = (x3Ay[dp] - mA) * iA * g1 + b1v;
            x3Bx[dp] = (x3Bx[dp] - mB) * iB * g0 + b0;
            x3By[dp] = (x3By[dp] - mB) * iB * g1 + b1v;
        }
    }

    __syncwarp();
    u64* x3sA = scrU;
    u64* x3sB = scrU + 240;
    if (act) {
        *reinterpret_cast<ulonglong2*>(x3sA + t*8)     = make_ulonglong2(pack2(x3Ax[0], x3Ay[0]), pack2(x3Ax[1], x3Ay[1]));
        *reinterpret_cast<ulonglong2*>(x3sA + t*8 + 2) = make_ulonglong2(pack2(x3Ax[2], x3Ay[2]), pack2(x3Ax[3], x3Ay[3]));
        *reinterpret_cast<ulonglong2*>(x3sA + t*8 + 4) = make_ulonglong2(pack2(x3Ax[4], x3Ay[4]), pack2(x3Ax[5], x3Ay[5]));
        x3sA[t*8 + 6] = pack2(x3Ax[6], x3Ay[6]);
        *reinterpret_cast<ulonglong2*>(x3sB + t*8)     = make_ulonglong2(pack2(x3Bx[0], x3By[0]), pack2(x3Bx[1], x3By[1]));
        *reinterpret_cast<ulonglong2*>(x3sB + t*8 + 2) = make_ulonglong2(pack2(x3Bx[2], x3By[2]), pack2(x3Bx[3], x3By[3]));
        *reinterpret_cast<ulonglong2*>(x3sB + t*8 + 4) = make_ulonglong2(pack2(x3Bx[4], x3By[4]), pack2(x3Bx[5], x3By[5]));
        x3sB[t*8 + 6] = pack2(x3Bx[6], x3By[6]);
    }
    __syncwarp();
    u64 accA[7], accB[7];
    {
        u64 bias2 = dup2(sbdy[t]);
        #pragma unroll
        for (int dp = 0; dp < 7; dp++) { accA[dp] = bias2; accB[dp] = bias2; }
        #pragma unroll
        for (int m = 0; m < 30; m++) {
            u64 wm2 = dup2(sWdy[m*30 + t]);
            const u64* xa = x3sA + m*8;
            const u64* xb = x3sB + m*8;
            ulonglong2 a0 = lds2(xa), a1 = lds2(xa+2), a2l = lds2(xa+4);
            u64 a6 = xa[6];
            ulonglong2 b0 = lds2(xb), b1v = lds2(xb+2), b2v = lds2(xb+4);
            u64 b6 = xb[6];
            accA[0] = fma2u(a0.x, wm2, accA[0]);  accB[0] = fma2u(b0.x, wm2, accB[0]);
            accA[1] = fma2u(a0.y, wm2, accA[1]);  accB[1] = fma2u(b0.y, wm2, accB[1]);
            accA[2] = fma2u(a1.x, wm2, accA[2]);  accB[2] = fma2u(b1v.x, wm2, accB[2]);
            accA[3] = fma2u(a1.y, wm2, accA[3]);  accB[3] = fma2u(b1v.y, wm2, accB[3]);
            accA[4] = fma2u(a2l.x, wm2, accA[4]); accB[4] = fma2u(b2v.x, wm2, accB[4]);
            accA[5] = fma2u(a2l.y, wm2, accA[5]); accB[5] = fma2u(b2v.y, wm2, accB[5]);
            accA[6] = fma2u(a6,   wm2, accA[6]);  accB[6] = fma2u(b6,   wm2, accB[6]);
        }
    }

    {
        float* foA = g_f + (size_t)smpA * 420;
        float* foB = g_f + (size_t)(smpA+1) * 420;
        const u64* adj = reinterpret_cast<const u64*>(sAdjP);
        #pragma unroll
        for (int i = 0; i < 14; i++) {
            const u64* ar = adj + i*8;
            ulonglong2 a0 = lds2(ar), a1 = lds2(ar+2), a2l = lds2(ar+4);
            u64 a6 = ar[6];
            u64 sA2 = fma2u(a0.x, accA[0], 0ULL);
            u64 sB2 = fma2u(a0.x, accB[0], 0ULL);
            sA2 = fma2u(a0.y, accA[1], sA2);  sB2 = fma2u(a0.y, accB[1], sB2);
            sA2 = fma2u(a1.x, accA[2], sA2);  sB2 = fma2u(a1.x, accB[2], sB2);
            sA2 = fma2u(a1.y, accA[3], sA2);  sB2 = fma2u(a1.y, accB[3], sB2);
            sA2 = fma2u(a2l.x, accA[4], sA2); sB2 = fma2u(a2l.x, accB[4], sB2);
            sA2 = fma2u(a2l.y, accA[5], sA2); sB2 = fma2u(a2l.y, accB[5], sB2);
            sA2 = fma2u(a6, accA[6], sA2);    sB2 = fma2u(a6, accB[6], sB2);
            float ax, ay;
            unpack2(sA2, ax, ay);
            if (act) foA[i*30 + t] = fmaxf(ax + ay, 0.f);
            unpack2(sB2, ax, ay);
            if (act) foB[i*30 + t] = fmaxf(ax + ay, 0.f);
        }
    }
}

// ============================================================================
// Kernel B (3xBF16 m16n8k16): hh = relu(f @ W1 + b1)
// A split at staging from g_f (f32); B copied pre-split from g_W1P.
// Epilogue emits hh pre-split into g_hhP.
// ============================================================================
__global__ __launch_bounds__(256) void kB(const float* __restrict__ b1)
{
    __shared__ __align__(16) uint2 Ahl[128][20];   // [m][kp] (16 used)
    __shared__ __align__(16) uint2 Bhl[64][20];    // [n][kp]
    const int tid = threadIdx.x;
    const int lane = tid & 31, wid = tid >> 5;
    const int wm = wid >> 1, wn = wid & 1;
    const int c4 = lane & 3;
    const size_t mbase = (size_t)blockIdx.x * 128;
    const int nbase = blockIdx.y * 64;
    float c[2][4][4] = {};

    for (int k0 = 0; k0 < 448; k0 += 32) {
        // A stage: split from g_f (zero-pad past 420)
        {
            int m = tid >> 1, half = tid & 1;
            const float4* gr = reinterpret_cast<const float4*>(g_f + (mbase + m) * 420);
            #pragma unroll
            for (int j = 0; j < 4; j++) {
                int kq = (k0 >> 2) + half*4 + j;
                float4 vv = (kq < 105) ? gr[kq] : make_float4(0.f,0.f,0.f,0.f);
                int kp = half*8 + 2*j;
                unsigned h, l;
                split_bf16x2(vv.x, vv.y, h, l); Ahl[m][kp]   = make_uint2(h, l);
                split_bf16x2(vv.z, vv.w, h, l); Ahl[m][kp+1] = make_uint2(h, l);
            }
        }
        // B stage: pure copy from g_W1P
        {
            int kp = tid >> 4;
            int n4 = (tid & 15) * 4;
            const uint2* wp = g_W1P + (size_t)((k0 >> 1) + kp) * 256 + nbase + n4;
            uint4 v01 = *reinterpret_cast<const uint4*>(wp);
            uint4 v23 = *reinterpret_cast<const uint4*>(wp + 2);
            Bhl[n4+0][kp] = make_uint2(v01.x, v01.y);
            Bhl[n4+1][kp] = make_uint2(v01.z, v01.w);
            Bhl[n4+2][kp] = make_uint2(v23.x, v23.y);
            Bhl[n4+3][kp] = make_uint2(v23.z, v23.w);
        }
        __syncthreads();
        #pragma unroll
        for (int ks = 0; ks < 2; ks++) {
            int kb = ks * 8;
            unsigned ah[2][4], al[2][4], bh[4][2], bl[4][2];
            #pragma unroll
            for (int mt = 0; mt < 2; mt++) {
                int r = wm*32 + mt*16 + (lane>>2);
                uint2 e;
                e = Ahl[r  ][kb + c4];     ah[mt][0] = e.x; al[mt][0] = e.y;
                e = Ahl[r+8][kb + c4];     ah[mt][1] = e.x; al[mt][1] = e.y;
                e = Ahl[r  ][kb + c4 + 4]; ah[mt][2] = e.x; al[mt][2] = e.y;
                e = Ahl[r+8][kb + c4 + 4]; ah[mt][3] = e.x; al[mt][3] = e.y;
            }
            #pragma unroll
            for (int nt = 0; nt < 4; nt++) {
                int nn = wn*32 + nt*8 + (lane>>2);
                uint2 e;
                e = Bhl[nn][kb + c4];     bh[nt][0] = e.x; bl[nt][0] = e.y;
                e = Bhl[nn][kb + c4 + 4]; bh[nt][1] = e.x; bl[nt][1] = e.y;
            }
            #pragma unroll
            for (int mt = 0; mt < 2; mt++)
                #pragma unroll
                for (int nt = 0; nt < 4; nt++) {
                    mma_bf16(c[mt][nt], ah[mt], bh[nt]);
                    mma_bf16(c[mt][nt], ah[mt], bl[nt]);
                    mma_bf16(c[mt][nt], al[mt], bh[nt]);
                }
        }
        __syncthreads();
    }
    // epilogue: relu(+b1), pre-split into g_hhP
    #pragma unroll
    for (int mt = 0; mt < 2; mt++) {
        int r0 = wm*32 + mt*16 + (lane>>2);
        #pragma unroll
        for (int nt = 0; nt < 4; nt++) {
            int cl = nbase + wn*32 + nt*8 + 2*(lane&3);
            float b0 = b1[cl], b1v = b1[cl+1];
            float v0 = fmaxf(c[mt][nt][0] + b0, 0.f);
            float v1 = fmaxf(c[mt][nt][1] + b1v, 0.f);
            float v2 = fmaxf(c[mt][nt][2] + b0, 0.f);
            float v3 = fmaxf(c[mt][nt][3] + b1v, 0.f);
            unsigned h, l;
            split_bf16x2(v0, v1, h, l);
            g_hhP[(mbase + r0) * 128 + (cl >> 1)] = make_uint2(h, l);
            split_bf16x2(v2, v3, h, l);
            g_hhP[(mbase + r0 + 8) * 128 + (cl >> 1)] = make_uint2(h, l);
        }
    }
}

// ============================================================================
// Kernel C (3xBF16, fused LN head): hr = [hh|f]@[W2;Wres]+b2+bres,
// out = LN64(hr)@W3+b3. A-tile: copy g_hhP / split g_f; B: copy g_W2P.
// ============================================================================
__global__ __launch_bounds__(256) void kC(const float* __restrict__ b2,
                                          const float* __restrict__ bres,
                                          const float* __restrict__ g_ln,
                                          const float* __restrict__ b_ln,
                                          const float* __restrict__ W3,
                                          const float* __restrict__ b3,
                                          float* __restrict__ out)
{
    __shared__ __align__(16) uint2 Ahl[128][20];
    __shared__ __align__(16) uint2 Bhl[64][20];
    __shared__ float sbb[64];
    __shared__ float sgw[64];
    __shared__ float sp[128][2][3];
    __shared__ float sconst[2];
    const int tid = threadIdx.x;
    const int lane = tid & 31, wid = tid >> 5;
    const int wm = wid >> 1, wn = wid & 1;
    const int c4 = lane & 3;
    const size_t mbase = (size_t)blockIdx.x * 128;
    float c[2][4][4] = {};

    if (tid < 64) {
        sbb[tid] = b2[tid] + bres[tid];
        sgw[tid] = g_ln[tid] * W3[tid];
    }

    for (int k0 = 0; k0 < 704; k0 += 32) {
        // A stage: [g_hhP pre-split (kp<128) | split from g_f (kp 128..337)]
        {
            int m = tid >> 1, half = tid & 1;
            const uint2* hrow = g_hhP + (size_t)(mbase + m) * 128;
            const float* frow = g_f + (size_t)(mbase + m) * 420;
            int kpg0 = (k0 >> 1) + half * 8;
            #pragma unroll
            for (int j = 0; j < 8; j += 2) {
                int kpg = kpg0 + j;          // even; uint4 covers kp kpg, kpg+1
                if (kpg < 128) {
                    *reinterpret_cast<uint4*>(&Ahl[m][half*8 + j]) =
                        *reinterpret_cast<const uint4*>(hrow + kpg);
                } else {
                    float4 vv = make_float4(0.f,0.f,0.f,0.f);
                    if (kpg < 338)
                        vv = *reinterpret_cast<const float4*>(frow + (kpg - 128) * 2);
                    unsigned h, l;
                    split_bf16x2(vv.x, vv.y, h, l); Ahl[m][half*8 + j]     = make_uint2(h, l);
                    split_bf16x2(vv.z, vv.w, h, l); Ahl[m][half*8 + j + 1] = make_uint2(h, l);
                }
            }
        }
        // B stage: copy from g_W2P
        {
            int kp = tid >> 4;
            int n4 = (tid & 15) * 4;
            const uint2* wp = g_W2P + (size_t)((k0 >> 1) + kp) * 64 + n4;
            uint4 v01 = *reinterpret_cast<const uint4*>(wp);
            uint4 v23 = *reinterpret_cast<const uint4*>(wp + 2);
            Bhl[n4+0][kp] = make_uint2(v01.x, v01.y);
            Bhl[n4+1][kp] = make_uint2(v01.z, v01.w);
            Bhl[n4+2][kp] = make_uint2(v23.x, v23.y);
            Bhl[n4+3][kp] = make_uint2(v23.z, v23.w);
        }
        __syncthreads();
        #pragma unroll
        for (int ks = 0; ks < 2; ks++) {
            int kb = ks * 8;
            unsigned ah[2][4], al[2][4], bh[4][2], bl[4][2];
            #pragma unroll
            for (int mt = 0; mt < 2; mt++) {
                int r = wm*32 + mt*16 + (lane>>2);
                uint2 e;
                e = Ahl[r  ][kb + c4];     ah[mt][0] = e.x; al[mt][0] = e.y;
                e = Ahl[r+8][kb + c4];     ah[mt][1] = e.x; al[mt][1] = e.y;
                e = Ahl[r  ][kb + c4 + 4]; ah[mt][2] = e.x; al[mt][2] = e.y;
                e = Ahl[r+8][kb + c4 + 4]; ah[mt][3] = e.x; al[mt][3] = e.y;
            }
            #pragma unroll
            for (int nt = 0; nt < 4; nt++) {
                int nn = wn*32 + nt*8 + (lane>>2);
                uint2 e;
                e = Bhl[nn][kb + c4];     bh[nt][0] = e.x; bl[nt][0] = e.y;
                e = Bhl[nn][kb + c4 + 4]; bh[nt][1] = e.x; bl[nt][1] = e.y;
            }
            #pragma unroll
            for (int mt = 0; mt < 2; mt++)
                #pragma unroll
                for (int nt = 0; nt < 4; nt++) {
                    mma_bf16(c[mt][nt], ah[mt], bh[nt]);
                    mma_bf16(c[mt][nt], ah[mt], bl[nt]);
                    mma_bf16(c[mt][nt], al[mt], bh[nt]);
                }
        }
        __syncthreads();
    }

    // ---- fused epilogue: partial LN sums per (row, wn-half) ----
    #pragma unroll
    for (int mt = 0; mt < 2; mt++) {
        #pragma unroll
        for (int rb = 0; rb < 2; rb++) {
            float sv = 0.f, sq = 0.f, sgd = 0.f;
            #pragma unroll
            for (int nt = 0; nt < 4; nt++) {
                int cl = wn*32 + nt*8 + 2*(lane&3);
                float v0 = c[mt][nt][2*rb]     + sbb[cl];
                float v1 = c[mt][nt][2*rb + 1] + sbb[cl+1];
                sv += v0 + v1;
                sq += v0*v0 + v1*v1;
                sgd += v0*sgw[cl] + v1*sgw[cl+1];
            }
            sv += __shfl_xor_sync(FULL, sv, 1);
            sq += __shfl_xor_sync(FULL, sq, 1);
            sgd += __shfl_xor_sync(FULL, sgd, 1);
            sv += __shfl_xor_sync(FULL, sv, 2);
            sq += __shfl_xor_sync(FULL, sq, 2);
            sgd += __shfl_xor_sync(FULL, sgd, 2);
            if ((lane & 3) == 0) {
                int row = wm*32 + mt*16 + rb*8 + (lane>>2);
                sp[row][wn][0] = sv;
                sp[row][wn][1] = sq;
                sp[row][wn][2] = sgd;
            }
        }
    }
    if (tid == 0) {
        float G = 0.f, cb = b3[0];
        for (int d = 0; d < 64; d++) { G += sgw[d]; cb += b_ln[d] * W3[d]; }
        sconst[0] = G; sconst[1] = cb;
    }
    __syncthreads();
    if (tid < 128) {
        int row = tid;
        float sv  = sp[row][0][0] + sp[row][1][0];
        float sq  = sp[row][0][1] + sp[row][1][1];
        float sgd = sp[row][0][2] + sp[row][1][2];
        float m = sv * (1.f / 64.f);
        float var = sq * (1.f / 64.f) - m * m;
        float invs = rsqrtf(var + 1e-5f);
        out[mbase + row] = invs * (sgd - m * sconst[0]) + sconst[1];
    }
}

// ============================================================================
extern "C" void kernel_launch(void* const* d_in, const int* in_sizes, int n_in,
                              void* d_out, int out_size)
{
    (void)in_sizes; (void)n_in; (void)out_size;
    const float* x = (const float*)d_in[0];

    kW<<<312, 256>>>((const float*)d_in[18], (const float*)d_in[20],
                     (const float*)d_in[22]);

    kA<<<BATCH / 16, 256>>>(x,
        (const float*)d_in[1],  (const float*)d_in[2],
        (const float*)d_in[3],  (const float*)d_in[4],
        (const float*)d_in[5],  (const float*)d_in[6],
        (const float*)d_in[7],  (const float*)d_in[8],
        (const float*)d_in[9],  (const float*)d_in[10],
        (const float*)d_in[11], (const float*)d_in[12],
        (const float*)d_in[13], (const float*)d_in[14],
        (const float*)d_in[15], (const float*)d_in[16],
        (const float*)d_in[17]);

    kB<<<dim3(BATCH / 128, 4), 256>>>((const float*)d_in[19]);

    kC<<<BATCH / 128, 256>>>((const float*)d_in[21], (const float*)d_in[23],
                             (const float*)d_in[24], (const float*)d_in[25],
                             (const float*)d_in[26], (const float*)d_in[27],
                             (float*)d_out);
}

// round 15
// speedup vs baseline: 1.1142x; 1.1083x over previous
#include <cuda_runtime.h>
#include <math.h>

#define BATCH 65536
#define FULL 0xffffffffu

typedef unsigned long long u64;

// -------- device scratch (allocation-free rule: __device__ globals) --------
__device__ float g_f [(size_t)BATCH * 420];   // DyConv output
__device__ float g_hh[(size_t)BATCH * 256];   // relu(f@W1+b1)

// ---------------- packed f32x2 ops on b64 registers ----------------
__device__ __forceinline__ u64 pack2(float x, float y) {
    u64 r; asm("mov.b64 %0, {%1, %2};" : "=l"(r) : "f"(x), "f"(y)); return r;
}
__device__ __forceinline__ u64 dup2(float s) { return pack2(s, s); }
__device__ __forceinline__ void unpack2(u64 v, float& x, float& y) {
    asm("mov.b64 {%0, %1}, %2;" : "=f"(x), "=f"(y) : "l"(v));
}
__device__ __forceinline__ u64 fma2u(u64 a, u64 b, u64 c) {
    u64 d; asm("fma.rn.f32x2 %0, %1, %2, %3;" : "=l"(d) : "l"(a), "l"(b), "l"(c)); return d;
}
__device__ __forceinline__ u64 add2u(u64 a, u64 b) {
    u64 d; asm("add.rn.f32x2 %0, %1, %2;" : "=l"(d) : "l"(a), "l"(b)); return d;
}
__device__ __forceinline__ ulonglong2 lds2(const u64* p) {
    return *reinterpret_cast<const ulonglong2*>(p);
}

// ---------------- split-bf16 helpers (3xBF16 compensated GEMM) -------------
// e0 -> low half, e1 -> high half (matches mma bf16x2 k-pair layout)
__device__ __forceinline__ void split_bf16x2(float e0, float e1,
                                             unsigned& hi, unsigned& lo) {
    asm("cvt.rn.bf16x2.f32 %0, %1, %2;" : "=r"(hi) : "f"(e1), "f"(e0));
    float h0 = __uint_as_float(hi << 16);
    float h1 = __uint_as_float(hi & 0xffff0000u);
    float r0 = e0 - h0, r1 = e1 - h1;
    asm("cvt.rn.bf16x2.f32 %0, %1, %2;" : "=r"(lo) : "f"(r1), "f"(r0));
}
__device__ __forceinline__ void mma_bf16(float* c, const unsigned* a, const unsigned* b) {
    asm volatile(
        "mma.sync.aligned.m16n8k16.row.col.f32.bf16.bf16.f32 "
        "{%0,%1,%2,%3},{%4,%5,%6,%7},{%8,%9},{%0,%1,%2,%3};"
        : "+f"(c[0]), "+f"(c[1]), "+f"(c[2]), "+f"(c[3])
        : "r"(a[0]), "r"(a[1]), "r"(a[2]), "r"(a[3]), "r"(b[0]), "r"(b[1]));
}

// ---- shuffle-scan series_decomp helper (replicate-pad MA-25) ----
__device__ __forceinline__ float decomp25(float val, int lane, int hi, int loix,
                                          int lom1, float fc0, float fc29) {
    float cs = val;
    #pragma unroll
    for (int off = 1; off < 32; off <<= 1) {
        float o = __shfl_up_sync(FULL, cs, off);
        if (lane >= off) cs += o;
    }
    float cshi = __shfl_sync(FULL, cs, hi);
    float cslo = __shfl_sync(FULL, cs, loix);
    float ssum = cshi - ((lom1 >= 0) ? cslo : 0.f);
    float x0  = __shfl_sync(FULL, val, 0);
    float x29 = __shfl_sync(FULL, val, 29);
    return val - (ssum + fc0 * x0 + fc29 * x29) * (1.f / 25.f);
}

// ---- warp-parallel top-3 with first-index tie-break, then softmax ----
__device__ __forceinline__ void top3softmax(float mv, int lane,
                                            float& w0, float& w1, float& w2,
                                            int& dl0, int& dl1, int& dl2) {
    float wv0, wv1, wv2;
    float mrun = mv;
    #pragma unroll
    for (int p = 0; p < 3; p++) {
        float bv = mrun; int bi = lane;
        #pragma unroll
        for (int off = 16; off; off >>= 1) {
            float vo = __shfl_xor_sync(FULL, bv, off);
            int   io = __shfl_xor_sync(FULL, bi, off);
            if (vo > bv || (vo == bv && io < bi)) { bv = vo; bi = io; }
        }
        if (p == 0) { wv0 = bv; dl0 = bi; }
        else if (p == 1) { wv1 = bv; dl1 = bi; }
        else { wv2 = bv; dl2 = bi; }
        if (lane == bi) mrun = -1e30f;
    }
    float e1 = expf(wv1 - wv0);
    float e2 = expf(wv2 - wv0);
    float inv = 1.f / (1.f + e1 + e2);
    w0 = inv; w1 = e1 * inv; w2 = e2 * inv;
}

// ---- circular correlation for one sample (lane = tau) ----
__device__ __forceinline__ float corr30(const u64* qsU, const u64* ksU,
                                        int t, bool act) {
    u64 acc2[4] = {};
    #pragma unroll
    for (int tq = 0; tq < 30; tq++) {
        int src = tq - t; if (src < 0) src += 30;
        ulonglong2 qa = lds2(qsU + tq*4), qb = lds2(qsU + tq*4 + 2);
        ulonglong2 ka = lds2(ksU + src*4), kb = lds2(ksU + src*4 + 2);
        acc2[0] = fma2u(qa.x, ka.x, acc2[0]);
        acc2[1] = fma2u(qa.y, ka.y, acc2[1]);
        acc2[2] = fma2u(qb.x, kb.x, acc2[2]);
        acc2[3] = fma2u(qb.y, kb.y, acc2[3]);
    }
    u64 s2 = add2u(add2u(acc2[0], acc2[1]), add2u(acc2[2], acc2[3]));
    float sx, sy; unpack2(s2, sx, sy);
    return act ? (sx + sy) * 0.125f : -1e30f;
}

// ============================================================================
// Kernel A: register-resident per-sample pipeline, FFMA2, 2 samples/warp.
// (exact R12 version)
// ============================================================================
__global__ __launch_bounds__(256, 2) void kA(
    const float* __restrict__ x,
    const float* __restrict__ W_emb, const float* __restrict__ b_emb,
    const float* __restrict__ Wq, const float* __restrict__ bq,
    const float* __restrict__ Wk, const float* __restrict__ bk,
    const float* __restrict__ Wv, const float* __restrict__ bv,
    const float* __restrict__ Wo, const float* __restrict__ bo,
    const float* __restrict__ Wff1, const float* __restrict__ Wff2,
    const float* __restrict__ gnorm, const float* __restrict__ bnorm,
    const float* __restrict__ Wdy, const float* __restrict__ bdy,
    const float* __restrict__ channels)
{
    __shared__ __align__(16) float2 sWeP[336];
    __shared__ __align__(16) float  sbe[14];
    __shared__ __align__(16) float  sWq[112], sWk[112], sWv[112];
    __shared__ __align__(16) float  sbq[8], sbk[8], sbv[8];
    __shared__ __align__(16) float2 sWoP[64];
    __shared__ __align__(16) float  sbo[14];
    __shared__ __align__(16) float2 sF1P[400];
    __shared__ __align__(16) float2 sF2P[400];
    __shared__ __align__(16) float  sg[14], sb[14];
    __shared__ __align__(16) float  sWdy[900], sbdy[32];
    __shared__ __align__(16) float2 sAdjP[112];
    __shared__ __align__(16) float  scr[8][960];

    const int tid = threadIdx.x;
    for (int i = tid; i < 336; i += 256) {
        int ct = i >> 3, op = i & 7;
        float a = 0.f, b = 0.f;
        if (op < 7) { a = W_emb[(2*op)*42 + ct]; b = W_emb[(2*op+1)*42 + ct]; }
        sWeP[i] = make_float2(a, b);
    }
    for (int i = tid; i < 112; i += 256) { sWq[i]=Wq[i]; sWk[i]=Wk[i]; sWv[i]=Wv[i]; }
    for (int i = tid; i < 64; i += 256) {
        int h = i >> 3, dp = i & 7;
        float a = 0.f, b = 0.f;
        if (dp < 7) { a = Wo[h*14 + 2*dp]; b = Wo[h*14 + 2*dp + 1]; }
        sWoP[i] = make_float2(a, b);
    }
    for (int i = tid; i < 400; i += 256) {
        int f = i >> 3, dp = i & 7;
        float a1 = 0.f, b1v = 0.f, a2 = 0.f, b2v = 0.f;
        if (dp < 7) {
            a1 = Wff1[(2*dp)*50 + f]; b1v = Wff1[(2*dp+1)*50 + f];
            a2 = Wff2[f*14 + 2*dp];   b2v = Wff2[f*14 + 2*dp + 1];
        }
        sF1P[i] = make_float2(a1, b1v);
        sF2P[i] = make_float2(a2, b2v);
    }
    for (int i = tid; i < 900; i += 256) sWdy[i] = Wdy[i];
    if (tid < 30) sbdy[tid] = bdy[tid];
    if (tid < 14) { sbe[tid]=b_emb[tid]; sbo[tid]=bo[tid]; sg[tid]=gnorm[tid]; sb[tid]=bnorm[tid]; }
    if (tid < 8)  { sbq[tid]=bq[tid]; sbk[tid]=bk[tid]; sbv[tid]=bv[tid]; }
    if (tid < 14) {
        const float* row = channels + tid * 14;
        float mx = -1e30f;
        #pragma unroll
        for (int j = 0; j < 14; j++) mx = fmaxf(mx, row[j]);
        float s = 0.f;
        #pragma unroll
        for (int j = 0; j < 14; j++) s += expf(row[j] - mx);
        float inv = 1.f / s;
        #pragma unroll
        for (int j = 0; j < 7; j++)
            sAdjP[tid*8 + j] = make_float2(expf(row[2*j] - mx) * inv,
                                           expf(row[2*j+1] - mx) * inv);
        sAdjP[tid*8 + 7] = make_float2(0.f, 0.f);
    }
    __syncthreads();

    const int w    = tid >> 5;
    const int lane = tid & 31;
    const int t    = (lane < 30) ? lane : 0;
    const bool act = (lane < 30);
    const int smpA = blockIdx.x * 16 + w * 2;
    u64* scrU = reinterpret_cast<u64*>(scr[w]);

    {
        const float4* xpA = reinterpret_cast<const float4*>(x + (size_t)smpA * 420);
        const float4* xpB = reinterpret_cast<const float4*>(x + (size_t)(smpA+1) * 420);
        float4* sp = reinterpret_cast<float4*>(scr[w]);
        #pragma unroll
        for (int i = lane; i < 105; i += 32) { sp[i] = xpA[i]; sp[105 + i] = xpB[i]; }
    }
    __syncwarp();
    float xrA[14], xrB[14];
    #pragma unroll
    for (int d = 0; d < 14; d++) {
        xrA[d] = scr[w][t*14 + d];
        xrB[d] = scr[w][420 + t*14 + d];
    }
    __syncwarp();

    u64 xeA[7], xeB[7];
    {
        const u64* sbe2 = reinterpret_cast<const u64*>(sbe);
        #pragma unroll
        for (int op = 0; op < 7; op++) { xeA[op] = sbe2[op]; xeB[op] = sbe2[op]; }
        const u64* we = reinterpret_cast<const u64*>(sWeP);
        #pragma unroll
        for (int ci = 0; ci < 14; ci++) {
            float upA = __shfl_up_sync(FULL, xrA[ci], 1);
            float dnA = __shfl_down_sync(FULL, xrA[ci], 1);
            float upB = __shfl_up_sync(FULL, xrB[ci], 1);
            float dnB = __shfl_down_sync(FULL, xrB[ci], 1);
            float tapA[3] = { (lane > 0) ? upA : 0.f, xrA[ci], (lane < 29) ? dnA : 0.f };
            float tapB[3] = { (lane > 0) ? upB : 0.f, xrB[ci], (lane < 29) ? dnB : 0.f };
            #pragma unroll
            for (int tp = 0; tp < 3; tp++) {
                u64 xa = dup2(tapA[tp]), xb = dup2(tapB[tp]);
                const u64* wr = we + (ci*3 + tp) * 8;
                ulonglong2 w0 = lds2(wr), w1 = lds2(wr+2), w2 = lds2(wr+4);
                u64 w6 = wr[6];
                xeA[0] = fma2u(xa, w0.x, xeA[0]); xeB[0] = fma2u(xb, w0.x, xeB[0]);
                xeA[1] = fma2u(xa, w0.y, xeA[1]); xeB[1] = fma2u(xb, w0.y, xeB[1]);
                xeA[2] = fma2u(xa, w1.x, xeA[2]); xeB[2] = fma2u(xb, w1.x, xeB[2]);
                xeA[3] = fma2u(xa, w1.y, xeA[3]); xeB[3] = fma2u(xb, w1.y, xeB[3]);
                xeA[4] = fma2u(xa, w2.x, xeA[4]); xeB[4] = fma2u(xb, w2.x, xeB[4]);
                xeA[5] = fma2u(xa, w2.y, xeA[5]); xeB[5] = fma2u(xb, w2.y, xeB[5]);
                xeA[6] = fma2u(xa, w6,   xeA[6]); xeB[6] = fma2u(xb, w6,   xeB[6]);
            }
        }
    }

    u64 qA[4], kA_[4], vA[4], qB[4], kB_[4], vB[4];
    {
        const u64* bq2 = reinterpret_cast<const u64*>(sbq);
        const u64* bk2 = reinterpret_cast<const u64*>(sbk);
        const u64* bv2 = reinterpret_cast<const u64*>(sbv);
        #pragma unroll
        for (int hp = 0; hp < 4; hp++) {
            qA[hp]=bq2[hp]; kA_[hp]=bk2[hp]; vA[hp]=bv2[hp];
            qB[hp]=bq2[hp]; kB_[hp]=bk2[hp]; vB[hp]=bv2[hp];
        }
        const u64* wq2 = reinterpret_cast<const u64*>(sWq);
        const u64* wk2 = reinterpret_cast<const u64*>(sWk);
        const u64* wv2 = reinterpret_cast<const u64*>(sWv);
        #pragma unroll
        for (int dp = 0; dp < 7; dp++) {
            float ax, ay, bx, by;
            unpack2(xeA[dp], ax, ay);
            unpack2(xeB[dp], bx, by);
            float sA[2] = { ax, ay }, sB[2] = { bx, by };
            #pragma unroll
            for (int half = 0; half < 2; half++) {
                int d = 2*dp + half;
                u64 xa = dup2(sA[half]), xb = dup2(sB[half]);
                ulonglong2 qa = lds2(wq2 + d*4), qb = lds2(wq2 + d*4 + 2);
                ulonglong2 ka = lds2(wk2 + d*4), kb = lds2(wk2 + d*4 + 2);
                ulonglong2 va = lds2(wv2 + d*4), vb = lds2(wv2 + d*4 + 2);
                qA[0] = fma2u(xa, qa.x, qA[0]); qB[0] = fma2u(xb, qa.x, qB[0]);
                qA[1] = fma2u(xa, qa.y, qA[1]); qB[1] = fma2u(xb, qa.y, qB[1]);
                qA[2] = fma2u(xa, qb.x, qA[2]); qB[2] = fma2u(xb, qb.x, qB[2]);
                qA[3] = fma2u(xa, qb.y, qA[3]); qB[3] = fma2u(xb, qb.y, qB[3]);
                kA_[0] = fma2u(xa, ka.x, kA_[0]); kB_[0] = fma2u(xb, ka.x, kB_[0]);
                kA_[1] = fma2u(xa, ka.y, kA_[1]); kB_[1] = fma2u(xb, ka.y, kB_[1]);
                kA_[2] = fma2u(xa, kb.x, kA_[2]); kB_[2] = fma2u(xb, kb.x, kB_[2]);
                kA_[3] = fma2u(xa, kb.y, kA_[3]); kB_[3] = fma2u(xb, kb.y, kB_[3]);
                vA[0] = fma2u(xa, va.x, vA[0]); vB[0] = fma2u(xb, va.x, vB[0]);
                vA[1] = fma2u(xa, va.y, vA[1]); vB[1] = fma2u(xb, va.y, vB[1]);
                vA[2] = fma2u(xa, vb.x, vA[2]); vB[2] = fma2u(xb, vb.x, vB[2]);
                vA[3] = fma2u(xa, vb.y, vA[3]); vB[3] = fma2u(xb, vb.y, vB[3]);
            }
        }
    }

    u64* qsA = scrU;
    u64* ksA = scrU + 120;
    u64* qsB = scrU + 240;
    u64* ksB = scrU + 360;
    if (act) {
        *reinterpret_cast<ulonglong2*>(qsA + t*4)     = make_ulonglong2(qA[0], qA[1]);
        *reinterpret_cast<ulonglong2*>(qsA + t*4 + 2) = make_ulonglong2(qA[2], qA[3]);
        *reinterpret_cast<ulonglong2*>(ksA + t*4)     = make_ulonglong2(kA_[0], kA_[1]);
        *reinterpret_cast<ulonglong2*>(ksA + t*4 + 2) = make_ulonglong2(kA_[2], kA_[3]);
        *reinterpret_cast<ulonglong2*>(qsB + t*4)     = make_ulonglong2(qB[0], qB[1]);
        *reinterpret_cast<ulonglong2*>(qsB + t*4 + 2) = make_ulonglong2(qB[2], qB[3]);
        *reinterpret_cast<ulonglong2*>(ksB + t*4)     = make_ulonglong2(kB_[0], kB_[1]);
        *reinterpret_cast<ulonglong2*>(ksB + t*4 + 2) = make_ulonglong2(kB_[2], kB_[3]);
    }
    __syncwarp();

    float mvA = corr30(qsA, ksA, t, act);
    float mvB = corr30(qsB, ksB, t, act);
    float w0A, w1A, w2A, w0B, w1B, w2B;
    int dl0A, dl1A, dl2A, dl0B, dl1B, dl2B;
    top3softmax(mvA, lane, w0A, w1A, w2A, dl0A, dl1A, dl2A);
    top3softmax(mvB, lane, w0B, w1B, w2B, dl0B, dl1B, dl2B);

    u64 aggA[4], aggB[4];
    {
        int s0 = t + dl0A; if (s0 >= 30) s0 -= 30;
        int s1 = t + dl1A; if (s1 >= 30) s1 -= 30;
        int s2 = t + dl2A; if (s2 >= 30) s2 -= 30;
        u64 c0 = dup2(w0A), c1 = dup2(w1A), c2 = dup2(w2A);
        #pragma unroll
        for (int hp = 0; hp < 4; hp++) {
            u64 y0 = __shfl_sync(FULL, vA[hp], s0);
            u64 y1 = __shfl_sync(FULL, vA[hp], s1);
            u64 y2 = __shfl_sync(FULL, vA[hp], s2);
            aggA[hp] = fma2u(c0, y0, fma2u(c1, y1, fma2u(c2, y2, 0ULL)));
        }
    }
    {
        int s0 = t + dl0B; if (s0 >= 30) s0 -= 30;
        int s1 = t + dl1B; if (s1 >= 30) s1 -= 30;
        int s2 = t + dl2B; if (s2 >= 30) s2 -= 30;
        u64 c0 = dup2(w0B), c1 = dup2(w1B), c2 = dup2(w2B);
        #pragma unroll
        for (int hp = 0; hp < 4; hp++) {
            u64 y0 = __shfl_sync(FULL, vB[hp], s0);
            u64 y1 = __shfl_sync(FULL, vB[hp], s1);
            u64 y2 = __shfl_sync(FULL, vB[hp], s2);
            aggB[hp] = fma2u(c0, y0, fma2u(c1, y1, fma2u(c2, y2, 0ULL)));
        }
    }

    u64 x1A[7], x1B[7];
    {
        const u64* sbo2 = reinterpret_cast<const u64*>(sbo);
        #pragma unroll
        for (int dp = 0; dp < 7; dp++) {
            x1A[dp] = add2u(xeA[dp], sbo2[dp]);
            x1B[dp] = add2u(xeB[dp], sbo2[dp]);
        }
        const u64* wo = reinterpret_cast<const u64*>(sWoP);
        #pragma unroll
        for (int hp = 0; hp < 4; hp++) {
            float aAx, aAy, aBx, aBy;
            unpack2(aggA[hp], aAx, aAy);
            unpack2(aggB[hp], aBx, aBy);
            float sA[2] = { aAx, aAy }, sB[2] = { aBx, aBy };
            #pragma unroll
            for (int half = 0; half < 2; half++) {
                int h = 2*hp + half;
                u64 aa = dup2(sA[half]), ab = dup2(sB[half]);
                const u64* wr = wo + h*8;
                ulonglong2 w0v = lds2(wr), w1v = lds2(wr+2), w2v = lds2(wr+4);
                u64 w6 = wr[6];
                x1A[0] = fma2u(aa, w0v.x, x1A[0]); x1B[0] = fma2u(ab, w0v.x, x1B[0]);
                x1A[1] = fma2u(aa, w0v.y, x1A[1]); x1B[1] = fma2u(ab, w0v.y, x1B[1]);
                x1A[2] = fma2u(aa, w1v.x, x1A[2]); x1B[2] = fma2u(ab, w1v.x, x1B[2]);
                x1A[3] = fma2u(aa, w1v.y, x1A[3]); x1B[3] = fma2u(ab, w1v.y, x1B[3]);
                x1A[4] = fma2u(aa, w2v.x, x1A[4]); x1B[4] = fma2u(ab, w2v.x, x1B[4]);
                x1A[5] = fma2u(aa, w2v.y, x1A[5]); x1B[5] = fma2u(ab, w2v.y, x1B[5]);
                x1A[6] = fma2u(aa, w6,    x1A[6]); x1B[6] = fma2u(ab, w6,    x1B[6]);
            }
        }
    }

    const float fc0  = (t < 12) ? (float)(12 - t) : 0.f;
    const float fc29 = (t > 17) ? (float)(t - 17) : 0.f;
    const int hi   = (t + 12 > 29) ? 29 : t + 12;
    const int lom1 = t - 13;
    const int loix = (lom1 < 0) ? 0 : lom1;
    u64 xdA[7], xdB[7];
    #pragma unroll
    for (int dp = 0; dp < 7; dp++) {
        float vx, vy;
        unpack2(x1A[dp], vx, vy);
        xdA[dp] = pack2(decomp25(vx, lane, hi, loix, lom1, fc0, fc29),
                        decomp25(vy, lane, hi, loix, lom1, fc0, fc29));
        unpack2(x1B[dp], vx, vy);
        xdB[dp] = pack2(decomp25(vx, lane, hi, loix, lom1, fc0, fc29),
                        decomp25(vy, lane, hi, loix, lom1, fc0, fc29));
    }

    u64 x2A[7], x2B[7];
    {
        u64 yA[7] = {}, yB[7] = {};
        const u64* f1 = reinterpret_cast<const u64*>(sF1P);
        const u64* f2 = reinterpret_cast<const u64*>(sF2P);
        #pragma unroll 5
        for (int f = 0; f < 50; f++) {
            const u64* r1 = f1 + f*8;
            ulonglong2 a0 = lds2(r1), a1 = lds2(r1+2), a2l = lds2(r1+4);
            u64 a6 = r1[6];
            u64 hA = fma2u(xdA[0], a0.x, 0ULL);
            u64 hB = fma2u(xdB[0], a0.x, 0ULL);
            hA = fma2u(xdA[1], a0.y, hA);   hB = fma2u(xdB[1], a0.y, hB);
            hA = fma2u(xdA[2], a1.x, hA);   hB = fma2u(xdB[2], a1.x, hB);
            hA = fma2u(xdA[3], a1.y, hA);   hB = fma2u(xdB[3], a1.y, hB);
            hA = fma2u(xdA[4], a2l.x, hA);  hB = fma2u(xdB[4], a2l.x, hB);
            hA = fma2u(xdA[5], a2l.y, hA);  hB = fma2u(xdB[5], a2l.y, hB);
            hA = fma2u(xdA[6], a6, hA);     hB = fma2u(xdB[6], a6, hB);
            float hx, hy;
            unpack2(hA, hx, hy);
            float hsA = hx + hy;
            unpack2(hB, hx, hy);
            float hsB = hx + hy;
            float gAv = 0.5f * hsA * (1.f + erff(hsA * 0.70710678118654752f));
            float gBv = 0.5f * hsB * (1.f + erff(hsB * 0.70710678118654752f));
            u64 gA2 = dup2(gAv), gB2 = dup2(gBv);
            const u64* r2 = f2 + f*8;
            ulonglong2 b0 = lds2(r2), b1v = lds2(r2+2), b2v = lds2(r2+4);
            u64 b6 = r2[6];
            yA[0] = fma2u(gA2, b0.x, yA[0]);  yB[0] = fma2u(gB2, b0.x, yB[0]);
            yA[1] = fma2u(gA2, b0.y, yA[1]);  yB[1] = fma2u(gB2, b0.y, yB[1]);
            yA[2] = fma2u(gA2, b1v.x, yA[2]); yB[2] = fma2u(gB2, b1v.x, yB[2]);
            yA[3] = fma2u(gA2, b1v.y, yA[3]); yB[3] = fma2u(gB2, b1v.y, yB[3]);
            yA[4] = fma2u(gA2, b2v.x, yA[4]); yB[4] = fma2u(gB2, b2v.x, yB[4]);
            yA[5] = fma2u(gA2, b2v.y, yA[5]); yB[5] = fma2u(gB2, b2v.y, yB[5]);
            yA[6] = fma2u(gA2, b6, yA[6]);    yB[6] = fma2u(gB2, b6, yB[6]);
        }
        #pragma unroll
        for (int dp = 0; dp < 7; dp++) {
            x2A[dp] = add2u(xdA[dp], yA[dp]);
            x2B[dp] = add2u(xdB[dp], yB[dp]);
        }
    }

    float x3Ax[7], x3Ay[7], x3Bx[7], x3By[7];
    #pragma unroll
    for (int dp = 0; dp < 7; dp++) {
        float vx, vy;
        unpack2(x2A[dp], vx, vy);
        x3Ax[dp] = decomp25(vx, lane, hi, loix, lom1, fc0, fc29);
        x3Ay[dp] = decomp25(vy, lane, hi, loix, lom1, fc0, fc29);
        unpack2(x2B[dp], vx, vy);
        x3Bx[dp] = decomp25(vx, lane, hi, loix, lom1, fc0, fc29);
        x3By[dp] = decomp25(vy, lane, hi, loix, lom1, fc0, fc29);
    }
    {
        float mA = 0.f, mB = 0.f;
        #pragma unroll
        for (int dp = 0; dp < 7; dp++) { mA += x3Ax[dp] + x3Ay[dp]; mB += x3Bx[dp] + x3By[dp]; }
        mA *= (1.f / 14.f); mB *= (1.f / 14.f);
        float vA_ = 0.f, vB_ = 0.f;
        #pragma unroll
        for (int dp = 0; dp < 7; dp++) {
            float dx = x3Ax[dp] - mA, dy = x3Ay[dp] - mA;
            vA_ += dx * dx + dy * dy;
            dx = x3Bx[dp] - mB; dy = x3By[dp] - mB;
            vB_ += dx * dx + dy * dy;
        }
        vA_ *= (1.f / 14.f); vB_ *= (1.f / 14.f);
        float iA = rsqrtf(vA_ + 1e-5f), iB = rsqrtf(vB_ + 1e-5f);
        #pragma unroll
        for (int dp = 0; dp < 7; dp++) {
            float g0 = sg[2*dp], g1 = sg[2*dp+1], b0 = sb[2*dp], b1v = sb[2*dp+1];
            x3Ax[dp] = (x3Ax[dp] - mA) * iA * g0 + b0;
            x3Ay[dp] = (x3Ay[dp] - mA) * iA * g1 + b1v;
            x3Bx[dp] = (x3Bx[dp] - mB) * iB * g0 + b0;
            x3By[dp] = (x3By[dp] - mB) * iB * g1 + b1v;
        }
    }

    __syncwarp();
    u64* x3sA = scrU;
    u64* x3sB = scrU + 240;
    if (act) {
        *reinterpret_cast<ulonglong2*>(x3sA + t*8)     = make_ulonglong2(pack2(x3Ax[0], x3Ay[0]), pack2(x3Ax[1], x3Ay[1]));
        *reinterpret_cast<ulonglong2*>(x3sA + t*8 + 2) = make_ulonglong2(pack2(x3Ax[2], x3Ay[2]), pack2(x3Ax[3], x3Ay[3]));
        *reinterpret_cast<ulonglong2*>(x3sA + t*8 + 4) = make_ulonglong2(pack2(x3Ax[4], x3Ay[4]), pack2(x3Ax[5], x3Ay[5]));
        x3sA[t*8 + 6] = pack2(x3Ax[6], x3Ay[6]);
        *reinterpret_cast<ulonglong2*>(x3sB + t*8)     = make_ulonglong2(pack2(x3Bx[0], x3By[0]), pack2(x3Bx[1], x3By[1]));
        *reinterpret_cast<ulonglong2*>(x3sB + t*8 + 2) = make_ulonglong2(pack2(x3Bx[2], x3By[2]), pack2(x3Bx[3], x3By[3]));
        *reinterpret_cast<ulonglong2*>(x3sB + t*8 + 4) = make_ulonglong2(pack2(x3Bx[4], x3By[4]), pack2(x3Bx[5], x3By[5]));
        x3sB[t*8 + 6] = pack2(x3Bx[6], x3By[6]);
    }
    __syncwarp();
    u64 accA[7], accB[7];
    {
        u64 bias2 = dup2(sbdy[t]);
        #pragma unroll
        for (int dp = 0; dp < 7; dp++) { accA[dp] = bias2; accB[dp] = bias2; }
        #pragma unroll
        for (int m = 0; m < 30; m++) {
            u64 wm2 = dup2(sWdy[m*30 + t]);
            const u64* xa = x3sA + m*8;
            const u64* xb = x3sB + m*8;
            ulonglong2 a0 = lds2(xa), a1 = lds2(xa+2), a2l = lds2(xa+4);
            u64 a6 = xa[6];
            ulonglong2 b0 = lds2(xb), b1v = lds2(xb+2), b2v = lds2(xb+4);
            u64 b6 = xb[6];
            accA[0] = fma2u(a0.x, wm2, accA[0]);  accB[0] = fma2u(b0.x, wm2, accB[0]);
            accA[1] = fma2u(a0.y, wm2, accA[1]);  accB[1] = fma2u(b0.y, wm2, accB[1]);
            accA[2] = fma2u(a1.x, wm2, accA[2]);  accB[2] = fma2u(b1v.x, wm2, accB[2]);
            accA[3] = fma2u(a1.y, wm2, accA[3]);  accB[3] = fma2u(b1v.y, wm2, accB[3]);
            accA[4] = fma2u(a2l.x, wm2, accA[4]); accB[4] = fma2u(b2v.x, wm2, accB[4]);
            accA[5] = fma2u(a2l.y, wm2, accA[5]); accB[5] = fma2u(b2v.y, wm2, accB[5]);
            accA[6] = fma2u(a6,   wm2, accA[6]);  accB[6] = fma2u(b6,   wm2, accB[6]);
        }
    }

    {
        float* foA = g_f + (size_t)smpA * 420;
        float* foB = g_f + (size_t)(smpA+1) * 420;
        const u64* adj = reinterpret_cast<const u64*>(sAdjP);
        #pragma unroll
        for (int i = 0; i < 14; i++) {
            const u64* ar = adj + i*8;
            ulonglong2 a0 = lds2(ar), a1 = lds2(ar+2), a2l = lds2(ar+4);
            u64 a6 = ar[6];
            u64 sA2 = fma2u(a0.x, accA[0], 0ULL);
            u64 sB2 = fma2u(a0.x, accB[0], 0ULL);
            sA2 = fma2u(a0.y, accA[1], sA2);  sB2 = fma2u(a0.y, accB[1], sB2);
            sA2 = fma2u(a1.x, accA[2], sA2);  sB2 = fma2u(a1.x, accB[2], sB2);
            sA2 = fma2u(a1.y, accA[3], sA2);  sB2 = fma2u(a1.y, accB[3], sB2);
            sA2 = fma2u(a2l.x, accA[4], sA2); sB2 = fma2u(a2l.x, accB[4], sB2);
            sA2 = fma2u(a2l.y, accA[5], sA2); sB2 = fma2u(a2l.y, accB[5], sB2);
            sA2 = fma2u(a6, accA[6], sA2);    sB2 = fma2u(a6, accB[6], sB2);
            float ax, ay;
            unpack2(sA2, ax, ay);
            if (act) foA[i*30 + t] = fmaxf(ax + ay, 0.f);
            unpack2(sB2, ax, ay);
            if (act) foB[i*30 + t] = fmaxf(ax + ay, 0.f);
        }
    }
}

// ============================================================================
// Kernel B (3xBF16 m16n8k16, R12 version, SWAPPED GRID: x = n-slice, y = m):
// hh = relu(f @ W1 + b1). Blocks sharing an A-tile are launch-adjacent -> L2.
// ============================================================================
__global__ __launch_bounds__(256) void kB(const float* __restrict__ W1,
                                          const float* __restrict__ b1)
{
    __shared__ unsigned Ah[128][20], Al[128][20];   // [m][kp], kp = k/2 (16 used)
    __shared__ unsigned Bh[64][20],  Bl[64][20];    // [n][kp]
    const int tid = threadIdx.x;
    const int lane = tid & 31, wid = tid >> 5;
    const int wm = wid >> 1, wn = wid & 1;
    const int c4 = lane & 3;
    const size_t mbase = (size_t)blockIdx.y * 128;   // SWAPPED
    const int nbase = blockIdx.x * 64;               // SWAPPED
    float c[2][4][4] = {};

    for (int k0 = 0; k0 < 448; k0 += 32) {
        // A stage: row m = tid>>1, half = tid&1 covers kps [half*8, half*8+8)
        {
            int m = tid >> 1, half = tid & 1;
            const float4* gr = reinterpret_cast<const float4*>(g_f + (mbase + m) * 420);
            #pragma unroll
            for (int j = 0; j < 4; j++) {
                int kq = (k0 >> 2) + half*4 + j;
                float4 vv = (kq < 105) ? gr[kq] : make_float4(0.f,0.f,0.f,0.f);
                int kp = half*8 + 2*j;
                unsigned h, l;
                split_bf16x2(vv.x, vv.y, h, l); Ah[m][kp]   = h; Al[m][kp]   = l;
                split_bf16x2(vv.z, vv.w, h, l); Ah[m][kp+1] = h; Al[m][kp+1] = l;
            }
        }
        // B stage: thread -> (kp = tid>>4, n4 = (tid&15)*4); loads k rows 2kp, 2kp+1
        {
            int kp = tid >> 4;
            int n4 = (tid & 15) * 4;
            int gk0 = k0 + 2*kp, gk1 = gk0 + 1;
            float4 r0 = (gk0 < 420) ? *reinterpret_cast<const float4*>(W1 + (size_t)gk0*256 + nbase + n4)
                                    : make_float4(0.f,0.f,0.f,0.f);
            float4 r1 = (gk1 < 420) ? *reinterpret_cast<const float4*>(W1 + (size_t)gk1*256 + nbase + n4)
                                    : make_float4(0.f,0.f,0.f,0.f);
            unsigned h, l;
            split_bf16x2(r0.x, r1.x, h, l); Bh[n4+0][kp] = h; Bl[n4+0][kp] = l;
            split_bf16x2(r0.y, r1.y, h, l); Bh[n4+1][kp] = h; Bl[n4+1][kp] = l;
            split_bf16x2(r0.z, r1.z, h, l); Bh[n4+2][kp] = h; Bl[n4+2][kp] = l;
            split_bf16x2(r0.w, r1.w, h, l); Bh[n4+3][kp] = h; Bl[n4+3][kp] = l;
        }
        __syncthreads();
        #pragma unroll
        for (int ks = 0; ks < 2; ks++) {
            int kb = ks * 8;
            unsigned ah[2][4], al[2][4], bh[4][2], bl[4][2];
            #pragma unroll
            for (int mt = 0; mt < 2; mt++) {
                int r = wm*32 + mt*16 + (lane>>2);
                ah[mt][0] = Ah[r  ][kb + c4];     al[mt][0] = Al[r  ][kb + c4];
                ah[mt][1] = Ah[r+8][kb + c4];     al[mt][1] = Al[r+8][kb + c4];
                ah[mt][2] = Ah[r  ][kb + c4 + 4]; al[mt][2] = Al[r  ][kb + c4 + 4];
                ah[mt][3] = Ah[r+8][kb + c4 + 4]; al[mt][3] = Al[r+8][kb + c4 + 4];
            }
            #pragma unroll
            for (int nt = 0; nt < 4; nt++) {
                int nn = wn*32 + nt*8 + (lane>>2);
                bh[nt][0] = Bh[nn][kb + c4];     bl[nt][0] = Bl[nn][kb + c4];
                bh[nt][1] = Bh[nn][kb + c4 + 4]; bl[nt][1] = Bl[nn][kb + c4 + 4];
            }
            #pragma unroll
            for (int mt = 0; mt < 2; mt++)
                #pragma unroll
                for (int nt = 0; nt < 4; nt++) {
                    mma_bf16(c[mt][nt], ah[mt], bh[nt]);
                    mma_bf16(c[mt][nt], ah[mt], bl[nt]);
                    mma_bf16(c[mt][nt], al[mt], bh[nt]);
                }
        }
        __syncthreads();
    }
    #pragma unroll
    for (int mt = 0; mt < 2; mt++) {
        int r0 = wm*32 + mt*16 + (lane>>2);
        #pragma unroll
        for (int nt = 0; nt < 4; nt++) {
            int cl = nbase + wn*32 + nt*8 + 2*(lane&3);
            float b0 = b1[cl], b1v = b1[cl+1];
            float2 lo = make_float2(fmaxf(c[mt][nt][0] + b0, 0.f), fmaxf(c[mt][nt][1] + b1v, 0.f));
            float2 hi = make_float2(fmaxf(c[mt][nt][2] + b0, 0.f), fmaxf(c[mt][nt][3] + b1v, 0.f));
            *reinterpret_cast<float2*>(g_hh + (mbase + r0    ) * 256 + cl) = lo;
            *reinterpret_cast<float2*>(g_hh + (mbase + r0 + 8) * 256 + cl) = hi;
        }
    }
}

// ============================================================================
// Kernel C (3xBF16, fused LN head, exact R12 version):
// hr = [hh|f]@[W2;Wres]+b2+bres, out = LN64(hr)@W3+b3. K=704(pad), BK=32.
// ============================================================================
__global__ __launch_bounds__(256) void kC(const float* __restrict__ W2,
                                          const float* __restrict__ b2,
                                          const float* __restrict__ Wres,
                                          const float* __restrict__ bres,
                                          const float* __restrict__ g_ln,
                                          const float* __restrict__ b_ln,
                                          const float* __restrict__ W3,
                                          const float* __restrict__ b3,
                                          float* __restrict__ out)
{
    __shared__ unsigned Ah[128][20], Al[128][20];
    __shared__ unsigned Bh[64][20],  Bl[64][20];
    __shared__ float sbb[64];
    __shared__ float sgw[64];
    __shared__ float sp[128][2][3];
    __shared__ float sconst[2];
    const int tid = threadIdx.x;
    const int lane = tid & 31, wid = tid >> 5;
    const int wm = wid >> 1, wn = wid & 1;
    const int c4 = lane & 3;
    const size_t mbase = (size_t)blockIdx.x * 128;
    float c[2][4][4] = {};

    if (tid < 64) {
        sbb[tid] = b2[tid] + bres[tid];
        sgw[tid] = g_ln[tid] * W3[tid];
    }

    for (int k0 = 0; k0 < 704; k0 += 32) {
        // A stage: concat [hh(256) | f(420)]
        {
            int m = tid >> 1, half = tid & 1;
            const float* hrow = g_hh + (mbase + m) * 256;
            const float* frow = g_f  + (mbase + m) * 420;
            #pragma unroll
            for (int j = 0; j < 4; j++) {
                int gk = k0 + half*16 + 4*j;
                float4 vv = make_float4(0.f,0.f,0.f,0.f);
                if (gk < 256) vv = *reinterpret_cast<const float4*>(hrow + gk);
                else { int kf = gk - 256; if (kf < 420) vv = *reinterpret_cast<const float4*>(frow + kf); }
                int kp = half*8 + 2*j;
                unsigned h, l;
                split_bf16x2(vv.x, vv.y, h, l); Ah[m][kp]   = h; Al[m][kp]   = l;
                split_bf16x2(vv.z, vv.w, h, l); Ah[m][kp+1] = h; Al[m][kp+1] = l;
            }
        }
        // B stage: concat [W2(256x64) ; Wres(420x64)]
        {
            int kp = tid >> 4;
            int n4 = (tid & 15) * 4;
            int gk0 = k0 + 2*kp, gk1 = gk0 + 1;
            float4 r0 = make_float4(0.f,0.f,0.f,0.f);
            float4 r1 = make_float4(0.f,0.f,0.f,0.f);
            if (gk0 < 256) r0 = *reinterpret_cast<const float4*>(W2 + (size_t)gk0*64 + n4);
            else { int kf = gk0 - 256; if (kf < 420) r0 = *reinterpret_cast<const float4*>(Wres + (size_t)kf*64 + n4); }
            if (gk1 < 256) r1 = *reinterpret_cast<const float4*>(W2 + (size_t)gk1*64 + n4);
            else { int kf = gk1 - 256; if (kf < 420) r1 = *reinterpret_cast<const float4*>(Wres + (size_t)kf*64 + n4); }
            unsigned h, l;
            split_bf16x2(r0.x, r1.x, h, l); Bh[n4+0][kp] = h; Bl[n4+0][kp] = l;
            split_bf16x2(r0.y, r1.y, h, l); Bh[n4+1][kp] = h; Bl[n4+1][kp] = l;
            split_bf16x2(r0.z, r1.z, h, l); Bh[n4+2][kp] = h; Bl[n4+2][kp] = l;
            split_bf16x2(r0.w, r1.w, h, l); Bh[n4+3][kp] = h; Bl[n4+3][kp] = l;
        }
        __syncthreads();
        #pragma unroll
        for (int ks = 0; ks < 2; ks++) {
            int kb = ks * 8;
            unsigned ah[2][4], al[2][4], bh[4][2], bl[4][2];
            #pragma unroll
            for (int mt = 0; mt < 2; mt++) {
                int r = wm*32 + mt*16 + (lane>>2);
                ah[mt][0] = Ah[r  ][kb + c4];     al[mt][0] = Al[r  ][kb + c4];
                ah[mt][1] = Ah[r+8][kb + c4];     al[mt][1] = Al[r+8][kb + c4];
                ah[mt][2] = Ah[r  ][kb + c4 + 4]; al[mt][2] = Al[r  ][kb + c4 + 4];
                ah[mt][3] = Ah[r+8][kb + c4 + 4]; al[mt][3] = Al[r+8][kb + c4 + 4];
            }
            #pragma unroll
            for (int nt = 0; nt < 4; nt++) {
                int nn = wn*32 + nt*8 + (lane>>2);
                bh[nt][0] = Bh[nn][kb + c4];     bl[nt][0] = Bl[nn][kb + c4];
                bh[nt][1] = Bh[nn][kb + c4 + 4]; bl[nt][1] = Bl[nn][kb + c4 + 4];
            }
            #pragma unroll
            for (int mt = 0; mt < 2; mt++)
                #pragma unroll
                for (int nt = 0; nt < 4; nt++) {
                    mma_bf16(c[mt][nt], ah[mt], bh[nt]);
                    mma_bf16(c[mt][nt], ah[mt], bl[nt]);
                    mma_bf16(c[mt][nt], al[mt], bh[nt]);
                }
        }
        __syncthreads();
    }

    // ---- fused epilogue: partial LN sums per (row, wn-half) ----
    #pragma unroll
    for (int mt = 0; mt < 2; mt++) {
        #pragma unroll
        for (int rb = 0; rb < 2; rb++) {
            float sv = 0.f, sq = 0.f, sgd = 0.f;
            #pragma unroll
            for (int nt = 0; nt < 4; nt++) {
                int cl = wn*32 + nt*8 + 2*(lane&3);
                float v0 = c[mt][nt][2*rb]     + sbb[cl];
                float v1 = c[mt][nt][2*rb + 1] + sbb[cl+1];
                sv += v0 + v1;
                sq += v0*v0 + v1*v1;
                sgd += v0*sgw[cl] + v1*sgw[cl+1];
            }
            sv += __shfl_xor_sync(FULL, sv, 1);
            sq += __shfl_xor_sync(FULL, sq, 1);
            sgd += __shfl_xor_sync(FULL, sgd, 1);
            sv += __shfl_xor_sync(FULL, sv, 2);
            sq += __shfl_xor_sync(FULL, sq, 2);
            sgd += __shfl_xor_sync(FULL, sgd, 2);
            if ((lane & 3) == 0) {
                int row = wm*32 + mt*16 + rb*8 + (lane>>2);
                sp[row][wn][0] = sv;
                sp[row][wn][1] = sq;
                sp[row][wn][2] = sgd;
            }
        }
    }
    if (tid == 0) {
        float G = 0.f, cb = b3[0];
        for (int d = 0; d < 64; d++) { G += sgw[d]; cb += b_ln[d] * W3[d]; }
        sconst[0] = G; sconst[1] = cb;
    }
    __syncthreads();
    if (tid < 128) {
        int row = tid;
        float sv  = sp[row][0][0] + sp[row][1][0];
        float sq  = sp[row][0][1] + sp[row][1][1];
        float sgd = sp[row][0][2] + sp[row][1][2];
        float m = sv * (1.f / 64.f);
        float var = sq * (1.f / 64.f) - m * m;
        float invs = rsqrtf(var + 1e-5f);
        out[mbase + row] = invs * (sgd - m * sconst[0]) + sconst[1];
    }
}

// ============================================================================
extern "C" void kernel_launch(void* const* d_in, const int* in_sizes, int n_in,
                              void* d_out, int out_size)
{
    (void)in_sizes; (void)n_in; (void)out_size;
    const float* x = (const float*)d_in[0];

    kA<<<BATCH / 16, 256>>>(x,
        (const float*)d_in[1],  (const float*)d_in[2],
        (const float*)d_in[3],  (const float*)d_in[4],
        (const float*)d_in[5],  (const float*)d_in[6],
        (const float*)d_in[7],  (const float*)d_in[8],
        (const float*)d_in[9],  (const float*)d_in[10],
        (const float*)d_in[11], (const float*)d_in[12],
        (const float*)d_in[13], (const float*)d_in[14],
        (const float*)d_in[15], (const float*)d_in[16],
        (const float*)d_in[17]);

    kB<<<dim3(4, BATCH / 128), 256>>>((const float*)d_in[18], (const float*)d_in[19]);

    kC<<<BATCH / 128, 256>>>((const float*)d_in[20], (const float*)d_in[21],
                             (const float*)d_in[22], (const float*)d_in[23],
                             (const float*)d_in[24], (const float*)d_in[25],
                             (const float*)d_in[26], (const float*)d_in[27],
                             (float*)d_out);
}

// round 16
// speedup vs baseline: 1.1658x; 1.0464x over previous
#include <cuda_runtime.h>
#include <math.h>

#define BATCH 65536
#define FULL 0xffffffffu

typedef unsigned long long u64;

// -------- device scratch (allocation-free rule: __device__ globals) --------
__device__ float g_f [(size_t)BATCH * 420];   // DyConv output
__device__ float g_hh[(size_t)BATCH * 256];   // relu(f@W1+b1)

// ---------------- packed f32x2 ops on b64 registers ----------------
__device__ __forceinline__ u64 pack2(float x, float y) {
    u64 r; asm("mov.b64 %0, {%1, %2};" : "=l"(r) : "f"(x), "f"(y)); return r;
}
__device__ __forceinline__ u64 dup2(float s) { return pack2(s, s); }
__device__ __forceinline__ void unpack2(u64 v, float& x, float& y) {
    asm("mov.b64 {%0, %1}, %2;" : "=f"(x), "=f"(y) : "l"(v));
}
__device__ __forceinline__ u64 fma2u(u64 a, u64 b, u64 c) {
    u64 d; asm("fma.rn.f32x2 %0, %1, %2, %3;" : "=l"(d) : "l"(a), "l"(b), "l"(c)); return d;
}
__device__ __forceinline__ u64 add2u(u64 a, u64 b) {
    u64 d; asm("add.rn.f32x2 %0, %1, %2;" : "=l"(d) : "l"(a), "l"(b)); return d;
}
__device__ __forceinline__ ulonglong2 lds2(const u64* p) {
    return *reinterpret_cast<const ulonglong2*>(p);
}

// ---- fast GELU (tanh form, MUFU.TANH). |hs| stays < ~1 in this model, where
// tanh-form vs erf-form differ < 1e-6 and tanh.approx adds < ~2e-5 abs. ----
__device__ __forceinline__ float gelu_fast(float x) {
    float u = x * (0.7978845608028654f + 0.0356774081363001f * x * x);
    float tv;
    asm("tanh.approx.f32 %0, %1;" : "=f"(tv) : "f"(u));
    return 0.5f * x * (1.f + tv);
}

// ---------------- split-bf16 helpers (3xBF16 compensated GEMM) -------------
// e0 -> low half, e1 -> high half (matches mma bf16x2 k-pair layout)
__device__ __forceinline__ void split_bf16x2(float e0, float e1,
                                             unsigned& hi, unsigned& lo) {
    asm("cvt.rn.bf16x2.f32 %0, %1, %2;" : "=r"(hi) : "f"(e1), "f"(e0));
    float h0 = __uint_as_float(hi << 16);
    float h1 = __uint_as_float(hi & 0xffff0000u);
    float r0 = e0 - h0, r1 = e1 - h1;
    asm("cvt.rn.bf16x2.f32 %0, %1, %2;" : "=r"(lo) : "f"(r1), "f"(r0));
}
__device__ __forceinline__ void mma_bf16(float* c, const unsigned* a, const unsigned* b) {
    asm volatile(
        "mma.sync.aligned.m16n8k16.row.col.f32.bf16.bf16.f32 "
        "{%0,%1,%2,%3},{%4,%5,%6,%7},{%8,%9},{%0,%1,%2,%3};"
        : "+f"(c[0]), "+f"(c[1]), "+f"(c[2]), "+f"(c[3])
        : "r"(a[0]), "r"(a[1]), "r"(a[2]), "r"(a[3]), "r"(b[0]), "r"(b[1]));
}

// ---- shuffle-scan series_decomp helper (replicate-pad MA-25) ----
__device__ __forceinline__ float decomp25(float val, int lane, int hi, int loix,
                                          int lom1, float fc0, float fc29) {
    float cs = val;
    #pragma unroll
    for (int off = 1; off < 32; off <<= 1) {
        float o = __shfl_up_sync(FULL, cs, off);
        if (lane >= off) cs += o;
    }
    float cshi = __shfl_sync(FULL, cs, hi);
    float cslo = __shfl_sync(FULL, cs, loix);
    float ssum = cshi - ((lom1 >= 0) ? cslo : 0.f);
    float x0  = __shfl_sync(FULL, val, 0);
    float x29 = __shfl_sync(FULL, val, 29);
    return val - (ssum + fc0 * x0 + fc29 * x29) * (1.f / 25.f);
}

// ---- warp-parallel top-3 with first-index tie-break, then softmax ----
__device__ __forceinline__ void top3softmax(float mv, int lane,
                                            float& w0, float& w1, float& w2,
                                            int& dl0, int& dl1, int& dl2) {
    float wv0, wv1, wv2;
    float mrun = mv;
    #pragma unroll
    for (int p = 0; p < 3; p++) {
        float bv = mrun; int bi = lane;
        #pragma unroll
        for (int off = 16; off; off >>= 1) {
            float vo = __shfl_xor_sync(FULL, bv, off);
            int   io = __shfl_xor_sync(FULL, bi, off);
            if (vo > bv || (vo == bv && io < bi)) { bv = vo; bi = io; }
        }
        if (p == 0) { wv0 = bv; dl0 = bi; }
        else if (p == 1) { wv1 = bv; dl1 = bi; }
        else { wv2 = bv; dl2 = bi; }
        if (lane == bi) mrun = -1e30f;
    }
    float e1 = expf(wv1 - wv0);
    float e2 = expf(wv2 - wv0);
    float inv = 1.f / (1.f + e1 + e2);
    w0 = inv; w1 = e1 * inv; w2 = e2 * inv;
}

// ---- circular correlation for one sample (lane = tau) ----
__device__ __forceinline__ float corr30(const u64* qsU, const u64* ksU,
                                        int t, bool act) {
    u64 acc2[4] = {};
    #pragma unroll
    for (int tq = 0; tq < 30; tq++) {
        int src = tq - t; if (src < 0) src += 30;
        ulonglong2 qa = lds2(qsU + tq*4), qb = lds2(qsU + tq*4 + 2);
        ulonglong2 ka = lds2(ksU + src*4), kb = lds2(ksU + src*4 + 2);
        acc2[0] = fma2u(qa.x, ka.x, acc2[0]);
        acc2[1] = fma2u(qa.y, ka.y, acc2[1]);
        acc2[2] = fma2u(qb.x, kb.x, acc2[2]);
        acc2[3] = fma2u(qb.y, kb.y, acc2[3]);
    }
    u64 s2 = add2u(add2u(acc2[0], acc2[1]), add2u(acc2[2], acc2[3]));
    float sx, sy; unpack2(s2, sx, sy);
    return act ? (sx + sy) * 0.125f : -1e30f;
}

// ============================================================================
// Kernel A: register-resident per-sample pipeline, FFMA2, 2 samples/warp.
// (R12/R15 version with fast GELU)
// ============================================================================
__global__ __launch_bounds__(256, 2) void kA(
    const float* __restrict__ x,
    const float* __restrict__ W_emb, const float* __restrict__ b_emb,
    const float* __restrict__ Wq, const float* __restrict__ bq,
    const float* __restrict__ Wk, const float* __restrict__ bk,
    const float* __restrict__ Wv, const float* __restrict__ bv,
    const float* __restrict__ Wo, const float* __restrict__ bo,
    const float* __restrict__ Wff1, const float* __restrict__ Wff2,
    const float* __restrict__ gnorm, const float* __restrict__ bnorm,
    const float* __restrict__ Wdy, const float* __restrict__ bdy,
    const float* __restrict__ channels)
{
    __shared__ __align__(16) float2 sWeP[336];
    __shared__ __align__(16) float  sbe[14];
    __shared__ __align__(16) float  sWq[112], sWk[112], sWv[112];
    __shared__ __align__(16) float  sbq[8], sbk[8], sbv[8];
    __shared__ __align__(16) float2 sWoP[64];
    __shared__ __align__(16) float  sbo[14];
    __shared__ __align__(16) float2 sF1P[400];
    __shared__ __align__(16) float2 sF2P[400];
    __shared__ __align__(16) float  sg[14], sb[14];
    __shared__ __align__(16) float  sWdy[900], sbdy[32];
    __shared__ __align__(16) float2 sAdjP[112];
    __shared__ __align__(16) float  scr[8][960];

    const int tid = threadIdx.x;
    for (int i = tid; i < 336; i += 256) {
        int ct = i >> 3, op = i & 7;
        float a = 0.f, b = 0.f;
        if (op < 7) { a = W_emb[(2*op)*42 + ct]; b = W_emb[(2*op+1)*42 + ct]; }
        sWeP[i] = make_float2(a, b);
    }
    for (int i = tid; i < 112; i += 256) { sWq[i]=Wq[i]; sWk[i]=Wk[i]; sWv[i]=Wv[i]; }
    for (int i = tid; i < 64; i += 256) {
        int h = i >> 3, dp = i & 7;
        float a = 0.f, b = 0.f;
        if (dp < 7) { a = Wo[h*14 + 2*dp]; b = Wo[h*14 + 2*dp + 1]; }
        sWoP[i] = make_float2(a, b);
    }
    for (int i = tid; i < 400; i += 256) {
        int f = i >> 3, dp = i & 7;
        float a1 = 0.f, b1v = 0.f, a2 = 0.f, b2v = 0.f;
        if (dp < 7) {
            a1 = Wff1[(2*dp)*50 + f]; b1v = Wff1[(2*dp+1)*50 + f];
            a2 = Wff2[f*14 + 2*dp];   b2v = Wff2[f*14 + 2*dp + 1];
        }
        sF1P[i] = make_float2(a1, b1v);
        sF2P[i] = make_float2(a2, b2v);
    }
    for (int i = tid; i < 900; i += 256) sWdy[i] = Wdy[i];
    if (tid < 30) sbdy[tid] = bdy[tid];
    if (tid < 14) { sbe[tid]=b_emb[tid]; sbo[tid]=bo[tid]; sg[tid]=gnorm[tid]; sb[tid]=bnorm[tid]; }
    if (tid < 8)  { sbq[tid]=bq[tid]; sbk[tid]=bk[tid]; sbv[tid]=bv[tid]; }
    if (tid < 14) {
        const float* row = channels + tid * 14;
        float mx = -1e30f;
        #pragma unroll
        for (int j = 0; j < 14; j++) mx = fmaxf(mx, row[j]);
        float s = 0.f;
        #pragma unroll
        for (int j = 0; j < 14; j++) s += expf(row[j] - mx);
        float inv = 1.f / s;
        #pragma unroll
        for (int j = 0; j < 7; j++)
            sAdjP[tid*8 + j] = make_float2(expf(row[2*j] - mx) * inv,
                                           expf(row[2*j+1] - mx) * inv);
        sAdjP[tid*8 + 7] = make_float2(0.f, 0.f);
    }
    __syncthreads();

    const int w    = tid >> 5;
    const int lane = tid & 31;
    const int t    = (lane < 30) ? lane : 0;
    const bool act = (lane < 30);
    const int smpA = blockIdx.x * 16 + w * 2;
    u64* scrU = reinterpret_cast<u64*>(scr[w]);

    {
        const float4* xpA = reinterpret_cast<const float4*>(x + (size_t)smpA * 420);
        const float4* xpB = reinterpret_cast<const float4*>(x + (size_t)(smpA+1) * 420);
        float4* sp = reinterpret_cast<float4*>(scr[w]);
        #pragma unroll
        for (int i = lane; i < 105; i += 32) { sp[i] = xpA[i]; sp[105 + i] = xpB[i]; }
    }
    __syncwarp();
    float xrA[14], xrB[14];
    #pragma unroll
    for (int d = 0; d < 14; d++) {
        xrA[d] = scr[w][t*14 + d];
        xrB[d] = scr[w][420 + t*14 + d];
    }
    __syncwarp();

    u64 xeA[7], xeB[7];
    {
        const u64* sbe2 = reinterpret_cast<const u64*>(sbe);
        #pragma unroll
        for (int op = 0; op < 7; op++) { xeA[op] = sbe2[op]; xeB[op] = sbe2[op]; }
        const u64* we = reinterpret_cast<const u64*>(sWeP);
        #pragma unroll
        for (int ci = 0; ci < 14; ci++) {
            float upA = __shfl_up_sync(FULL, xrA[ci], 1);
            float dnA = __shfl_down_sync(FULL, xrA[ci], 1);
            float upB = __shfl_up_sync(FULL, xrB[ci], 1);
            float dnB = __shfl_down_sync(FULL, xrB[ci], 1);
            float tapA[3] = { (lane > 0) ? upA : 0.f, xrA[ci], (lane < 29) ? dnA : 0.f };
            float tapB[3] = { (lane > 0) ? upB : 0.f, xrB[ci], (lane < 29) ? dnB : 0.f };
            #pragma unroll
            for (int tp = 0; tp < 3; tp++) {
                u64 xa = dup2(tapA[tp]), xb = dup2(tapB[tp]);
                const u64* wr = we + (ci*3 + tp) * 8;
                ulonglong2 w0 = lds2(wr), w1 = lds2(wr+2), w2 = lds2(wr+4);
                u64 w6 = wr[6];
                xeA[0] = fma2u(xa, w0.x, xeA[0]); xeB[0] = fma2u(xb, w0.x, xeB[0]);
                xeA[1] = fma2u(xa, w0.y, xeA[1]); xeB[1] = fma2u(xb, w0.y, xeB[1]);
                xeA[2] = fma2u(xa, w1.x, xeA[2]); xeB[2] = fma2u(xb, w1.x, xeB[2]);
                xeA[3] = fma2u(xa, w1.y, xeA[3]); xeB[3] = fma2u(xb, w1.y, xeB[3]);
                xeA[4] = fma2u(xa, w2.x, xeA[4]); xeB[4] = fma2u(xb, w2.x, xeB[4]);
                xeA[5] = fma2u(xa, w2.y, xeA[5]); xeB[5] = fma2u(xb, w2.y, xeB[5]);
                xeA[6] = fma2u(xa, w6,   xeA[6]); xeB[6] = fma2u(xb, w6,   xeB[6]);
            }
        }
    }

    u64 qA[4], kA_[4], vA[4], qB[4], kB_[4], vB[4];
    {
        const u64* bq2 = reinterpret_cast<const u64*>(sbq);
        const u64* bk2 = reinterpret_cast<const u64*>(sbk);
        const u64* bv2 = reinterpret_cast<const u64*>(sbv);
        #pragma unroll
        for (int hp = 0; hp < 4; hp++) {
            qA[hp]=bq2[hp]; kA_[hp]=bk2[hp]; vA[hp]=bv2[hp];
            qB[hp]=bq2[hp]; kB_[hp]=bk2[hp]; vB[hp]=bv2[hp];
        }
        const u64* wq2 = reinterpret_cast<const u64*>(sWq);
        const u64* wk2 = reinterpret_cast<const u64*>(sWk);
        const u64* wv2 = reinterpret_cast<const u64*>(sWv);
        #pragma unroll
        for (int dp = 0; dp < 7; dp++) {
            float ax, ay, bx, by;
            unpack2(xeA[dp], ax, ay);
            unpack2(xeB[dp], bx, by);
            float sA[2] = { ax, ay }, sB[2] = { bx, by };
            #pragma unroll
            for (int half = 0; half < 2; half++) {
                int d = 2*dp + half;
                u64 xa = dup2(sA[half]), xb = dup2(sB[half]);
                ulonglong2 qa = lds2(wq2 + d*4), qb = lds2(wq2 + d*4 + 2);
                ulonglong2 ka = lds2(wk2 + d*4), kb = lds2(wk2 + d*4 + 2);
                ulonglong2 va = lds2(wv2 + d*4), vb = lds2(wv2 + d*4 + 2);
                qA[0] = fma2u(xa, qa.x, qA[0]); qB[0] = fma2u(xb, qa.x, qB[0]);
                qA[1] = fma2u(xa, qa.y, qA[1]); qB[1] = fma2u(xb, qa.y, qB[1]);
                qA[2] = fma2u(xa, qb.x, qA[2]); qB[2] = fma2u(xb, qb.x, qB[2]);
                qA[3] = fma2u(xa, qb.y, qA[3]); qB[3] = fma2u(xb, qb.y, qB[3]);
                kA_[0] = fma2u(xa, ka.x, kA_[0]); kB_[0] = fma2u(xb, ka.x, kB_[0]);
                kA_[1] = fma2u(xa, ka.y, kA_[1]); kB_[1] = fma2u(xb, ka.y, kB_[1]);
                kA_[2] = fma2u(xa, kb.x, kA_[2]); kB_[2] = fma2u(xb, kb.x, kB_[2]);
                kA_[3] = fma2u(xa, kb.y, kA_[3]); kB_[3] = fma2u(xb, kb.y, kB_[3]);
                vA[0] = fma2u(xa, va.x, vA[0]); vB[0] = fma2u(xb, va.x, vB[0]);
                vA[1] = fma2u(xa, va.y, vA[1]); vB[1] = fma2u(xb, va.y, vB[1]);
                vA[2] = fma2u(xa, vb.x, vA[2]); vB[2] = fma2u(xb, vb.x, vB[2]);
                vA[3] = fma2u(xa, vb.y, vA[3]); vB[3] = fma2u(xb, vb.y, vB[3]);
            }
        }
    }

    u64* qsA = scrU;
    u64* ksA = scrU + 120;
    u64* qsB = scrU + 240;
    u64* ksB = scrU + 360;
    if (act) {
        *reinterpret_cast<ulonglong2*>(qsA + t*4)     = make_ulonglong2(qA[0], qA[1]);
        *reinterpret_cast<ulonglong2*>(qsA + t*4 + 2) = make_ulonglong2(qA[2], qA[3]);
        *reinterpret_cast<ulonglong2*>(ksA + t*4)     = make_ulonglong2(kA_[0], kA_[1]);
        *reinterpret_cast<ulonglong2*>(ksA + t*4 + 2) = make_ulonglong2(kA_[2], kA_[3]);
        *reinterpret_cast<ulonglong2*>(qsB + t*4)     = make_ulonglong2(qB[0], qB[1]);
        *reinterpret_cast<ulonglong2*>(qsB + t*4 + 2) = make_ulonglong2(qB[2], qB[3]);
        *reinterpret_cast<ulonglong2*>(ksB + t*4)     = make_ulonglong2(kB_[0], kB_[1]);
        *reinterpret_cast<ulonglong2*>(ksB + t*4 + 2) = make_ulonglong2(kB_[2], kB_[3]);
    }
    __syncwarp();

    float mvA = corr30(qsA, ksA, t, act);
    float mvB = corr30(qsB, ksB, t, act);
    float w0A, w1A, w2A, w0B, w1B, w2B;
    int dl0A, dl1A, dl2A, dl0B, dl1B, dl2B;
    top3softmax(mvA, lane, w0A, w1A, w2A, dl0A, dl1A, dl2A);
    top3softmax(mvB, lane, w0B, w1B, w2B, dl0B, dl1B, dl2B);

    u64 aggA[4], aggB[4];
    {
        int s0 = t + dl0A; if (s0 >= 30) s0 -= 30;
        int s1 = t + dl1A; if (s1 >= 30) s1 -= 30;
        int s2 = t + dl2A; if (s2 >= 30) s2 -= 30;
        u64 c0 = dup2(w0A), c1 = dup2(w1A), c2 = dup2(w2A);
        #pragma unroll
        for (int hp = 0; hp < 4; hp++) {
            u64 y0 = __shfl_sync(FULL, vA[hp], s0);
            u64 y1 = __shfl_sync(FULL, vA[hp], s1);
            u64 y2 = __shfl_sync(FULL, vA[hp], s2);
            aggA[hp] = fma2u(c0, y0, fma2u(c1, y1, fma2u(c2, y2, 0ULL)));
        }
    }
    {
        int s0 = t + dl0B; if (s0 >= 30) s0 -= 30;
        int s1 = t + dl1B; if (s1 >= 30) s1 -= 30;
        int s2 = t + dl2B; if (s2 >= 30) s2 -= 30;
        u64 c0 = dup2(w0B), c1 = dup2(w1B), c2 = dup2(w2B);
        #pragma unroll
        for (int hp = 0; hp < 4; hp++) {
            u64 y0 = __shfl_sync(FULL, vB[hp], s0);
            u64 y1 = __shfl_sync(FULL, vB[hp], s1);
            u64 y2 = __shfl_sync(FULL, vB[hp], s2);
            aggB[hp] = fma2u(c0, y0, fma2u(c1, y1, fma2u(c2, y2, 0ULL)));
        }
    }

    u64 x1A[7], x1B[7];
    {
        const u64* sbo2 = reinterpret_cast<const u64*>(sbo);
        #pragma unroll
        for (int dp = 0; dp < 7; dp++) {
            x1A[dp] = add2u(xeA[dp], sbo2[dp]);
            x1B[dp] = add2u(xeB[dp], sbo2[dp]);
        }
        const u64* wo = reinterpret_cast<const u64*>(sWoP);
        #pragma unroll
        for (int hp = 0; hp < 4; hp++) {
            float aAx, aAy, aBx, aBy;
            unpack2(aggA[hp], aAx, aAy);
            unpack2(aggB[hp], aBx, aBy);
            float sA[2] = { aAx, aAy }, sB[2] = { aBx, aBy };
            #pragma unroll
            for (int half = 0; half < 2; half++) {
                int h = 2*hp + half;
                u64 aa = dup2(sA[half]), ab = dup2(sB[half]);
                const u64* wr = wo + h*8;
                ulonglong2 w0v = lds2(wr), w1v = lds2(wr+2), w2v = lds2(wr+4);
                u64 w6 = wr[6];
                x1A[0] = fma2u(aa, w0v.x, x1A[0]); x1B[0] = fma2u(ab, w0v.x, x1B[0]);
                x1A[1] = fma2u(aa, w0v.y, x1A[1]); x1B[1] = fma2u(ab, w0v.y, x1B[1]);
                x1A[2] = fma2u(aa, w1v.x, x1A[2]); x1B[2] = fma2u(ab, w1v.x, x1B[2]);
                x1A[3] = fma2u(aa, w1v.y, x1A[3]); x1B[3] = fma2u(ab, w1v.y, x1B[3]);
                x1A[4] = fma2u(aa, w2v.x, x1A[4]); x1B[4] = fma2u(ab, w2v.x, x1B[4]);
                x1A[5] = fma2u(aa, w2v.y, x1A[5]); x1B[5] = fma2u(ab, w2v.y, x1B[5]);
                x1A[6] = fma2u(aa, w6,    x1A[6]); x1B[6] = fma2u(ab, w6,    x1B[6]);
            }
        }
    }

    const float fc0  = (t < 12) ? (float)(12 - t) : 0.f;
    const float fc29 = (t > 17) ? (float)(t - 17) : 0.f;
    const int hi   = (t + 12 > 29) ? 29 : t + 12;
    const int lom1 = t - 13;
    const int loix = (lom1 < 0) ? 0 : lom1;
    u64 xdA[7], xdB[7];
    #pragma unroll
    for (int dp = 0; dp < 7; dp++) {
        float vx, vy;
        unpack2(x1A[dp], vx, vy);
        xdA[dp] = pack2(decomp25(vx, lane, hi, loix, lom1, fc0, fc29),
                        decomp25(vy, lane, hi, loix, lom1, fc0, fc29));
        unpack2(x1B[dp], vx, vy);
        xdB[dp] = pack2(decomp25(vx, lane, hi, loix, lom1, fc0, fc29),
                        decomp25(vy, lane, hi, loix, lom1, fc0, fc29));
    }

    u64 x2A[7], x2B[7];
    {
        u64 yA[7] = {}, yB[7] = {};
        const u64* f1 = reinterpret_cast<const u64*>(sF1P);
        const u64* f2 = reinterpret_cast<const u64*>(sF2P);
        #pragma unroll 5
        for (int f = 0; f < 50; f++) {
            const u64* r1 = f1 + f*8;
            ulonglong2 a0 = lds2(r1), a1 = lds2(r1+2), a2l = lds2(r1+4);
            u64 a6 = r1[6];
            u64 hA = fma2u(xdA[0], a0.x, 0ULL);
            u64 hB = fma2u(xdB[0], a0.x, 0ULL);
            hA = fma2u(xdA[1], a0.y, hA);   hB = fma2u(xdB[1], a0.y, hB);
            hA = fma2u(xdA[2], a1.x, hA);   hB = fma2u(xdB[2], a1.x, hB);
            hA = fma2u(xdA[3], a1.y, hA);   hB = fma2u(xdB[3], a1.y, hB);
            hA = fma2u(xdA[4], a2l.x, hA);  hB = fma2u(xdB[4], a2l.x, hB);
            hA = fma2u(xdA[5], a2l.y, hA);  hB = fma2u(xdB[5], a2l.y, hB);
            hA = fma2u(xdA[6], a6, hA);     hB = fma2u(xdB[6], a6, hB);
            float hx, hy;
            unpack2(hA, hx, hy);
            float hsA = hx + hy;
            unpack2(hB, hx, hy);
            float hsB = hx + hy;
            float gAv = gelu_fast(hsA);
            float gBv = gelu_fast(hsB);
            u64 gA2 = dup2(gAv), gB2 = dup2(gBv);
            const u64* r2 = f2 + f*8;
            ulonglong2 b0 = lds2(r2), b1v = lds2(r2+2), b2v = lds2(r2+4);
            u64 b6 = r2[6];
            yA[0] = fma2u(gA2, b0.x, yA[0]);  yB[0] = fma2u(gB2, b0.x, yB[0]);
            yA[1] = fma2u(gA2, b0.y, yA[1]);  yB[1] = fma2u(gB2, b0.y, yB[1]);
            yA[2] = fma2u(gA2, b1v.x, yA[2]); yB[2] = fma2u(gB2, b1v.x, yB[2]);
            yA[3] = fma2u(gA2, b1v.y, yA[3]); yB[3] = fma2u(gB2, b1v.y, yB[3]);
            yA[4] = fma2u(gA2, b2v.x, yA[4]); yB[4] = fma2u(gB2, b2v.x, yB[4]);
            yA[5] = fma2u(gA2, b2v.y, yA[5]); yB[5] = fma2u(gB2, b2v.y, yB[5]);
            yA[6] = fma2u(gA2, b6, yA[6]);    yB[6] = fma2u(gB2, b6, yB[6]);
        }
        #pragma unroll
        for (int dp = 0; dp < 7; dp++) {
            x2A[dp] = add2u(xdA[dp], yA[dp]);
            x2B[dp] = add2u(xdB[dp], yB[dp]);
        }
    }

    float x3Ax[7], x3Ay[7], x3Bx[7], x3By[7];
    #pragma unroll
    for (int dp = 0; dp < 7; dp++) {
        float vx, vy;
        unpack2(x2A[dp], vx, vy);
        x3Ax[dp] = decomp25(vx, lane, hi, loix, lom1, fc0, fc29);
        x3Ay[dp] = decomp25(vy, lane, hi, loix, lom1, fc0, fc29);
        unpack2(x2B[dp], vx, vy);
        x3Bx[dp] = decomp25(vx, lane, hi, loix, lom1, fc0, fc29);
        x3By[dp] = decomp25(vy, lane, hi, loix, lom1, fc0, fc29);
    }
    {
        float mA = 0.f, mB = 0.f;
        #pragma unroll
        for (int dp = 0; dp < 7; dp++) { mA += x3Ax[dp] + x3Ay[dp]; mB += x3Bx[dp] + x3By[dp]; }
        mA *= (1.f / 14.f); mB *= (1.f / 14.f);
        float vA_ = 0.f, vB_ = 0.f;
        #pragma unroll
        for (int dp = 0; dp < 7; dp++) {
            float dx = x3Ax[dp] - mA, dy = x3Ay[dp] - mA;
            vA_ += dx * dx + dy * dy;
            dx = x3Bx[dp] - mB; dy = x3By[dp] - mB;
            vB_ += dx * dx + dy * dy;
        }
        vA_ *= (1.f / 14.f); vB_ *= (1.f / 14.f);
        float iA = rsqrtf(vA_ + 1e-5f), iB = rsqrtf(vB_ + 1e-5f);
        #pragma unroll
        for (int dp = 0; dp < 7; dp++) {
            float g0 = sg[2*dp], g1 = sg[2*dp+1], b0 = sb[2*dp], b1v = sb[2*dp+1];
            x3Ax[dp] = (x3Ax[dp] - mA) * iA * g0 + b0;
            x3Ay[dp] = (x3Ay[dp] - mA) * iA * g1 + b1v;
            x3Bx[dp] = (x3Bx[dp] - mB) * iB * g0 + b0;
            x3By[dp] = (x3By[dp] - mB) * iB * g1 + b1v;
        }
    }

    __syncwarp();
    u64* x3sA = scrU;
    u64* x3sB = scrU + 240;
    if (act) {
        *reinterpret_cast<ulonglong2*>(x3sA + t*8)     = make_ulonglong2(pack2(x3Ax[0], x3Ay[0]), pack2(x3Ax[1], x3Ay[1]));
        *reinterpret_cast<ulonglong2*>(x3sA + t*8 + 2) = make_ulonglong2(pack2(x3Ax[2], x3Ay[2]), pack2(x3Ax[3], x3Ay[3]));
        *reinterpret_cast<ulonglong2*>(x3sA + t*8 + 4) = make_ulonglong2(pack2(x3Ax[4], x3Ay[4]), pack2(x3Ax[5], x3Ay[5]));
        x3sA[t*8 + 6] = pack2(x3Ax[6], x3Ay[6]);
        *reinterpret_cast<ulonglong2*>(x3sB + t*8)     = make_ulonglong2(pack2(x3Bx[0], x3By[0]), pack2(x3Bx[1], x3By[1]));
        *reinterpret_cast<ulonglong2*>(x3sB + t*8 + 2) = make_ulonglong2(pack2(x3Bx[2], x3By[2]), pack2(x3Bx[3], x3By[3]));
        *reinterpret_cast<ulonglong2*>(x3sB + t*8 + 4) = make_ulonglong2(pack2(x3Bx[4], x3By[4]), pack2(x3Bx[5], x3By[5]));
        x3sB[t*8 + 6] = pack2(x3Bx[6], x3By[6]);
    }
    __syncwarp();
    u64 accA[7], accB[7];
    {
        u64 bias2 = dup2(sbdy[t]);
        #pragma unroll
        for (int dp = 0; dp < 7; dp++) { accA[dp] = bias2; accB[dp] = bias2; }
        #pragma unroll
        for (int m = 0; m < 30; m++) {
            u64 wm2 = dup2(sWdy[m*30 + t]);
            const u64* xa = x3sA + m*8;
            const u64* xb = x3sB + m*8;
            ulonglong2 a0 = lds2(xa), a1 = lds2(xa+2), a2l = lds2(xa+4);
            u64 a6 = xa[6];
            ulonglong2 b0 = lds2(xb), b1v = lds2(xb+2), b2v = lds2(xb+4);
            u64 b6 = xb[6];
            accA[0] = fma2u(a0.x, wm2, accA[0]);  accB[0] = fma2u(b0.x, wm2, accB[0]);
            accA[1] = fma2u(a0.y, wm2, accA[1]);  accB[1] = fma2u(b0.y, wm2, accB[1]);
            accA[2] = fma2u(a1.x, wm2, accA[2]);  accB[2] = fma2u(b1v.x, wm2, accB[2]);
            accA[3] = fma2u(a1.y, wm2, accA[3]);  accB[3] = fma2u(b1v.y, wm2, accB[3]);
            accA[4] = fma2u(a2l.x, wm2, accA[4]); accB[4] = fma2u(b2v.x, wm2, accB[4]);
            accA[5] = fma2u(a2l.y, wm2, accA[5]); accB[5] = fma2u(b2v.y, wm2, accB[5]);
            accA[6] = fma2u(a6,   wm2, accA[6]);  accB[6] = fma2u(b6,   wm2, accB[6]);
        }
    }

    {
        float* foA = g_f + (size_t)smpA * 420;
        float* foB = g_f + (size_t)(smpA+1) * 420;
        const u64* adj = reinterpret_cast<const u64*>(sAdjP);
        #pragma unroll
        for (int i = 0; i < 14; i++) {
            const u64* ar = adj + i*8;
            ulonglong2 a0 = lds2(ar), a1 = lds2(ar+2), a2l = lds2(ar+4);
            u64 a6 = ar[6];
            u64 sA2 = fma2u(a0.x, accA[0], 0ULL);
            u64 sB2 = fma2u(a0.x, accB[0], 0ULL);
            sA2 = fma2u(a0.y, accA[1], sA2);  sB2 = fma2u(a0.y, accB[1], sB2);
            sA2 = fma2u(a1.x, accA[2], sA2);  sB2 = fma2u(a1.x, accB[2], sB2);
            sA2 = fma2u(a1.y, accA[3], sA2);  sB2 = fma2u(a1.y, accB[3], sB2);
            sA2 = fma2u(a2l.x, accA[4], sA2); sB2 = fma2u(a2l.x, accB[4], sB2);
            sA2 = fma2u(a2l.y, accA[5], sA2); sB2 = fma2u(a2l.y, accB[5], sB2);
            sA2 = fma2u(a6, accA[6], sA2);    sB2 = fma2u(a6, accB[6], sB2);
            float ax, ay;
            unpack2(sA2, ax, ay);
            if (act) foA[i*30 + t] = fmaxf(ax + ay, 0.f);
            unpack2(sB2, ax, ay);
            if (act) foB[i*30 + t] = fmaxf(ax + ay, 0.f);
        }
    }
}

// ============================================================================
// Kernel B (3xBF16 m16n8k16): hh = relu(f @ W1 + b1)   (R12/R15 version)
// ============================================================================
__global__ __launch_bounds__(256) void kB(const float* __restrict__ W1,
                                          const float* __restrict__ b1)
{
    __shared__ unsigned Ah[128][20], Al[128][20];   // [m][kp], kp = k/2 (16 used)
    __shared__ unsigned Bh[64][20],  Bl[64][20];    // [n][kp]
    const int tid = threadIdx.x;
    const int lane = tid & 31, wid = tid >> 5;
    const int wm = wid >> 1, wn = wid & 1;
    const int c4 = lane & 3;
    const size_t mbase = (size_t)blockIdx.y * 128;
    const int nbase = blockIdx.x * 64;
    float c[2][4][4] = {};

    for (int k0 = 0; k0 < 448; k0 += 32) {
        {
            int m = tid >> 1, half = tid & 1;
            const float4* gr = reinterpret_cast<const float4*>(g_f + (mbase + m) * 420);
            #pragma unroll
            for (int j = 0; j < 4; j++) {
                int kq = (k0 >> 2) + half*4 + j;
                float4 vv = (kq < 105) ? gr[kq] : make_float4(0.f,0.f,0.f,0.f);
                int kp = half*8 + 2*j;
                unsigned h, l;
                split_bf16x2(vv.x, vv.y, h, l); Ah[m][kp]   = h; Al[m][kp]   = l;
                split_bf16x2(vv.z, vv.w, h, l); Ah[m][kp+1] = h; Al[m][kp+1] = l;
            }
        }
        {
            int kp = tid >> 4;
            int n4 = (tid & 15) * 4;
            int gk0 = k0 + 2*kp, gk1 = gk0 + 1;
            float4 r0 = (gk0 < 420) ? *reinterpret_cast<const float4*>(W1 + (size_t)gk0*256 + nbase + n4)
                                    : make_float4(0.f,0.f,0.f,0.f);
            float4 r1 = (gk1 < 420) ? *reinterpret_cast<const float4*>(W1 + (size_t)gk1*256 + nbase + n4)
                                    : make_float4(0.f,0.f,0.f,0.f);
            unsigned h, l;
            split_bf16x2(r0.x, r1.x, h, l); Bh[n4+0][kp] = h; Bl[n4+0][kp] = l;
            split_bf16x2(r0.y, r1.y, h, l); Bh[n4+1][kp] = h; Bl[n4+1][kp] = l;
            split_bf16x2(r0.z, r1.z, h, l); Bh[n4+2][kp] = h; Bl[n4+2][kp] = l;
            split_bf16x2(r0.w, r1.w, h, l); Bh[n4+3][kp] = h; Bl[n4+3][kp] = l;
        }
        __syncthreads();
        #pragma unroll
        for (int ks = 0; ks < 2; ks++) {
            int kb = ks * 8;
            unsigned ah[2][4], al[2][4], bh[4][2], bl[4][2];
            #pragma unroll
            for (int mt = 0; mt < 2; mt++) {
                int r = wm*32 + mt*16 + (lane>>2);
                ah[mt][0] = Ah[r  ][kb + c4];     al[mt][0] = Al[r  ][kb + c4];
                ah[mt][1] = Ah[r+8][kb + c4];     al[mt][1] = Al[r+8][kb + c4];
                ah[mt][2] = Ah[r  ][kb + c4 + 4]; al[mt][2] = Al[r  ][kb + c4 + 4];
                ah[mt][3] = Ah[r+8][kb + c4 + 4]; al[mt][3] = Al[r+8][kb + c4 + 4];
            }
            #pragma unroll
            for (int nt = 0; nt < 4; nt++) {
                int nn = wn*32 + nt*8 + (lane>>2);
                bh[nt][0] = Bh[nn][kb + c4];     bl[nt][0] = Bl[nn][kb + c4];
                bh[nt][1] = Bh[nn][kb + c4 + 4]; bl[nt][1] = Bl[nn][kb + c4 + 4];
            }
            #pragma unroll
            for (int mt = 0; mt < 2; mt++)
                #pragma unroll
                for (int nt = 0; nt < 4; nt++) {
                    mma_bf16(c[mt][nt], ah[mt], bh[nt]);
                    mma_bf16(c[mt][nt], ah[mt], bl[nt]);
                    mma_bf16(c[mt][nt], al[mt], bh[nt]);
                }
        }
        __syncthreads();
    }
    #pragma unroll
    for (int mt = 0; mt < 2; mt++) {
        int r0 = wm*32 + mt*16 + (lane>>2);
        #pragma unroll
        for (int nt = 0; nt < 4; nt++) {
            int cl = nbase + wn*32 + nt*8 + 2*(lane&3);
            float b0 = b1[cl], b1v = b1[cl+1];
            float2 lo = make_float2(fmaxf(c[mt][nt][0] + b0, 0.f), fmaxf(c[mt][nt][1] + b1v, 0.f));
            float2 hi = make_float2(fmaxf(c[mt][nt][2] + b0, 0.f), fmaxf(c[mt][nt][3] + b1v, 0.f));
            *reinterpret_cast<float2*>(g_hh + (mbase + r0    ) * 256 + cl) = lo;
            *reinterpret_cast<float2*>(g_hh + (mbase + r0 + 8) * 256 + cl) = hi;
        }
    }
}

// ============================================================================
// Kernel C (3xBF16, fused LN head):
// hr = [hh|f]@[W2;Wres]+b2+bres, out = LN64(hr)@W3+b3. K=704(pad), BK=32.
// ============================================================================
__global__ __launch_bounds__(256) void kC(const float* __restrict__ W2,
                                          const float* __restrict__ b2,
                                          const float* __restrict__ Wres,
                                          const float* __restrict__ bres,
                                          const float* __restrict__ g_ln,
                                          const float* __restrict__ b_ln,
                                          const float* __restrict__ W3,
                                          const float* __restrict__ b3,
                                          float* __restrict__ out)
{
    __shared__ unsigned Ah[128][20], Al[128][20];
    __shared__ unsigned Bh[64][20],  Bl[64][20];
    __shared__ float sbb[64];
    __shared__ float sgw[64];
    __shared__ float sp[128][2][3];
    __shared__ float sconst[2];
    const int tid = threadIdx.x;
    const int lane = tid & 31, wid = tid >> 5;
    const int wm = wid >> 1, wn = wid & 1;
    const int c4 = lane & 3;
    const size_t mbase = (size_t)blockIdx.x * 128;
    float c[2][4][4] = {};

    if (tid < 64) {
        sbb[tid] = b2[tid] + bres[tid];
        sgw[tid] = g_ln[tid] * W3[tid];
    }

    for (int k0 = 0; k0 < 704; k0 += 32) {
        {
            int m = tid >> 1, half = tid & 1;
            const float* hrow = g_hh + (mbase + m) * 256;
            const float* frow = g_f  + (mbase + m) * 420;
            #pragma unroll
            for (int j = 0; j < 4; j++) {
                int gk = k0 + half*16 + 4*j;
                float4 vv = make_float4(0.f,0.f,0.f,0.f);
                if (gk < 256) vv = *reinterpret_cast<const float4*>(hrow + gk);
                else { int kf = gk - 256; if (kf < 420) vv = *reinterpret_cast<const float4*>(frow + kf); }
                int kp = half*8 + 2*j;
                unsigned h, l;
                split_bf16x2(vv.x, vv.y, h, l); Ah[m][kp]   = h; Al[m][kp]   = l;
                split_bf16x2(vv.z, vv.w, h, l); Ah[m][kp+1] = h; Al[m][kp+1] = l;
            }
        }
        {
            int kp = tid >> 4;
            int n4 = (tid & 15) * 4;
            int gk0 = k0 + 2*kp, gk1 = gk0 + 1;
            float4 r0 = make_float4(0.f,0.f,0.f,0.f);
            float4 r1 = make_float4(0.f,0.f,0.f,0.f);
            if (gk0 < 256) r0 = *reinterpret_cast<const float4*>(W2 + (size_t)gk0*64 + n4);
            else { int kf = gk0 - 256; if (kf < 420) r0 = *reinterpret_cast<const float4*>(Wres + (size_t)kf*64 + n4); }
            if (gk1 < 256) r1 = *reinterpret_cast<const float4*>(W2 + (size_t)gk1*64 + n4);
            else { int kf = gk1 - 256; if (kf < 420) r1 = *reinterpret_cast<const float4*>(Wres + (size_t)kf*64 + n4); }
            unsigned h, l;
            split_bf16x2(r0.x, r1.x, h, l); Bh[n4+0][kp] = h; Bl[n4+0][kp] = l;
            split_bf16x2(r0.y, r1.y, h, l); Bh[n4+1][kp] = h; Bl[n4+1][kp] = l;
            split_bf16x2(r0.z, r1.z, h, l); Bh[n4+2][kp] = h; Bl[n4+2][kp] = l;
            split_bf16x2(r0.w, r1.w, h, l); Bh[n4+3][kp] = h; Bl[n4+3][kp] = l;
        }
        __syncthreads();
        #pragma unroll
        for (int ks = 0; ks < 2; ks++) {
            int kb = ks * 8;
            unsigned ah[2][4], al[2][4], bh[4][2], bl[4][2];
            #pragma unroll
            for (int mt = 0; mt < 2; mt++) {
                int r = wm*32 + mt*16 + (lane>>2);
                ah[mt][0] = Ah[r  ][kb + c4];     al[mt][0] = Al[r  ][kb + c4];
                ah[mt][1] = Ah[r+8][kb + c4];     al[mt][1] = Al[r+8][kb + c4];
                ah[mt][2] = Ah[r  ][kb + c4 + 4]; al[mt][2] = Al[r  ][kb + c4 + 4];
                ah[mt][3] = Ah[r+8][kb + c4 + 4]; al[mt][3] = Al[r+8][kb + c4 + 4];
            }
            #pragma unroll
            for (int nt = 0; nt < 4; nt++) {
                int nn = wn*32 + nt*8 + (lane>>2);
                bh[nt][0] = Bh[nn][kb + c4];     bl[nt][0] = Bl[nn][kb + c4];
                bh[nt][1] = Bh[nn][kb + c4 + 4]; bl[nt][1] = Bl[nn][kb + c4 + 4];
            }
            #pragma unroll
            for (int mt = 0; mt < 2; mt++)
                #pragma unroll
                for (int nt = 0; nt < 4; nt++) {
                    mma_bf16(c[mt][nt], ah[mt], bh[nt]);
                    mma_bf16(c[mt][nt], ah[mt], bl[nt]);
                    mma_bf16(c[mt][nt], al[mt], bh[nt]);
                }
        }
        __syncthreads();
    }

    // ---- fused epilogue: partial LN sums per (row, wn-half) ----
    #pragma unroll
    for (int mt = 0; mt < 2; mt++) {
        #pragma unroll
        for (int rb = 0; rb < 2; rb++) {
            float sv = 0.f, sq = 0.f, sgd = 0.f;
            #pragma unroll
            for (int nt = 0; nt < 4; nt++) {
                int cl = wn*32 + nt*8 + 2*(lane&3);
                float v0 = c[mt][nt][2*rb]     + sbb[cl];
                float v1 = c[mt][nt][2*rb + 1] + sbb[cl+1];
                sv += v0 + v1;
                sq += v0*v0 + v1*v1;
                sgd += v0*sgw[cl] + v1*sgw[cl+1];
            }
            sv += __shfl_xor_sync(FULL, sv, 1);
            sq += __shfl_xor_sync(FULL, sq, 1);
            sgd += __shfl_xor_sync(FULL, sgd, 1);
            sv += __shfl_xor_sync(FULL, sv, 2);
            sq += __shfl_xor_sync(FULL, sq, 2);
            sgd += __shfl_xor_sync(FULL, sgd, 2);
            if ((lane & 3) == 0) {
                int row = wm*32 + mt*16 + rb*8 + (lane>>2);
                sp[row][wn][0] = sv;
                sp[row][wn][1] = sq;
                sp[row][wn][2] = sgd;
            }
        }
    }
    if (tid == 0) {
        float G = 0.f, cb = b3[0];
        for (int d = 0; d < 64; d++) { G += sgw[d]; cb += b_ln[d] * W3[d]; }
        sconst[0] = G; sconst[1] = cb;
    }
    __syncthreads();
    if (tid < 128) {
        int row = tid;
        float sv  = sp[row][0][0] + sp[row][1][0];
        float sq  = sp[row][0][1] + sp[row][1][1];
        float sgd = sp[row][0][2] + sp[row][1][2];
        float m = sv * (1.f / 64.f);
        float var = sq * (1.f / 64.f) - m * m;
        float invs = rsqrtf(var + 1e-5f);
        out[mbase + row] = invs * (sgd - m * sconst[0]) + sconst[1];
    }
}

// ============================================================================
extern "C" void kernel_launch(void* const* d_in, const int* in_sizes, int n_in,
                              void* d_out, int out_size)
{
    (void)in_sizes; (void)n_in; (void)out_size;
    const float* x = (const float*)d_in[0];

    kA<<<BATCH / 16, 256>>>(x,
        (const float*)d_in[1],  (const float*)d_in[2],
        (const float*)d_in[3],  (const float*)d_in[4],
        (const float*)d_in[5],  (const float*)d_in[6],
        (const float*)d_in[7],  (const float*)d_in[8],
        (const float*)d_in[9],  (const float*)d_in[10],
        (const float*)d_in[11], (const float*)d_in[12],
        (const float*)d_in[13], (const float*)d_in[14],
        (const float*)d_in[15], (const float*)d_in[16],
        (const float*)d_in[17]);

    kB<<<dim3(4, BATCH / 128), 256>>>((const float*)d_in[18], (const float*)d_in[19]);

    kC<<<BATCH / 128, 256>>>((const float*)d_in[20], (const float*)d_in[21],
                             (const float*)d_in[22], (const float*)d_in[23],
                             (const float*)d_in[24], (const float*)d_in[25],
                             (const float*)d_in[26], (const float*)d_in[27],
                             (float*)d_out);
}

// round 17
// speedup vs baseline: 1.2086x; 1.0366x over previous
#include <cuda_runtime.h>
#include <math.h>

#define BATCH 65536
#define FULL 0xffffffffu

typedef unsigned long long u64;

// -------- device scratch (allocation-free rule: __device__ globals) --------
__device__ float g_f [(size_t)BATCH * 420];   // DyConv output
__device__ float g_hh[(size_t)BATCH * 256];   // relu(f@W1+b1)

// ---------------- packed f32x2 ops on b64 registers ----------------
__device__ __forceinline__ u64 pack2(float x, float y) {
    u64 r; asm("mov.b64 %0, {%1, %2};" : "=l"(r) : "f"(x), "f"(y)); return r;
}
__device__ __forceinline__ u64 dup2(float s) { return pack2(s, s); }
__device__ __forceinline__ void unpack2(u64 v, float& x, float& y) {
    asm("mov.b64 {%0, %1}, %2;" : "=f"(x), "=f"(y) : "l"(v));
}
__device__ __forceinline__ u64 fma2u(u64 a, u64 b, u64 c) {
    u64 d; asm("fma.rn.f32x2 %0, %1, %2, %3;" : "=l"(d) : "l"(a), "l"(b), "l"(c)); return d;
}
__device__ __forceinline__ u64 add2u(u64 a, u64 b) {
    u64 d; asm("add.rn.f32x2 %0, %1, %2;" : "=l"(d) : "l"(a), "l"(b)); return d;
}
__device__ __forceinline__ ulonglong2 lds2(const u64* p) {
    return *reinterpret_cast<const ulonglong2*>(p);
}

// ---- fast GELU (tanh form, MUFU.TANH) ----
__device__ __forceinline__ float gelu_fast(float x) {
    float u = x * (0.7978845608028654f + 0.0356774081363001f * x * x);
    float tv;
    asm("tanh.approx.f32 %0, %1;" : "=f"(tv) : "f"(u));
    return 0.5f * x * (1.f + tv);
}

// ---------------- split-bf16 helpers (3xBF16 compensated GEMM) -------------
__device__ __forceinline__ void split_bf16x2(float e0, float e1,
                                             unsigned& hi, unsigned& lo) {
    asm("cvt.rn.bf16x2.f32 %0, %1, %2;" : "=r"(hi) : "f"(e1), "f"(e0));
    float h0 = __uint_as_float(hi << 16);
    float h1 = __uint_as_float(hi & 0xffff0000u);
    float r0 = e0 - h0, r1 = e1 - h1;
    asm("cvt.rn.bf16x2.f32 %0, %1, %2;" : "=r"(lo) : "f"(r1), "f"(r0));
}
__device__ __forceinline__ void mma_bf16(float* c, const unsigned* a, const unsigned* b) {
    asm volatile(
        "mma.sync.aligned.m16n8k16.row.col.f32.bf16.bf16.f32 "
        "{%0,%1,%2,%3},{%4,%5,%6,%7},{%8,%9},{%0,%1,%2,%3};"
        : "+f"(c[0]), "+f"(c[1]), "+f"(c[2]), "+f"(c[3])
        : "r"(a[0]), "r"(a[1]), "r"(a[2]), "r"(a[3]), "r"(b[0]), "r"(b[1]));
}

// ---- shuffle-scan series_decomp helper (replicate-pad MA-25) ----
__device__ __forceinline__ float decomp25(float val, int lane, int hi, int loix,
                                          int lom1, float fc0, float fc29) {
    float cs = val;
    #pragma unroll
    for (int off = 1; off < 32; off <<= 1) {
        float o = __shfl_up_sync(FULL, cs, off);
        if (lane >= off) cs += o;
    }
    float cshi = __shfl_sync(FULL, cs, hi);
    float cslo = __shfl_sync(FULL, cs, loix);
    float ssum = cshi - ((lom1 >= 0) ? cslo : 0.f);
    float x0  = __shfl_sync(FULL, val, 0);
    float x29 = __shfl_sync(FULL, val, 29);
    return val - (ssum + fc0 * x0 + fc29 * x29) * (1.f / 25.f);
}

// ---- warp-parallel top-3 with first-index tie-break, then softmax ----
__device__ __forceinline__ void top3softmax(float mv, int lane,
                                            float& w0, float& w1, float& w2,
                                            int& dl0, int& dl1, int& dl2) {
    float wv0, wv1, wv2;
    float mrun = mv;
    #pragma unroll
    for (int p = 0; p < 3; p++) {
        float bv = mrun; int bi = lane;
        #pragma unroll
        for (int off = 16; off; off >>= 1) {
            float vo = __shfl_xor_sync(FULL, bv, off);
            int   io = __shfl_xor_sync(FULL, bi, off);
            if (vo > bv || (vo == bv && io < bi)) { bv = vo; bi = io; }
        }
        if (p == 0) { wv0 = bv; dl0 = bi; }
        else if (p == 1) { wv1 = bv; dl1 = bi; }
        else { wv2 = bv; dl2 = bi; }
        if (lane == bi) mrun = -1e30f;
    }
    float e1 = expf(wv1 - wv0);
    float e2 = expf(wv2 - wv0);
    float inv = 1.f / (1.f + e1 + e2);
    w0 = inv; w1 = e1 * inv; w2 = e2 * inv;
}

// ---- circular correlation for one sample (lane = tau) ----
__device__ __forceinline__ float corr30(const u64* qsU, const u64* ksU,
                                        int t, bool act) {
    u64 acc2[4] = {};
    #pragma unroll
    for (int tq = 0; tq < 30; tq++) {
        int src = tq - t; if (src < 0) src += 30;
        ulonglong2 qa = lds2(qsU + tq*4), qb = lds2(qsU + tq*4 + 2);
        ulonglong2 ka = lds2(ksU + src*4), kb = lds2(ksU + src*4 + 2);
        acc2[0] = fma2u(qa.x, ka.x, acc2[0]);
        acc2[1] = fma2u(qa.y, ka.y, acc2[1]);
        acc2[2] = fma2u(qb.x, kb.x, acc2[2]);
        acc2[3] = fma2u(qb.y, kb.y, acc2[3]);
    }
    u64 s2 = add2u(add2u(acc2[0], acc2[1]), add2u(acc2[2], acc2[3]));
    float sx, sy; unpack2(s2, sx, sy);
    return act ? (sx + sy) * 0.125f : -1e30f;
}

// ============================================================================
// Kernel A: register-resident per-sample pipeline, FFMA2, 2 samples/warp.
// (exact R16 version)
// ============================================================================
__global__ __launch_bounds__(256, 2) void kA(
    const float* __restrict__ x,
    const float* __restrict__ W_emb, const float* __restrict__ b_emb,
    const float* __restrict__ Wq, const float* __restrict__ bq,
    const float* __restrict__ Wk, const float* __restrict__ bk,
    const float* __restrict__ Wv, const float* __restrict__ bv,
    const float* __restrict__ Wo, const float* __restrict__ bo,
    const float* __restrict__ Wff1, const float* __restrict__ Wff2,
    const float* __restrict__ gnorm, const float* __restrict__ bnorm,
    const float* __restrict__ Wdy, const float* __restrict__ bdy,
    const float* __restrict__ channels)
{
    __shared__ __align__(16) float2 sWeP[336];
    __shared__ __align__(16) float  sbe[14];
    __shared__ __align__(16) float  sWq[112], sWk[112], sWv[112];
    __shared__ __align__(16) float  sbq[8], sbk[8], sbv[8];
    __shared__ __align__(16) float2 sWoP[64];
    __shared__ __align__(16) float  sbo[14];
    __shared__ __align__(16) float2 sF1P[400];
    __shared__ __align__(16) float2 sF2P[400];
    __shared__ __align__(16) float  sg[14], sb[14];
    __shared__ __align__(16) float  sWdy[900], sbdy[32];
    __shared__ __align__(16) float2 sAdjP[112];
    __shared__ __align__(16) float  scr[8][960];

    const int tid = threadIdx.x;
    for (int i = tid; i < 336; i += 256) {
        int ct = i >> 3, op = i & 7;
        float a = 0.f, b = 0.f;
        if (op < 7) { a = W_emb[(2*op)*42 + ct]; b = W_emb[(2*op+1)*42 + ct]; }
        sWeP[i] = make_float2(a, b);
    }
    for (int i = tid; i < 112; i += 256) { sWq[i]=Wq[i]; sWk[i]=Wk[i]; sWv[i]=Wv[i]; }
    for (int i = tid; i < 64; i += 256) {
        int h = i >> 3, dp = i & 7;
        float a = 0.f, b = 0.f;
        if (dp < 7) { a = Wo[h*14 + 2*dp]; b = Wo[h*14 + 2*dp + 1]; }
        sWoP[i] = make_float2(a, b);
    }
    for (int i = tid; i < 400; i += 256) {
        int f = i >> 3, dp = i & 7;
        float a1 = 0.f, b1v = 0.f, a2 = 0.f, b2v = 0.f;
        if (dp < 7) {
            a1 = Wff1[(2*dp)*50 + f]; b1v = Wff1[(2*dp+1)*50 + f];
            a2 = Wff2[f*14 + 2*dp];   b2v = Wff2[f*14 + 2*dp + 1];
        }
        sF1P[i] = make_float2(a1, b1v);
        sF2P[i] = make_float2(a2, b2v);
    }
    for (int i = tid; i < 900; i += 256) sWdy[i] = Wdy[i];
    if (tid < 30) sbdy[tid] = bdy[tid];
    if (tid < 14) { sbe[tid]=b_emb[tid]; sbo[tid]=bo[tid]; sg[tid]=gnorm[tid]; sb[tid]=bnorm[tid]; }
    if (tid < 8)  { sbq[tid]=bq[tid]; sbk[tid]=bk[tid]; sbv[tid]=bv[tid]; }
    if (tid < 14) {
        const float* row = channels + tid * 14;
        float mx = -1e30f;
        #pragma unroll
        for (int j = 0; j < 14; j++) mx = fmaxf(mx, row[j]);
        float s = 0.f;
        #pragma unroll
        for (int j = 0; j < 14; j++) s += expf(row[j] - mx);
        float inv = 1.f / s;
        #pragma unroll
        for (int j = 0; j < 7; j++)
            sAdjP[tid*8 + j] = make_float2(expf(row[2*j] - mx) * inv,
                                           expf(row[2*j+1] - mx) * inv);
        sAdjP[tid*8 + 7] = make_float2(0.f, 0.f);
    }
    __syncthreads();

    const int w    = tid >> 5;
    const int lane = tid & 31;
    const int t    = (lane < 30) ? lane : 0;
    const bool act = (lane < 30);
    const int smpA = blockIdx.x * 16 + w * 2;
    u64* scrU = reinterpret_cast<u64*>(scr[w]);

    {
        const float4* xpA = reinterpret_cast<const float4*>(x + (size_t)smpA * 420);
        const float4* xpB = reinterpret_cast<const float4*>(x + (size_t)(smpA+1) * 420);
        float4* sp = reinterpret_cast<float4*>(scr[w]);
        #pragma unroll
        for (int i = lane; i < 105; i += 32) { sp[i] = xpA[i]; sp[105 + i] = xpB[i]; }
    }
    __syncwarp();
    float xrA[14], xrB[14];
    #pragma unroll
    for (int d = 0; d < 14; d++) {
        xrA[d] = scr[w][t*14 + d];
        xrB[d] = scr[w][420 + t*14 + d];
    }
    __syncwarp();

    u64 xeA[7], xeB[7];
    {
        const u64* sbe2 = reinterpret_cast<const u64*>(sbe);
        #pragma unroll
        for (int op = 0; op < 7; op++) { xeA[op] = sbe2[op]; xeB[op] = sbe2[op]; }
        const u64* we = reinterpret_cast<const u64*>(sWeP);
        #pragma unroll
        for (int ci = 0; ci < 14; ci++) {
            float upA = __shfl_up_sync(FULL, xrA[ci], 1);
            float dnA = __shfl_down_sync(FULL, xrA[ci], 1);
            float upB = __shfl_up_sync(FULL, xrB[ci], 1);
            float dnB = __shfl_down_sync(FULL, xrB[ci], 1);
            float tapA[3] = { (lane > 0) ? upA : 0.f, xrA[ci], (lane < 29) ? dnA : 0.f };
            float tapB[3] = { (lane > 0) ? upB : 0.f, xrB[ci], (lane < 29) ? dnB : 0.f };
            #pragma unroll
            for (int tp = 0; tp < 3; tp++) {
                u64 xa = dup2(tapA[tp]), xb = dup2(tapB[tp]);
                const u64* wr = we + (ci*3 + tp) * 8;
                ulonglong2 w0 = lds2(wr), w1 = lds2(wr+2), w2 = lds2(wr+4);
                u64 w6 = wr[6];
                xeA[0] = fma2u(xa, w0.x, xeA[0]); xeB[0] = fma2u(xb, w0.x, xeB[0]);
                xeA[1] = fma2u(xa, w0.y, xeA[1]); xeB[1] = fma2u(xb, w0.y, xeB[1]);
                xeA[2] = fma2u(xa, w1.x, xeA[2]); xeB[2] = fma2u(xb, w1.x, xeB[2]);
                xeA[3] = fma2u(xa, w1.y, xeA[3]); xeB[3] = fma2u(xb, w1.y, xeB[3]);
                xeA[4] = fma2u(xa, w2.x, xeA[4]); xeB[4] = fma2u(xb, w2.x, xeB[4]);
                xeA[5] = fma2u(xa, w2.y, xeA[5]); xeB[5] = fma2u(xb, w2.y, xeB[5]);
                xeA[6] = fma2u(xa, w6,   xeA[6]); xeB[6] = fma2u(xb, w6,   xeB[6]);
            }
        }
    }

    u64 qA[4], kA_[4], vA[4], qB[4], kB_[4], vB[4];
    {
        const u64* bq2 = reinterpret_cast<const u64*>(sbq);
        const u64* bk2 = reinterpret_cast<const u64*>(sbk);
        const u64* bv2 = reinterpret_cast<const u64*>(sbv);
        #pragma unroll
        for (int hp = 0; hp < 4; hp++) {
            qA[hp]=bq2[hp]; kA_[hp]=bk2[hp]; vA[hp]=bv2[hp];
            qB[hp]=bq2[hp]; kB_[hp]=bk2[hp]; vB[hp]=bv2[hp];
        }
        const u64* wq2 = reinterpret_cast<const u64*>(sWq);
        const u64* wk2 = reinterpret_cast<const u64*>(sWk);
        const u64* wv2 = reinterpret_cast<const u64*>(sWv);
        #pragma unroll
        for (int dp = 0; dp < 7; dp++) {
            float ax, ay, bx, by;
            unpack2(xeA[dp], ax, ay);
            unpack2(xeB[dp], bx, by);
            float sA[2] = { ax, ay }, sB[2] = { bx, by };
            #pragma unroll
            for (int half = 0; half < 2; half++) {
                int d = 2*dp + half;
                u64 xa = dup2(sA[half]), xb = dup2(sB[half]);
                ulonglong2 qa = lds2(wq2 + d*4), qb = lds2(wq2 + d*4 + 2);
                ulonglong2 ka = lds2(wk2 + d*4), kb = lds2(wk2 + d*4 + 2);
                ulonglong2 va = lds2(wv2 + d*4), vb = lds2(wv2 + d*4 + 2);
                qA[0] = fma2u(xa, qa.x, qA[0]); qB[0] = fma2u(xb, qa.x, qB[0]);
                qA[1] = fma2u(xa, qa.y, qA[1]); qB[1] = fma2u(xb, qa.y, qB[1]);
                qA[2] = fma2u(xa, qb.x, qA[2]); qB[2] = fma2u(xb, qb.x, qB[2]);
                qA[3] = fma2u(xa, qb.y, qA[3]); qB[3] = fma2u(xb, qb.y, qB[3]);
                kA_[0] = fma2u(xa, ka.x, kA_[0]); kB_[0] = fma2u(xb, ka.x, kB_[0]);
                kA_[1] = fma2u(xa, ka.y, kA_[1]); kB_[1] = fma2u(xb, ka.y, kB_[1]);
                kA_[2] = fma2u(xa, kb.x, kA_[2]); kB_[2] = fma2u(xb, kb.x, kB_[2]);
                kA_[3] = fma2u(xa, kb.y, kA_[3]); kB_[3] = fma2u(xb, kb.y, kB_[3]);
                vA[0] = fma2u(xa, va.x, vA[0]); vB[0] = fma2u(xb, va.x, vB[0]);
                vA[1] = fma2u(xa, va.y, vA[1]); vB[1] = fma2u(xb, va.y, vB[1]);
                vA[2] = fma2u(xa, vb.x, vA[2]); vB[2] = fma2u(xb, vb.x, vB[2]);
                vA[3] = fma2u(xa, vb.y, vA[3]); vB[3] = fma2u(xb, vb.y, vB[3]);
            }
        }
    }

    u64* qsA = scrU;
    u64* ksA = scrU + 120;
    u64* qsB = scrU + 240;
    u64* ksB = scrU + 360;
    if (act) {
        *reinterpret_cast<ulonglong2*>(qsA + t*4)     = make_ulonglong2(qA[0], qA[1]);
        *reinterpret_cast<ulonglong2*>(qsA + t*4 + 2) = make_ulonglong2(qA[2], qA[3]);
        *reinterpret_cast<ulonglong2*>(ksA + t*4)     = make_ulonglong2(kA_[0], kA_[1]);
        *reinterpret_cast<ulonglong2*>(ksA + t*4 + 2) = make_ulonglong2(kA_[2], kA_[3]);
        *reinterpret_cast<ulonglong2*>(qsB + t*4)     = make_ulonglong2(qB[0], qB[1]);
        *reinterpret_cast<ulonglong2*>(qsB + t*4 + 2) = make_ulonglong2(qB[2], qB[3]);
        *reinterpret_cast<ulonglong2*>(ksB + t*4)     = make_ulonglong2(kB_[0], kB_[1]);
        *reinterpret_cast<ulonglong2*>(ksB + t*4 + 2) = make_ulonglong2(kB_[2], kB_[3]);
    }
    __syncwarp();

    float mvA = corr30(qsA, ksA, t, act);
    float mvB = corr30(qsB, ksB, t, act);
    float w0A, w1A, w2A, w0B, w1B, w2B;
    int dl0A, dl1A, dl2A, dl0B, dl1B, dl2B;
    top3softmax(mvA, lane, w0A, w1A, w2A, dl0A, dl1A, dl2A);
    top3softmax(mvB, lane, w0B, w1B, w2B, dl0B, dl1B, dl2B);

    u64 aggA[4], aggB[4];
    {
        int s0 = t + dl0A; if (s0 >= 30) s0 -= 30;
        int s1 = t + dl1A; if (s1 >= 30) s1 -= 30;
        int s2 = t + dl2A; if (s2 >= 30) s2 -= 30;
        u64 c0 = dup2(w0A), c1 = dup2(w1A), c2 = dup2(w2A);
        #pragma unroll
        for (int hp = 0; hp < 4; hp++) {
            u64 y0 = __shfl_sync(FULL, vA[hp], s0);
            u64 y1 = __shfl_sync(FULL, vA[hp], s1);
            u64 y2 = __shfl_sync(FULL, vA[hp], s2);
            aggA[hp] = fma2u(c0, y0, fma2u(c1, y1, fma2u(c2, y2, 0ULL)));
        }
    }
    {
        int s0 = t + dl0B; if (s0 >= 30) s0 -= 30;
        int s1 = t + dl1B; if (s1 >= 30) s1 -= 30;
        int s2 = t + dl2B; if (s2 >= 30) s2 -= 30;
        u64 c0 = dup2(w0B), c1 = dup2(w1B), c2 = dup2(w2B);
        #pragma unroll
        for (int hp = 0; hp < 4; hp++) {
            u64 y0 = __shfl_sync(FULL, vB[hp], s0);
            u64 y1 = __shfl_sync(FULL, vB[hp], s1);
            u64 y2 = __shfl_sync(FULL, vB[hp], s2);
            aggB[hp] = fma2u(c0, y0, fma2u(c1, y1, fma2u(c2, y2, 0ULL)));
        }
    }

    u64 x1A[7], x1B[7];
    {
        const u64* sbo2 = reinterpret_cast<const u64*>(sbo);
        #pragma unroll
        for (int dp = 0; dp < 7; dp++) {
            x1A[dp] = add2u(xeA[dp], sbo2[dp]);
            x1B[dp] = add2u(xeB[dp], sbo2[dp]);
        }
        const u64* wo = reinterpret_cast<const u64*>(sWoP);
        #pragma unroll
        for (int hp = 0; hp < 4; hp++) {
            float aAx, aAy, aBx, aBy;
            unpack2(aggA[hp], aAx, aAy);
            unpack2(aggB[hp], aBx, aBy);
            float sA[2] = { aAx, aAy }, sB[2] = { aBx, aBy };
            #pragma unroll
            for (int half = 0; half < 2; half++) {
                int h = 2*hp + half;
                u64 aa = dup2(sA[half]), ab = dup2(sB[half]);
                const u64* wr = wo + h*8;
                ulonglong2 w0v = lds2(wr), w1v = lds2(wr+2), w2v = lds2(wr+4);
                u64 w6 = wr[6];
                x1A[0] = fma2u(aa, w0v.x, x1A[0]); x1B[0] = fma2u(ab, w0v.x, x1B[0]);
                x1A[1] = fma2u(aa, w0v.y, x1A[1]); x1B[1] = fma2u(ab, w0v.y, x1B[1]);
                x1A[2] = fma2u(aa, w1v.x, x1A[2]); x1B[2] = fma2u(ab, w1v.x, x1B[2]);
                x1A[3] = fma2u(aa, w1v.y, x1A[3]); x1B[3] = fma2u(ab, w1v.y, x1B[3]);
                x1A[4] = fma2u(aa, w2v.x, x1A[4]); x1B[4] = fma2u(ab, w2v.x, x1B[4]);
                x1A[5] = fma2u(aa, w2v.y, x1A[5]); x1B[5] = fma2u(ab, w2v.y, x1B[5]);
                x1A[6] = fma2u(aa, w6,    x1A[6]); x1B[6] = fma2u(ab, w6,    x1B[6]);
            }
        }
    }

    const float fc0  = (t < 12) ? (float)(12 - t) : 0.f;
    const float fc29 = (t > 17) ? (float)(t - 17) : 0.f;
    const int hi   = (t + 12 > 29) ? 29 : t + 12;
    const int lom1 = t - 13;
    const int loix = (lom1 < 0) ? 0 : lom1;
    u64 xdA[7], xdB[7];
    #pragma unroll
    for (int dp = 0; dp < 7; dp++) {
        float vx, vy;
        unpack2(x1A[dp], vx, vy);
        xdA[dp] = pack2(decomp25(vx, lane, hi, loix, lom1, fc0, fc29),
                        decomp25(vy, lane, hi, loix, lom1, fc0, fc29));
        unpack2(x1B[dp], vx, vy);
        xdB[dp] = pack2(decomp25(vx, lane, hi, loix, lom1, fc0, fc29),
                        decomp25(vy, lane, hi, loix, lom1, fc0, fc29));
    }

    u64 x2A[7], x2B[7];
    {
        u64 yA[7] = {}, yB[7] = {};
        const u64* f1 = reinterpret_cast<const u64*>(sF1P);
        const u64* f2 = reinterpret_cast<const u64*>(sF2P);
        #pragma unroll 5
        for (int f = 0; f < 50; f++) {
            const u64* r1 = f1 + f*8;
            ulonglong2 a0 = lds2(r1), a1 = lds2(r1+2), a2l = lds2(r1+4);
            u64 a6 = r1[6];
            u64 hA = fma2u(xdA[0], a0.x, 0ULL);
            u64 hB = fma2u(xdB[0], a0.x, 0ULL);
            hA = fma2u(xdA[1], a0.y, hA);   hB = fma2u(xdB[1], a0.y, hB);
            hA = fma2u(xdA[2], a1.x, hA);   hB = fma2u(xdB[2], a1.x, hB);
            hA = fma2u(xdA[3], a1.y, hA);   hB = fma2u(xdB[3], a1.y, hB);
            hA = fma2u(xdA[4], a2l.x, hA);  hB = fma2u(xdB[4], a2l.x, hB);
            hA = fma2u(xdA[5], a2l.y, hA);  hB = fma2u(xdB[5], a2l.y, hB);
            hA = fma2u(xdA[6], a6, hA);     hB = fma2u(xdB[6], a6, hB);
            float hx, hy;
            unpack2(hA, hx, hy);
            float hsA = hx + hy;
            unpack2(hB, hx, hy);
            float hsB = hx + hy;
            float gAv = gelu_fast(hsA);
            float gBv = gelu_fast(hsB);
            u64 gA2 = dup2(gAv), gB2 = dup2(gBv);
            const u64* r2 = f2 + f*8;
            ulonglong2 b0 = lds2(r2), b1v = lds2(r2+2), b2v = lds2(r2+4);
            u64 b6 = r2[6];
            yA[0] = fma2u(gA2, b0.x, yA[0]);  yB[0] = fma2u(gB2, b0.x, yB[0]);
            yA[1] = fma2u(gA2, b0.y, yA[1]);  yB[1] = fma2u(gB2, b0.y, yB[1]);
            yA[2] = fma2u(gA2, b1v.x, yA[2]); yB[2] = fma2u(gB2, b1v.x, yB[2]);
            yA[3] = fma2u(gA2, b1v.y, yA[3]); yB[3] = fma2u(gB2, b1v.y, yB[3]);
            yA[4] = fma2u(gA2, b2v.x, yA[4]); yB[4] = fma2u(gB2, b2v.x, yB[4]);
            yA[5] = fma2u(gA2, b2v.y, yA[5]); yB[5] = fma2u(gB2, b2v.y, yB[5]);
            yA[6] = fma2u(gA2, b6, yA[6]);    yB[6] = fma2u(gB2, b6, yB[6]);
        }
        #pragma unroll
        for (int dp = 0; dp < 7; dp++) {
            x2A[dp] = add2u(xdA[dp], yA[dp]);
            x2B[dp] = add2u(xdB[dp], yB[dp]);
        }
    }

    float x3Ax[7], x3Ay[7], x3Bx[7], x3By[7];
    #pragma unroll
    for (int dp = 0; dp < 7; dp++) {
        float vx, vy;
        unpack2(x2A[dp], vx, vy);
        x3Ax[dp] = decomp25(vx, lane, hi, loix, lom1, fc0, fc29);
        x3Ay[dp] = decomp25(vy, lane, hi, loix, lom1, fc0, fc29);
        unpack2(x2B[dp], vx, vy);
        x3Bx[dp] = decomp25(vx, lane, hi, loix, lom1, fc0, fc29);
        x3By[dp] = decomp25(vy, lane, hi, loix, lom1, fc0, fc29);
    }
    {
        float mA = 0.f, mB = 0.f;
        #pragma unroll
        for (int dp = 0; dp < 7; dp++) { mA += x3Ax[dp] + x3Ay[dp]; mB += x3Bx[dp] + x3By[dp]; }
        mA *= (1.f / 14.f); mB *= (1.f / 14.f);
        float vA_ = 0.f, vB_ = 0.f;
        #pragma unroll
        for (int dp = 0; dp < 7; dp++) {
            float dx = x3Ax[dp] - mA, dy = x3Ay[dp] - mA;
            vA_ += dx * dx + dy * dy;
            dx = x3Bx[dp] - mB; dy = x3By[dp] - mB;
            vB_ += dx * dx + dy * dy;
        }
        vA_ *= (1.f / 14.f); vB_ *= (1.f / 14.f);
        float iA = rsqrtf(vA_ + 1e-5f), iB = rsqrtf(vB_ + 1e-5f);
        #pragma unroll
        for (int dp = 0; dp < 7; dp++) {
            float g0 = sg[2*dp], g1 = sg[2*dp+1], b0 = sb[2*dp], b1v = sb[2*dp+1];
            x3Ax[dp] = (x3Ax[dp] - mA) * iA * g0 + b0;
            x3Ay[dp] = (x3Ay[dp] - mA) * iA * g1 + b1v;
            x3Bx[dp] = (x3Bx[dp] - mB) * iB * g0 + b0;
            x3By[dp] = (x3By[dp] - mB) * iB * g1 + b1v;
        }
    }

    __syncwarp();
    u64* x3sA = scrU;
    u64* x3sB = scrU + 240;
    if (act) {
        *reinterpret_cast<ulonglong2*>(x3sA + t*8)     = make_ulonglong2(pack2(x3Ax[0], x3Ay[0]), pack2(x3Ax[1], x3Ay[1]));
        *reinterpret_cast<ulonglong2*>(x3sA + t*8 + 2) = make_ulonglong2(pack2(x3Ax[2], x3Ay[2]), pack2(x3Ax[3], x3Ay[3]));
        *reinterpret_cast<ulonglong2*>(x3sA + t*8 + 4) = make_ulonglong2(pack2(x3Ax[4], x3Ay[4]), pack2(x3Ax[5], x3Ay[5]));
        x3sA[t*8 + 6] = pack2(x3Ax[6], x3Ay[6]);
        *reinterpret_cast<ulonglong2*>(x3sB + t*8)     = make_ulonglong2(pack2(x3Bx[0], x3By[0]), pack2(x3Bx[1], x3By[1]));
        *reinterpret_cast<ulonglong2*>(x3sB + t*8 + 2) = make_ulonglong2(pack2(x3Bx[2], x3By[2]), pack2(x3Bx[3], x3By[3]));
        *reinterpret_cast<ulonglong2*>(x3sB + t*8 + 4) = make_ulonglong2(pack2(x3Bx[4], x3By[4]), pack2(x3Bx[5], x3By[5]));
        x3sB[t*8 + 6] = pack2(x3Bx[6], x3By[6]);
    }
    __syncwarp();
    u64 accA[7], accB[7];
    {
        u64 bias2 = dup2(sbdy[t]);
        #pragma unroll
        for (int dp = 0; dp < 7; dp++) { accA[dp] = bias2; accB[dp] = bias2; }
        #pragma unroll
        for (int m = 0; m < 30; m++) {
            u64 wm2 = dup2(sWdy[m*30 + t]);
            const u64* xa = x3sA + m*8;
            const u64* xb = x3sB + m*8;
            ulonglong2 a0 = lds2(xa), a1 = lds2(xa+2), a2l = lds2(xa+4);
            u64 a6 = xa[6];
            ulonglong2 b0 = lds2(xb), b1v = lds2(xb+2), b2v = lds2(xb+4);
            u64 b6 = xb[6];
            accA[0] = fma2u(a0.x, wm2, accA[0]);  accB[0] = fma2u(b0.x, wm2, accB[0]);
            accA[1] = fma2u(a0.y, wm2, accA[1]);  accB[1] = fma2u(b0.y, wm2, accB[1]);
            accA[2] = fma2u(a1.x, wm2, accA[2]);  accB[2] = fma2u(b1v.x, wm2, accB[2]);
            accA[3] = fma2u(a1.y, wm2, accA[3]);  accB[3] = fma2u(b1v.y, wm2, accB[3]);
            accA[4] = fma2u(a2l.x, wm2, accA[4]); accB[4] = fma2u(b2v.x, wm2, accB[4]);
            accA[5] = fma2u(a2l.y, wm2, accA[5]); accB[5] = fma2u(b2v.y, wm2, accB[5]);
            accA[6] = fma2u(a6,   wm2, accA[6]);  accB[6] = fma2u(b6,   wm2, accB[6]);
        }
    }

    {
        float* foA = g_f + (size_t)smpA * 420;
        float* foB = g_f + (size_t)(smpA+1) * 420;
        const u64* adj = reinterpret_cast<const u64*>(sAdjP);
        #pragma unroll
        for (int i = 0; i < 14; i++) {
            const u64* ar = adj + i*8;
            ulonglong2 a0 = lds2(ar), a1 = lds2(ar+2), a2l = lds2(ar+4);
            u64 a6 = ar[6];
            u64 sA2 = fma2u(a0.x, accA[0], 0ULL);
            u64 sB2 = fma2u(a0.x, accB[0], 0ULL);
            sA2 = fma2u(a0.y, accA[1], sA2);  sB2 = fma2u(a0.y, accB[1], sB2);
            sA2 = fma2u(a1.x, accA[2], sA2);  sB2 = fma2u(a1.x, accB[2], sB2);
            sA2 = fma2u(a1.y, accA[3], sA2);  sB2 = fma2u(a1.y, accB[3], sB2);
            sA2 = fma2u(a2l.x, accA[4], sA2); sB2 = fma2u(a2l.x, accB[4], sB2);
            sA2 = fma2u(a2l.y, accA[5], sA2); sB2 = fma2u(a2l.y, accB[5], sB2);
            sA2 = fma2u(a6, accA[6], sA2);    sB2 = fma2u(a6, accB[6], sB2);
            float ax, ay;
            unpack2(sA2, ax, ay);
            if (act) foA[i*30 + t] = fmaxf(ax + ay, 0.f);
            unpack2(sB2, ax, ay);
            if (act) foB[i*30 + t] = fmaxf(ax + ay, 0.f);
        }
    }
}

// ============================================================================
// Kernel B (3xBF16 m16n8k16, DOUBLE-BUFFERED): hh = relu(f @ W1 + b1)
// M=65536, K=420 (pad 448), N=256. BM=128, BN=64, BK=32. 14 k-iters.
// ============================================================================
__global__ __launch_bounds__(256) void kB(const float* __restrict__ W1,
                                          const float* __restrict__ b1)
{
    __shared__ unsigned Ah[2][128][20], Al[2][128][20];
    __shared__ unsigned Bh[2][64][20],  Bl[2][64][20];
    const int tid = threadIdx.x;
    const int lane = tid & 31, wid = tid >> 5;
    const int wm = wid >> 1, wn = wid & 1;
    const int c4 = lane & 3;
    const size_t mbase = (size_t)blockIdx.y * 128;
    const int nbase = blockIdx.x * 64;
    const int mrow = tid >> 1, mhalf = tid & 1;
    const int kpB = tid >> 4, n4 = (tid & 15) * 4;
    float c[2][4][4] = {};

    const float4* grA = reinterpret_cast<const float4*>(g_f + (mbase + mrow) * 420);

    float4 va[4], vb0, vb1;
    // ---- load tile 0 ----
    #pragma unroll
    for (int j = 0; j < 4; j++) {
        int kq = mhalf*4 + j;
        va[j] = (kq < 105) ? grA[kq] : make_float4(0.f,0.f,0.f,0.f);
    }
    {
        int gk0 = 2*kpB, gk1 = gk0 + 1;
        vb0 = (gk0 < 420) ? *reinterpret_cast<const float4*>(W1 + (size_t)gk0*256 + nbase + n4)
                          : make_float4(0.f,0.f,0.f,0.f);
        vb1 = (gk1 < 420) ? *reinterpret_cast<const float4*>(W1 + (size_t)gk1*256 + nbase + n4)
                          : make_float4(0.f,0.f,0.f,0.f);
    }
    // ---- store tile 0 into buf 0 ----
    {
        #pragma unroll
        for (int j = 0; j < 4; j++) {
            int kp = mhalf*8 + 2*j;
            unsigned h, l;
            split_bf16x2(va[j].x, va[j].y, h, l); Ah[0][mrow][kp]   = h; Al[0][mrow][kp]   = l;
            split_bf16x2(va[j].z, va[j].w, h, l); Ah[0][mrow][kp+1] = h; Al[0][mrow][kp+1] = l;
        }
        unsigned h, l;
        split_bf16x2(vb0.x, vb1.x, h, l); Bh[0][n4+0][kpB] = h; Bl[0][n4+0][kpB] = l;
        split_bf16x2(vb0.y, vb1.y, h, l); Bh[0][n4+1][kpB] = h; Bl[0][n4+1][kpB] = l;
        split_bf16x2(vb0.z, vb1.z, h, l); Bh[0][n4+2][kpB] = h; Bl[0][n4+2][kpB] = l;
        split_bf16x2(vb0.w, vb1.w, h, l); Bh[0][n4+3][kpB] = h; Bl[0][n4+3][kpB] = l;
    }
    __syncthreads();

    int buf = 0;
    for (int ki = 0; ki < 14; ki++) {
        // ---- prefetch next tile into registers ----
        if (ki < 13) {
            int k0n = (ki + 1) * 32;
            #pragma unroll
            for (int j = 0; j < 4; j++) {
                int kq = (k0n >> 2) + mhalf*4 + j;
                va[j] = (kq < 105) ? grA[kq] : make_float4(0.f,0.f,0.f,0.f);
            }
            int gk0 = k0n + 2*kpB, gk1 = gk0 + 1;
            vb0 = (gk0 < 420) ? *reinterpret_cast<const float4*>(W1 + (size_t)gk0*256 + nbase + n4)
                              : make_float4(0.f,0.f,0.f,0.f);
            vb1 = (gk1 < 420) ? *reinterpret_cast<const float4*>(W1 + (size_t)gk1*256 + nbase + n4)
                              : make_float4(0.f,0.f,0.f,0.f);
        }
        // ---- MMAs on current buffer ----
        #pragma unroll
        for (int ks = 0; ks < 2; ks++) {
            int kb = ks * 8;
            unsigned ah[2][4], al[2][4], bh[4][2], bl[4][2];
            #pragma unroll
            for (int mt = 0; mt < 2; mt++) {
                int r = wm*32 + mt*16 + (lane>>2);
                ah[mt][0] = Ah[buf][r  ][kb + c4];     al[mt][0] = Al[buf][r  ][kb + c4];
                ah[mt][1] = Ah[buf][r+8][kb + c4];     al[mt][1] = Al[buf][r+8][kb + c4];
                ah[mt][2] = Ah[buf][r  ][kb + c4 + 4]; al[mt][2] = Al[buf][r  ][kb + c4 + 4];
                ah[mt][3] = Ah[buf][r+8][kb + c4 + 4]; al[mt][3] = Al[buf][r+8][kb + c4 + 4];
            }
            #pragma unroll
            for (int nt = 0; nt < 4; nt++) {
                int nn = wn*32 + nt*8 + (lane>>2);
                bh[nt][0] = Bh[buf][nn][kb + c4];     bl[nt][0] = Bl[buf][nn][kb + c4];
                bh[nt][1] = Bh[buf][nn][kb + c4 + 4]; bl[nt][1] = Bl[buf][nn][kb + c4 + 4];
            }
            #pragma unroll
            for (int mt = 0; mt < 2; mt++)
                #pragma unroll
                for (int nt = 0; nt < 4; nt++) {
                    mma_bf16(c[mt][nt], ah[mt], bh[nt]);
                    mma_bf16(c[mt][nt], ah[mt], bl[nt]);
                    mma_bf16(c[mt][nt], al[mt], bh[nt]);
                }
        }
        // ---- split + store prefetched tile into alternate buffer ----
        if (ki < 13) {
            int nb = buf ^ 1;
            #pragma unroll
            for (int j = 0; j < 4; j++) {
                int kp = mhalf*8 + 2*j;
                unsigned h, l;
                split_bf16x2(va[j].x, va[j].y, h, l); Ah[nb][mrow][kp]   = h; Al[nb][mrow][kp]   = l;
                split_bf16x2(va[j].z, va[j].w, h, l); Ah[nb][mrow][kp+1] = h; Al[nb][mrow][kp+1] = l;
            }
            unsigned h, l;
            split_bf16x2(vb0.x, vb1.x, h, l); Bh[nb][n4+0][kpB] = h; Bl[nb][n4+0][kpB] = l;
            split_bf16x2(vb0.y, vb1.y, h, l); Bh[nb][n4+1][kpB] = h; Bl[nb][n4+1][kpB] = l;
            split_bf16x2(vb0.z, vb1.z, h, l); Bh[nb][n4+2][kpB] = h; Bl[nb][n4+2][kpB] = l;
            split_bf16x2(vb0.w, vb1.w, h, l); Bh[nb][n4+3][kpB] = h; Bl[nb][n4+3][kpB] = l;
            __syncthreads();
            buf = nb;
        }
    }
    #pragma unroll
    for (int mt = 0; mt < 2; mt++) {
        int r0 = wm*32 + mt*16 + (lane>>2);
        #pragma unroll
        for (int nt = 0; nt < 4; nt++) {
            int cl = nbase + wn*32 + nt*8 + 2*(lane&3);
            float b0 = b1[cl], b1v = b1[cl+1];
            float2 lo = make_float2(fmaxf(c[mt][nt][0] + b0, 0.f), fmaxf(c[mt][nt][1] + b1v, 0.f));
            float2 hi = make_float2(fmaxf(c[mt][nt][2] + b0, 0.f), fmaxf(c[mt][nt][3] + b1v, 0.f));
            *reinterpret_cast<float2*>(g_hh + (mbase + r0    ) * 256 + cl) = lo;
            *reinterpret_cast<float2*>(g_hh + (mbase + r0 + 8) * 256 + cl) = hi;
        }
    }
}

// ============================================================================
// Kernel C (3xBF16, DOUBLE-BUFFERED, fused LN head):
// hr = [hh|f]@[W2;Wres]+b2+bres, out = LN64(hr)@W3+b3. K=704(pad), 22 iters.
// ============================================================================
__global__ __launch_bounds__(256) void kC(const float* __restrict__ W2,
                                          const float* __restrict__ b2,
                                          const float* __restrict__ Wres,
                                          const float* __restrict__ bres,
                                          const float* __restrict__ g_ln,
                                          const float* __restrict__ b_ln,
                                          const float* __restrict__ W3,
                                          const float* __restrict__ b3,
                                          float* __restrict__ out)
{
    __shared__ unsigned Ah[2][128][20], Al[2][128][20];
    __shared__ unsigned Bh[2][64][20],  Bl[2][64][20];
    __shared__ float sbb[64];
    __shared__ float sgw[64];
    __shared__ float sp[128][2][3];
    __shared__ float sconst[2];
    const int tid = threadIdx.x;
    const int lane = tid & 31, wid = tid >> 5;
    const int wm = wid >> 1, wn = wid & 1;
    const int c4 = lane & 3;
    const size_t mbase = (size_t)blockIdx.x * 128;
    const int mrow = tid >> 1, mhalf = tid & 1;
    const int kpB = tid >> 4, n4 = (tid & 15) * 4;
    float c[2][4][4] = {};

    if (tid < 64) {
        sbb[tid] = b2[tid] + bres[tid];
        sgw[tid] = g_ln[tid] * W3[tid];
    }

    const float* hrow = g_hh + (mbase + mrow) * 256;
    const float* frow = g_f  + (mbase + mrow) * 420;

    float4 va[4], vb0, vb1;
    // ---- load tile 0 ----
    #pragma unroll
    for (int j = 0; j < 4; j++) {
        int gk = mhalf*16 + 4*j;
        float4 vv = make_float4(0.f,0.f,0.f,0.f);
        if (gk < 256) vv = *reinterpret_cast<const float4*>(hrow + gk);
        else { int kf = gk - 256; if (kf < 420) vv = *reinterpret_cast<const float4*>(frow + kf); }
        va[j] = vv;
    }
    {
        int gk0 = 2*kpB, gk1 = gk0 + 1;
        float4 r0 = make_float4(0.f,0.f,0.f,0.f);
        float4 r1 = make_float4(0.f,0.f,0.f,0.f);
        if (gk0 < 256) r0 = *reinterpret_cast<const float4*>(W2 + (size_t)gk0*64 + n4);
        else { int kf = gk0 - 256; if (kf < 420) r0 = *reinterpret_cast<const float4*>(Wres + (size_t)kf*64 + n4); }
        if (gk1 < 256) r1 = *reinterpret_cast<const float4*>(W2 + (size_t)gk1*64 + n4);
        else { int kf = gk1 - 256; if (kf < 420) r1 = *reinterpret_cast<const float4*>(Wres + (size_t)kf*64 + n4); }
        vb0 = r0; vb1 = r1;
    }
    // ---- store tile 0 into buf 0 ----
    {
        #pragma unroll
        for (int j = 0; j < 4; j++) {
            int kp = mhalf*8 + 2*j;
            unsigned h, l;
            split_bf16x2(va[j].x, va[j].y, h, l); Ah[0][mrow][kp]   = h; Al[0][mrow][kp]   = l;
            split_bf16x2(va[j].z, va[j].w, h, l); Ah[0][mrow][kp+1] = h; Al[0][mrow][kp+1] = l;
        }
        unsigned h, l;
        split_bf16x2(vb0.x, vb1.x, h, l); Bh[0][n4+0][kpB] = h; Bl[0][n4+0][kpB] = l;
        split_bf16x2(vb0.y, vb1.y, h, l); Bh[0][n4+1][kpB] = h; Bl[0][n4+1][kpB] = l;
        split_bf16x2(vb0.z, vb1.z, h, l); Bh[0][n4+2][kpB] = h; Bl[0][n4+2][kpB] = l;
        split_bf16x2(vb0.w, vb1.w, h, l); Bh[0][n4+3][kpB] = h; Bl[0][n4+3][kpB] = l;
    }
    __syncthreads();

    int buf = 0;
    for (int ki = 0; ki < 22; ki++) {
        if (ki < 21) {
            int k0n = (ki + 1) * 32;
            #pragma unroll
            for (int j = 0; j < 4; j++) {
                int gk = k0n + mhalf*16 + 4*j;
                float4 vv = make_float4(0.f,0.f,0.f,0.f);
                if (gk < 256) vv = *reinterpret_cast<const float4*>(hrow + gk);
                else { int kf = gk - 256; if (kf < 420) vv = *reinterpret_cast<const float4*>(frow + kf); }
                va[j] = vv;
            }
            int gk0 = k0n + 2*kpB, gk1 = gk0 + 1;
            float4 r0 = make_float4(0.f,0.f,0.f,0.f);
            float4 r1 = make_float4(0.f,0.f,0.f,0.f);
            if (gk0 < 256) r0 = *reinterpret_cast<const float4*>(W2 + (size_t)gk0*64 + n4);
            else { int kf = gk0 - 256; if (kf < 420) r0 = *reinterpret_cast<const float4*>(Wres + (size_t)kf*64 + n4); }
            if (gk1 < 256) r1 = *reinterpret_cast<const float4*>(W2 + (size_t)gk1*64 + n4);
            else { int kf = gk1 - 256; if (kf < 420) r1 = *reinterpret_cast<const float4*>(Wres + (size_t)kf*64 + n4); }
            vb0 = r0; vb1 = r1;
        }
        #pragma unroll
        for (int ks = 0; ks < 2; ks++) {
            int kb = ks * 8;
            unsigned ah[2][4], al[2][4], bh[4][2], bl[4][2];
            #pragma unroll
            for (int mt = 0; mt < 2; mt++) {
                int r = wm*32 + mt*16 + (lane>>2);
                ah[mt][0] = Ah[buf][r  ][kb + c4];     al[mt][0] = Al[buf][r  ][kb + c4];
                ah[mt][1] = Ah[buf][r+8][kb + c4];     al[mt][1] = Al[buf][r+8][kb + c4];
                ah[mt][2] = Ah[buf][r  ][kb + c4 + 4]; al[mt][2] = Al[buf][r  ][kb + c4 + 4];
                ah[mt][3] = Ah[buf][r+8][kb + c4 + 4]; al[mt][3] = Al[buf][r+8][kb + c4 + 4];
            }
            #pragma unroll
            for (int nt = 0; nt < 4; nt++) {
                int nn = wn*32 + nt*8 + (lane>>2);
                bh[nt][0] = Bh[buf][nn][kb + c4];     bl[nt][0] = Bl[buf][nn][kb + c4];
                bh[nt][1] = Bh[buf][nn][kb + c4 + 4]; bl[nt][1] = Bl[buf][nn][kb + c4 + 4];
            }
            #pragma unroll
            for (int mt = 0; mt < 2; mt++)
                #pragma unroll
                for (int nt = 0; nt < 4; nt++) {
                    mma_bf16(c[mt][nt], ah[mt], bh[nt]);
                    mma_bf16(c[mt][nt], ah[mt], bl[nt]);
                    mma_bf16(c[mt][nt], al[mt], bh[nt]);
                }
        }
        if (ki < 21) {
            int nb = buf ^ 1;
            #pragma unroll
            for (int j = 0; j < 4; j++) {
                int kp = mhalf*8 + 2*j;
                unsigned h, l;
                split_bf16x2(va[j].x, va[j].y, h, l); Ah[nb][mrow][kp]   = h; Al[nb][mrow][kp]   = l;
                split_bf16x2(va[j].z, va[j].w, h, l); Ah[nb][mrow][kp+1] = h; Al[nb][mrow][kp+1] = l;
            }
            unsigned h, l;
            split_bf16x2(vb0.x, vb1.x, h, l); Bh[nb][n4+0][kpB] = h; Bl[nb][n4+0][kpB] = l;
            split_bf16x2(vb0.y, vb1.y, h, l); Bh[nb][n4+1][kpB] = h; Bl[nb][n4+1][kpB] = l;
            split_bf16x2(vb0.z, vb1.z, h, l); Bh[nb][n4+2][kpB] = h; Bl[nb][n4+2][kpB] = l;
            split_bf16x2(vb0.w, vb1.w, h, l); Bh[nb][n4+3][kpB] = h; Bl[nb][n4+3][kpB] = l;
            __syncthreads();
            buf = nb;
        }
    }

    // ---- fused epilogue: partial LN sums per (row, wn-half) ----
    #pragma unroll
    for (int mt = 0; mt < 2; mt++) {
        #pragma unroll
        for (int rb = 0; rb < 2; rb++) {
            float sv = 0.f, sq = 0.f, sgd = 0.f;
            #pragma unroll
            for (int nt = 0; nt < 4; nt++) {
                int cl = wn*32 + nt*8 + 2*(lane&3);
                float v0 = c[mt][nt][2*rb]     + sbb[cl];
                float v1 = c[mt][nt][2*rb + 1] + sbb[cl+1];
                sv += v0 + v1;
                sq += v0*v0 + v1*v1;
                sgd += v0*sgw[cl] + v1*sgw[cl+1];
            }
            sv += __shfl_xor_sync(FULL, sv, 1);
            sq += __shfl_xor_sync(FULL, sq, 1);
            sgd += __shfl_xor_sync(FULL, sgd, 1);
            sv += __shfl_xor_sync(FULL, sv, 2);
            sq += __shfl_xor_sync(FULL, sq, 2);
            sgd += __shfl_xor_sync(FULL, sgd, 2);
            if ((lane & 3) == 0) {
                int row = wm*32 + mt*16 + rb*8 + (lane>>2);
                sp[row][wn][0] = sv;
                sp[row][wn][1] = sq;
                sp[row][wn][2] = sgd;
            }
        }
    }
    if (tid == 0) {
        float G = 0.f, cb = b3[0];
        for (int d = 0; d < 64; d++) { G += sgw[d]; cb += b_ln[d] * W3[d]; }
        sconst[0] = G; sconst[1] = cb;
    }
    __syncthreads();
    if (tid < 128) {
        int row = tid;
        float sv  = sp[row][0][0] + sp[row][1][0];
        float sq  = sp[row][0][1] + sp[row][1][1];
        float sgd = sp[row][0][2] + sp[row][1][2];
        float m = sv * (1.f / 64.f);
        float var = sq * (1.f / 64.f) - m * m;
        float invs = rsqrtf(var + 1e-5f);
        out[mbase + row] = invs * (sgd - m * sconst[0]) + sconst[1];
    }
}

// ============================================================================
extern "C" void kernel_launch(void* const* d_in, const int* in_sizes, int n_in,
                              void* d_out, int out_size)
{
    (void)in_sizes; (void)n_in; (void)out_size;
    const float* x = (const float*)d_in[0];

    kA<<<BATCH / 16, 256>>>(x,
        (const float*)d_in[1],  (const float*)d_in[2],
        (const float*)d_in[3],  (const float*)d_in[4],
        (const float*)d_in[5],  (const float*)d_in[6],
        (const float*)d_in[7],  (const float*)d_in[8],
        (const float*)d_in[9],  (const float*)d_in[10],
        (const float*)d_in[11], (const float*)d_in[12],
        (const float*)d_in[13], (const float*)d_in[14],
        (const float*)d_in[15], (const float*)d_in[16],
        (const float*)d_in[17]);

    kB<<<dim3(4, BATCH / 128), 256>>>((const float*)d_in[18], (const float*)d_in[19]);

    kC<<<BATCH / 128, 256>>>((const float*)d_in[20], (const float*)d_in[21],
                             (const float*)d_in[22], (const float*)d_in[23],
                             (const float*)d_in[24], (const float*)d_in[25],
                             (const float*)d_in[26], (const float*)d_in[27],
                             (float*)d_out);
}